// round 1
// baseline (speedup 1.0000x reference)
#include <cuda_runtime.h>
#include <cuda_bf16.h>
#include <math.h>

#define BB 8
#define SS 2048
#define DD 320
#define NHH 5
#define HDD 64
#define FFF 864
#define NLL 6
#define KSEL 1638
#define M_TOK (BB*SS)      // 16384
#define M_SEL (BB*KSEL)    // 13104
#define EPSF 1e-6f

// ---------------- scratch (static device globals; no allocation) ----------------
__device__ float g_x[M_TOK*DD];
__device__ float g_h[M_TOK*DD];
__device__ float g_qkv[M_TOK*3*DD];
__device__ float g_q[M_TOK*DD];   // [B,NH,S,HD]
__device__ float g_k[M_TOK*DD];
__device__ float g_v[M_TOK*DD];
__device__ float g_att[M_TOK*DD]; // [B,S,D]
__device__ float g_probs[M_TOK];
__device__ int   g_tidx[M_SEL];
__device__ float g_tp[M_SEL];
__device__ float g_hs[M_SEL*DD];
__device__ float g_gate[M_SEL*FFF];
__device__ float g_up[M_SEL*FFF];
__device__ float g_mlp[M_SEL*DD];
__device__ float g_cos[SS*32];
__device__ float g_sin[SS*32];

// ---------------- rope tables ----------------
__global__ void rope_table_kernel() {
    int i = blockIdx.x*blockDim.x + threadIdx.x;
    if (i >= SS*32) return;
    int s = i / 32, d = i % 32;
    double freq = exp(-((double)(2*d)/64.0)*log(10000.0));
    double f = (double)s * freq;
    g_cos[i] = (float)cos(f);
    g_sin[i] = (float)sin(f);
}

// ---------------- embed ----------------
__global__ void embed_kernel(const int* __restrict__ ids, const int* __restrict__ iter,
                             const float* __restrict__ emb, const float* __restrict__ iter_emb) {
    int i = blockIdx.x*blockDim.x + threadIdx.x;
    if (i >= M_TOK*DD) return;
    int t = i / DD, d = i % DD;
    float v = emb[(size_t)ids[t]*DD + d];
    int it = iter[0];
    if (it < 8) v += iter_emb[(size_t)it*DD + d];
    g_x[i] = v;
}

// ---------------- rmsnorm (block per token) ----------------
__global__ void rmsnorm_kernel(const float* __restrict__ X, const float* __restrict__ w,
                               float* __restrict__ Y) {
    int t = blockIdx.x;
    const float* xr = X + (size_t)t*DD;
    float ss = 0.f;
    for (int d = threadIdx.x; d < DD; d += 128) { float v = xr[d]; ss += v*v; }
    #pragma unroll
    for (int o = 16; o > 0; o >>= 1) ss += __shfl_xor_sync(0xffffffffu, ss, o);
    __shared__ float red[4];
    if ((threadIdx.x & 31) == 0) red[threadIdx.x >> 5] = ss;
    __syncthreads();
    float tot = red[0]+red[1]+red[2]+red[3];
    float sc = rsqrtf(tot*(1.f/DD) + EPSF);
    for (int d = threadIdx.x; d < DD; d += 128) Y[(size_t)t*DD + d] = w[d]*xr[d]*sc;
}

// ---------------- SGEMM: C[M,N] (+)= A[M,K] * B[N,K]^T ; BM=BN=64, BK=16, 256 thr ----------
template<bool ACCUM>
__global__ void sgemm64(const float* __restrict__ A, const float* __restrict__ Bm,
                        float* __restrict__ C, int M, int N, int K) {
    __shared__ float As[16][64];
    __shared__ float Bs[16][64];
    int tid = threadIdx.x;
    int tx = tid & 15, ty = tid >> 4;
    int row0 = blockIdx.y*64, col0 = blockIdx.x*64;
    int lr = tid >> 2;
    int lk = (tid & 3) * 4;
    float acc[4][4] = {};
    const float4* Arow = (const float4*)(A + (size_t)(row0+lr)*K + lk);
    const float4* Brow = (const float4*)(Bm + (size_t)(col0+lr)*K + lk);
    bool aval = (row0+lr) < M;
    bool bval = (col0+lr) < N;
    for (int k0 = 0; k0 < K; k0 += 16) {
        float4 a = aval ? Arow[k0>>2] : make_float4(0,0,0,0);
        float4 b = bval ? Brow[k0>>2] : make_float4(0,0,0,0);
        __syncthreads();
        As[lk+0][lr]=a.x; As[lk+1][lr]=a.y; As[lk+2][lr]=a.z; As[lk+3][lr]=a.w;
        Bs[lk+0][lr]=b.x; Bs[lk+1][lr]=b.y; Bs[lk+2][lr]=b.z; Bs[lk+3][lr]=b.w;
        __syncthreads();
        #pragma unroll
        for (int kk = 0; kk < 16; kk++) {
            float4 av = *(const float4*)&As[kk][ty*4];
            float4 bv = *(const float4*)&Bs[kk][tx*4];
            acc[0][0]+=av.x*bv.x; acc[0][1]+=av.x*bv.y; acc[0][2]+=av.x*bv.z; acc[0][3]+=av.x*bv.w;
            acc[1][0]+=av.y*bv.x; acc[1][1]+=av.y*bv.y; acc[1][2]+=av.y*bv.z; acc[1][3]+=av.y*bv.w;
            acc[2][0]+=av.z*bv.x; acc[2][1]+=av.z*bv.y; acc[2][2]+=av.z*bv.z; acc[2][3]+=av.z*bv.w;
            acc[3][0]+=av.w*bv.x; acc[3][1]+=av.w*bv.y; acc[3][2]+=av.w*bv.z; acc[3][3]+=av.w*bv.w;
        }
    }
    #pragma unroll
    for (int i = 0; i < 4; i++) {
        int r = row0 + ty*4 + i;
        if (r < M) {
            #pragma unroll
            for (int j = 0; j < 4; j++) {
                int c = col0 + tx*4 + j;
                if (c < N) {
                    size_t off = (size_t)r*N + c;
                    if (ACCUM) C[off] += acc[i][j]; else C[off] = acc[i][j];
                }
            }
        }
    }
}

// ---------------- rope + split to [B,NH,S,HD] ----------------
__global__ void rope_kernel() {
    int i = blockIdx.x*blockDim.x + threadIdx.x;
    if (i >= M_TOK*NHH*32) return;
    int t = i / (NHH*32);
    int r = i % (NHH*32);
    int h = r / 32, d = r % 32;
    int b = t / SS, s = t % SS;
    const float* base = g_qkv + (size_t)t*(3*DD) + h*HDD;
    float c = g_cos[s*32+d], sn = g_sin[s*32+d];
    float q1 = base[d],        q2 = base[d+32];
    float k1 = base[DD+d],     k2 = base[DD+d+32];
    size_t o = ((size_t)(b*NHH+h)*SS + s)*HDD;
    g_q[o+d]    = q1*c - q2*sn;
    g_q[o+d+32] = q2*c + q1*sn;
    g_k[o+d]    = k1*c - k2*sn;
    g_k[o+d+32] = k2*c + k1*sn;
    g_v[o+d]    = base[2*DD+d];
    g_v[o+d+32] = base[2*DD+d+32];
}

// ---------------- flash attention (fp32, thread per q row) ----------------
__global__ void __launch_bounds__(128) flash_attn_kernel() {
    __shared__ float Ks[64][64];
    __shared__ float Vs[64][64];
    int b = blockIdx.z, h = blockIdx.y;
    int qi = blockIdx.x*128 + threadIdx.x;
    const float* Qp = g_q + ((size_t)(b*NHH+h)*SS)*HDD;
    const float* Kp = g_k + ((size_t)(b*NHH+h)*SS)*HDD;
    const float* Vp = g_v + ((size_t)(b*NHH+h)*SS)*HDD;
    float q[64], o[64];
    #pragma unroll
    for (int d = 0; d < 64; d++) { q[d] = Qp[(size_t)qi*64 + d]*0.125f; o[d] = 0.f; }
    float m = -1e30f, lsum = 0.f;
    int ntiles = blockIdx.x*2 + 2;
    for (int kt = 0; kt < ntiles; kt++) {
        for (int i = threadIdx.x; i < 64*16; i += 128) {
            int rr = i >> 4, cc = (i & 15) << 2;
            *(float4*)&Ks[rr][cc] = *(const float4*)&Kp[(size_t)(kt*64+rr)*64 + cc];
            *(float4*)&Vs[rr][cc] = *(const float4*)&Vp[(size_t)(kt*64+rr)*64 + cc];
        }
        __syncthreads();
        int kend = qi - kt*64 + 1;
        if (kend > 64) kend = 64;
        for (int kr = 0; kr < kend; kr++) {
            const float* kk = Ks[kr];
            float p0=0.f, p1=0.f, p2=0.f, p3=0.f;
            #pragma unroll
            for (int d = 0; d < 64; d += 4) {
                p0 += q[d+0]*kk[d+0];
                p1 += q[d+1]*kk[d+1];
                p2 += q[d+2]*kk[d+2];
                p3 += q[d+3]*kk[d+3];
            }
            float sv = (p0+p1)+(p2+p3);
            const float* vv = Vs[kr];
            if (sv <= m) {
                float p = __expf(sv - m);
                lsum += p;
                #pragma unroll
                for (int d = 0; d < 64; d++) o[d] += p*vv[d];
            } else {
                float cfac = __expf(m - sv);
                lsum = lsum*cfac + 1.f;
                m = sv;
                #pragma unroll
                for (int d = 0; d < 64; d++) o[d] = o[d]*cfac + vv[d];
            }
        }
        __syncthreads();
    }
    float inv = 1.f/lsum;
    float* op = g_att + ((size_t)(b*SS)+qi)*DD + h*HDD;
    #pragma unroll
    for (int d = 0; d < 64; d++) op[d] = o[d]*inv;
}

// ---------------- router ----------------
__global__ void router_kernel(const float* __restrict__ rw) {
    int t = blockIdx.x*4 + (threadIdx.x >> 5);
    int lane = threadIdx.x & 31;
    const float* xr = g_x + (size_t)t*DD;
    float s = 0.f;
    for (int d = lane; d < DD; d += 32) s += xr[d]*rw[d];
    #pragma unroll
    for (int o = 16; o > 0; o >>= 1) s += __shfl_xor_sync(0xffffffffu, s, o);
    if (lane == 0) g_probs[t] = 1.f/(1.f + __expf(-s));
}

// ---------------- per-batch top-k via bitonic sort (set membership only matters) ----------
__global__ void topk_kernel() {
    __shared__ float sv[2048];
    __shared__ int   si[2048];
    int bb = blockIdx.x;
    for (int i = threadIdx.x; i < 2048; i += 1024) { sv[i] = g_probs[(size_t)bb*SS + i]; si[i] = i; }
    __syncthreads();
    for (int k = 2; k <= 2048; k <<= 1) {
        for (int j = k >> 1; j > 0; j >>= 1) {
            for (int t = threadIdx.x; t < 2048; t += 1024) {
                int ixj = t ^ j;
                if (ixj > t) {
                    bool desc = ((t & k) == 0);
                    float a = sv[t], b2 = sv[ixj];
                    bool sw = desc ? (a < b2) : (a > b2);
                    if (sw) {
                        sv[t] = b2; sv[ixj] = a;
                        int tmp = si[t]; si[t] = si[ixj]; si[ixj] = tmp;
                    }
                }
            }
            __syncthreads();
        }
    }
    for (int i = threadIdx.x; i < KSEL; i += 1024) {
        g_tidx[(size_t)bb*KSEL + i] = si[i];
        g_tp[(size_t)bb*KSEL + i]   = sv[i];
    }
}

// ---------------- gather + rmsnorm ----------------
__global__ void gather_rmsnorm_kernel(const float* __restrict__ w) {
    int i = blockIdx.x;
    int b = i / KSEL;
    int tok = g_tidx[i];
    const float* xr = g_x + ((size_t)b*SS + tok)*DD;
    float ss = 0.f;
    for (int d = threadIdx.x; d < DD; d += 128) { float v = xr[d]; ss += v*v; }
    #pragma unroll
    for (int o = 16; o > 0; o >>= 1) ss += __shfl_xor_sync(0xffffffffu, ss, o);
    __shared__ float red[4];
    if ((threadIdx.x & 31) == 0) red[threadIdx.x >> 5] = ss;
    __syncthreads();
    float tot = red[0]+red[1]+red[2]+red[3];
    float sc = rsqrtf(tot*(1.f/DD) + EPSF);
    for (int d = threadIdx.x; d < DD; d += 128) g_hs[(size_t)i*DD + d] = w[d]*xr[d]*sc;
}

// ---------------- silu(gate)*up ----------------
__global__ void silu_kernel() {
    size_t i = (size_t)blockIdx.x*blockDim.x + threadIdx.x;
    if (i >= (size_t)M_SEL*FFF) return;
    float g = g_gate[i];
    float u = g_up[i];
    float sig = 1.f/(1.f + __expf(-g));
    g_gate[i] = g*sig*u;
}

// ---------------- scaled scatter-add ----------------
__global__ void scatter_kernel() {
    int i = blockIdx.x;
    int b = i / KSEL;
    int tok = g_tidx[i];
    float p = g_tp[i];
    float* xr = g_x + ((size_t)b*SS + tok)*DD;
    const float* mr = g_mlp + (size_t)i*DD;
    for (int d = threadIdx.x; d < DD; d += 128) xr[d] += mr[d]*p;
}

// ---------------- host orchestration ----------------
extern "C" void kernel_launch(void* const* d_in, const int* in_sizes, int n_in,
                              void* d_out, int out_size) {
    const int*   ids       = (const int*)d_in[0];
    const int*   iter      = (const int*)d_in[1];
    const float* emb       = (const float*)d_in[2];
    const float* iter_emb  = (const float*)d_in[3];
    const float* attn_norm = (const float*)d_in[4];
    const float* Wqkv      = (const float*)d_in[5];
    const float* wo        = (const float*)d_in[6];
    const float* router    = (const float*)d_in[7];
    const float* mlp_norm  = (const float*)d_in[8];
    const float* gate_w    = (const float*)d_in[9];
    const float* up_w      = (const float*)d_in[10];
    const float* down_w    = (const float*)d_in[11];
    const float* fnorm     = (const float*)d_in[12];

    float *px, *ph, *pqkv, *patt, *phs, *pgate, *pup, *pmlp;
    cudaGetSymbolAddress((void**)&px,   g_x);
    cudaGetSymbolAddress((void**)&ph,   g_h);
    cudaGetSymbolAddress((void**)&pqkv, g_qkv);
    cudaGetSymbolAddress((void**)&patt, g_att);
    cudaGetSymbolAddress((void**)&phs,  g_hs);
    cudaGetSymbolAddress((void**)&pgate,g_gate);
    cudaGetSymbolAddress((void**)&pup,  g_up);
    cudaGetSymbolAddress((void**)&pmlp, g_mlp);

    rope_table_kernel<<<(SS*32 + 255)/256, 256>>>();
    embed_kernel<<<(M_TOK*DD + 255)/256, 256>>>(ids, iter, emb, iter_emb);

    for (int l = 0; l < NLL; l++) {
        rmsnorm_kernel<<<M_TOK, 128>>>(px, attn_norm + (size_t)l*DD, ph);
        sgemm64<false><<<dim3((3*DD)/64, M_TOK/64), 256>>>(ph, Wqkv + (size_t)l*3*DD*DD, pqkv, M_TOK, 3*DD, DD);
        rope_kernel<<<(M_TOK*NHH*32 + 255)/256, 256>>>();
        flash_attn_kernel<<<dim3(SS/128, NHH, BB), 128>>>();
        sgemm64<true><<<dim3(DD/64, M_TOK/64), 256>>>(patt, wo + (size_t)l*DD*DD, px, M_TOK, DD, DD);
        router_kernel<<<M_TOK/4, 128>>>(router + (size_t)l*DD);
        topk_kernel<<<BB, 1024>>>();
        gather_rmsnorm_kernel<<<M_SEL, 128>>>(mlp_norm + (size_t)l*DD);
        sgemm64<false><<<dim3((FFF+63)/64, (M_SEL+63)/64), 256>>>(phs, gate_w + (size_t)l*FFF*DD, pgate, M_SEL, FFF, DD);
        sgemm64<false><<<dim3((FFF+63)/64, (M_SEL+63)/64), 256>>>(phs, up_w + (size_t)l*FFF*DD, pup, M_SEL, FFF, DD);
        silu_kernel<<<(int)(((size_t)M_SEL*FFF + 255)/256), 256>>>();
        sgemm64<false><<<dim3(DD/64, (M_SEL+63)/64), 256>>>(pgate, down_w + (size_t)l*DD*FFF, pmlp, M_SEL, DD, FFF);
        scatter_kernel<<<M_SEL, 128>>>();
    }
    rmsnorm_kernel<<<M_TOK, 128>>>(px, fnorm, (float*)d_out);
}

// round 2
// speedup vs baseline: 1.2406x; 1.2406x over previous
#include <cuda_runtime.h>
#include <cuda_bf16.h>
#include <math.h>

#define BB 8
#define SS 2048
#define DD 320
#define NHH 5
#define HDD 64
#define FFF 864
#define NLL 6
#define KSEL 1638
#define M_TOK (BB*SS)      // 16384
#define M_SEL (BB*KSEL)    // 13104
#define EPSF 1e-6f

// ---------------- scratch (static device globals; no allocation) ----------------
__device__ float g_x[M_TOK*DD];
__device__ float g_h[M_TOK*DD];
__device__ float g_qkv[M_TOK*3*DD];
__device__ float g_q[M_TOK*DD];   // [B,NH,S,HD]
__device__ float g_k[M_TOK*DD];
__device__ float g_v[M_TOK*DD];
__device__ float g_att[M_TOK*DD]; // [B,S,D]
__device__ float g_probs[M_TOK];
__device__ int   g_tidx[M_SEL];
__device__ float g_tp[M_SEL];
__device__ float g_hs[M_SEL*DD];
__device__ float g_gate[M_SEL*FFF];
__device__ float g_up[M_SEL*FFF];
__device__ float g_mlp[M_SEL*DD];
__device__ float g_cos[SS*32];
__device__ float g_sin[SS*32];

// ---------------- rope tables ----------------
__global__ void rope_table_kernel() {
    int i = blockIdx.x*blockDim.x + threadIdx.x;
    if (i >= SS*32) return;
    int s = i / 32, d = i % 32;
    double freq = exp(-((double)(2*d)/64.0)*log(10000.0));
    double f = (double)s * freq;
    g_cos[i] = (float)cos(f);
    g_sin[i] = (float)sin(f);
}

// ---------------- embed ----------------
__global__ void embed_kernel(const int* __restrict__ ids, const int* __restrict__ iter,
                             const float* __restrict__ emb, const float* __restrict__ iter_emb) {
    int i = blockIdx.x*blockDim.x + threadIdx.x;
    if (i >= M_TOK*DD) return;
    int t = i / DD, d = i % DD;
    float v = emb[(size_t)ids[t]*DD + d];
    int it = iter[0];
    if (it < 8) v += iter_emb[(size_t)it*DD + d];
    g_x[i] = v;
}

// ---------------- rmsnorm (block per token) ----------------
__global__ void rmsnorm_kernel(const float* __restrict__ X, const float* __restrict__ w,
                               float* __restrict__ Y) {
    int t = blockIdx.x;
    const float* xr = X + (size_t)t*DD;
    float ss = 0.f;
    for (int d = threadIdx.x; d < DD; d += 128) { float v = xr[d]; ss += v*v; }
    #pragma unroll
    for (int o = 16; o > 0; o >>= 1) ss += __shfl_xor_sync(0xffffffffu, ss, o);
    __shared__ float red[4];
    if ((threadIdx.x & 31) == 0) red[threadIdx.x >> 5] = ss;
    __syncthreads();
    float tot = red[0]+red[1]+red[2]+red[3];
    float sc = rsqrtf(tot*(1.f/DD) + EPSF);
    for (int d = threadIdx.x; d < DD; d += 128) Y[(size_t)t*DD + d] = w[d]*xr[d]*sc;
}

// ---------------- SGEMM: C[M,N] (+)= A[M,K] * B[N,K]^T ; BM=BN=128, BK=16, 256 thr, 8x8 ----
template<bool ACCUM>
__global__ void __launch_bounds__(256, 2) sgemm128(const float* __restrict__ A, const float* __restrict__ Bm,
                        float* __restrict__ C, int M, int N, int K) {
    __shared__ float As[16*128];
    __shared__ float Bs[16*128];
    int tid = threadIdx.x;
    int tx = tid & 15, ty = tid >> 4;
    int row0 = blockIdx.y*128, col0 = blockIdx.x*128;
    int lr = tid >> 2;          // 0..63
    int lk = (tid & 3) * 4;     // 0,4,8,12
    float acc[8][8];
    #pragma unroll
    for (int i = 0; i < 8; i++)
        #pragma unroll
        for (int j = 0; j < 8; j++) acc[i][j] = 0.f;

    const float* Ap0 = A + (size_t)(row0+lr)*K + lk;
    const float* Ap1 = A + (size_t)(row0+lr+64)*K + lk;
    const float* Bp0 = Bm + (size_t)(col0+lr)*K + lk;
    const float* Bp1 = Bm + (size_t)(col0+lr+64)*K + lk;
    bool av0 = (row0+lr) < M, av1 = (row0+lr+64) < M;
    bool bv0 = (col0+lr) < N, bv1 = (col0+lr+64) < N;
    const float4 f40 = make_float4(0,0,0,0);
    float4 ra0 = av0 ? *(const float4*)Ap0 : f40;
    float4 ra1 = av1 ? *(const float4*)Ap1 : f40;
    float4 rb0 = bv0 ? *(const float4*)Bp0 : f40;
    float4 rb1 = bv1 ? *(const float4*)Bp1 : f40;

    int gswz = (tid & 3) << 3;  // swizzle for the 4 k's this thread stores
    for (int k0 = 0; k0 < K; k0 += 16) {
        __syncthreads();
        {
            const float* a0 = (const float*)&ra0;
            const float* a1 = (const float*)&ra1;
            const float* b0 = (const float*)&rb0;
            const float* b1 = (const float*)&rb1;
            #pragma unroll
            for (int j = 0; j < 4; j++) {
                int kk = lk + j;
                int c0 = lr ^ gswz;
                As[kk*128 + c0]      = a0[j];
                As[kk*128 + c0 + 64] = a1[j];
                Bs[kk*128 + c0]      = b0[j];
                Bs[kk*128 + c0 + 64] = b1[j];
            }
        }
        __syncthreads();
        if (k0 + 16 < K) {
            int off = (k0 + 16) >> 2;
            ra0 = av0 ? ((const float4*)Ap0)[off] : f40;
            ra1 = av1 ? ((const float4*)Ap1)[off] : f40;
            rb0 = bv0 ? ((const float4*)Bp0)[off] : f40;
            rb1 = bv1 ? ((const float4*)Bp1)[off] : f40;
        }
        #pragma unroll
        for (int kk = 0; kk < 16; kk++) {
            int g = ((kk >> 2) & 7) << 3;
            float a[8], b[8];
            *(float4*)&a[0] = *(const float4*)&As[kk*128 + ((ty*8) ^ g)];
            *(float4*)&a[4] = *(const float4*)&As[kk*128 + ((ty*8) ^ g) + 4];
            *(float4*)&b[0] = *(const float4*)&Bs[kk*128 + ((tx*8) ^ g)];
            *(float4*)&b[4] = *(const float4*)&Bs[kk*128 + ((tx*8) ^ g) + 4];
            #pragma unroll
            for (int i = 0; i < 8; i++)
                #pragma unroll
                for (int j = 0; j < 8; j++)
                    acc[i][j] += a[i]*b[j];
        }
    }
    #pragma unroll
    for (int i = 0; i < 8; i++) {
        int r = row0 + ty*8 + i;
        if (r < M) {
            #pragma unroll
            for (int j = 0; j < 8; j++) {
                int c = col0 + tx*8 + j;
                if (c < N) {
                    size_t off = (size_t)r*N + c;
                    if (ACCUM) C[off] += acc[i][j]; else C[off] = acc[i][j];
                }
            }
        }
    }
}

// ---------------- rope + split to [B,NH,S,HD] ----------------
__global__ void rope_kernel() {
    int i = blockIdx.x*blockDim.x + threadIdx.x;
    if (i >= M_TOK*NHH*32) return;
    int t = i / (NHH*32);
    int r = i % (NHH*32);
    int h = r / 32, d = r % 32;
    int b = t / SS, s = t % SS;
    const float* base = g_qkv + (size_t)t*(3*DD) + h*HDD;
    float c = g_cos[s*32+d], sn = g_sin[s*32+d];
    float q1 = base[d],        q2 = base[d+32];
    float k1 = base[DD+d],     k2 = base[DD+d+32];
    size_t o = ((size_t)(b*NHH+h)*SS + s)*HDD;
    g_q[o+d]    = q1*c - q2*sn;
    g_q[o+d+32] = q2*c + q1*sn;
    g_k[o+d]    = k1*c - k2*sn;
    g_k[o+d+32] = k2*c + k1*sn;
    g_v[o+d]    = base[2*DD+d];
    g_v[o+d+32] = base[2*DD+d+32];
}

// ---------------- flash attention v2: GEMM-style, 128q x 64k tiles, 8x8/thread --------
// dynamic smem: Qs[64][128] | Ks[64][64] | Vs[64][64] | Ps[64][128]  = 96KB
__global__ void __launch_bounds__(128) flash2_kernel() {
    extern __shared__ float sm[];
    float* Qs = sm;                    // transposed [d][q], swizzled
    float* Ks = sm + 64*128;           // transposed [d][k], swizzled
    float* Vs = sm + 64*128 + 64*64;   // natural [k][d]
    float* Ps = sm + 64*128 + 2*64*64; // [k][q], swizzled
    int b = blockIdx.z, h = blockIdx.y;
    int qb = (int)(gridDim.x - 1u - blockIdx.x);   // heavy blocks first
    int tid = threadIdx.x;
    int kx = tid & 7;        // k/d column group (8 cols)
    int qy = tid >> 3;       // q row group (8 rows), 0..15
    const float* Qp = g_q + ((size_t)(b*NHH+h)*SS)*HDD;
    const float* Kp = g_k + ((size_t)(b*NHH+h)*SS)*HDD;
    const float* Vp = g_v + ((size_t)(b*NHH+h)*SS)*HDD;

    // load Q tile (128 rows x 64 d), transposed + swizzled + scaled
    for (int i = tid; i < 128*16; i += 128) {
        int r = i >> 4, dc = (i & 15) << 2;
        float4 v = *(const float4*)&Qp[(size_t)(qb*128 + r)*64 + dc];
        float vv[4] = {v.x, v.y, v.z, v.w};
        #pragma unroll
        for (int j = 0; j < 4; j++) {
            int d = dc + j;
            int g = ((d >> 2) & 7) << 3;
            Qs[d*128 + (r ^ g)] = vv[j]*0.125f;
        }
    }

    float O[8][8];
    float m[8], l[8];
    #pragma unroll
    for (int i = 0; i < 8; i++) {
        m[i] = -1e30f; l[i] = 0.f;
        #pragma unroll
        for (int j = 0; j < 8; j++) O[i][j] = 0.f;
    }

    int ntiles = 2*qb + 2;
    for (int kt = 0; kt < ntiles; kt++) {
        __syncthreads();   // previous PV done before overwriting Ks/Vs
        for (int i = tid; i < 64*16; i += 128) {
            int r = i >> 4, dc = (i & 15) << 2;
            float4 kv = *(const float4*)&Kp[(size_t)(kt*64 + r)*64 + dc];
            float kk4[4] = {kv.x, kv.y, kv.z, kv.w};
            #pragma unroll
            for (int j = 0; j < 4; j++) {
                int d = dc + j;
                int g = ((d >> 2) & 7) << 3;
                Ks[d*64 + (r ^ g)] = kk4[j];
            }
            *(float4*)&Vs[r*64 + dc] = *(const float4*)&Vp[(size_t)(kt*64 + r)*64 + dc];
        }
        __syncthreads();

        // scores S[8q][8k]
        float s[8][8];
        #pragma unroll
        for (int i = 0; i < 8; i++)
            #pragma unroll
            for (int j = 0; j < 8; j++) s[i][j] = 0.f;
        #pragma unroll 8
        for (int d = 0; d < 64; d++) {
            int g = ((d >> 2) & 7) << 3;
            float a[8], bv[8];
            *(float4*)&a[0]  = *(const float4*)&Qs[d*128 + ((qy*8) ^ g)];
            *(float4*)&a[4]  = *(const float4*)&Qs[d*128 + ((qy*8) ^ g) + 4];
            *(float4*)&bv[0] = *(const float4*)&Ks[d*64  + ((kx*8) ^ g)];
            *(float4*)&bv[4] = *(const float4*)&Ks[d*64  + ((kx*8) ^ g) + 4];
            #pragma unroll
            for (int i = 0; i < 8; i++)
                #pragma unroll
                for (int j = 0; j < 8; j++)
                    s[i][j] += a[i]*bv[j];
        }
        // causal mask on diagonal tiles
        if (kt >= 2*qb) {
            int koff = (kt - 2*qb)*64;
            #pragma unroll
            for (int i = 0; i < 8; i++)
                #pragma unroll
                for (int j = 0; j < 8; j++)
                    if (koff + kx*8 + j > qy*8 + i) s[i][j] = -1e30f;
        }
        // online softmax update (per-row state replicated across 8 kx lanes)
        #pragma unroll
        for (int i = 0; i < 8; i++) {
            float rm = s[i][0];
            #pragma unroll
            for (int j = 1; j < 8; j++) rm = fmaxf(rm, s[i][j]);
            rm = fmaxf(rm, __shfl_xor_sync(0xffffffffu, rm, 1));
            rm = fmaxf(rm, __shfl_xor_sync(0xffffffffu, rm, 2));
            rm = fmaxf(rm, __shfl_xor_sync(0xffffffffu, rm, 4));
            float mn = fmaxf(m[i], rm);
            float cc = __expf(m[i] - mn);
            m[i] = mn;
            float rs = 0.f;
            #pragma unroll
            for (int j = 0; j < 8; j++) {
                float p = __expf(s[i][j] - mn);
                s[i][j] = p;
                rs += p;
            }
            rs += __shfl_xor_sync(0xffffffffu, rs, 1);
            rs += __shfl_xor_sync(0xffffffffu, rs, 2);
            rs += __shfl_xor_sync(0xffffffffu, rs, 4);
            l[i] = l[i]*cc + rs;
            #pragma unroll
            for (int j = 0; j < 8; j++) O[i][j] *= cc;
        }
        // store P -> Ps (k-major, swizzled)
        #pragma unroll
        for (int j = 0; j < 8; j++) {
            int k = kx*8 + j;
            int g = ((k >> 2) & 7) << 3;
            float4 p0 = make_float4(s[0][j], s[1][j], s[2][j], s[3][j]);
            float4 p1 = make_float4(s[4][j], s[5][j], s[6][j], s[7][j]);
            *(float4*)&Ps[k*128 + ((qy*8) ^ g)]     = p0;
            *(float4*)&Ps[k*128 + ((qy*8) ^ g) + 4] = p1;
        }
        __syncthreads();
        // O += P * V
        #pragma unroll 8
        for (int k = 0; k < 64; k++) {
            int g = ((k >> 2) & 7) << 3;
            float p[8], v[8];
            *(float4*)&p[0] = *(const float4*)&Ps[k*128 + ((qy*8) ^ g)];
            *(float4*)&p[4] = *(const float4*)&Ps[k*128 + ((qy*8) ^ g) + 4];
            *(float4*)&v[0] = *(const float4*)&Vs[k*64 + kx*8];
            *(float4*)&v[4] = *(const float4*)&Vs[k*64 + kx*8 + 4];
            #pragma unroll
            for (int i = 0; i < 8; i++)
                #pragma unroll
                for (int j = 0; j < 8; j++)
                    O[i][j] += p[i]*v[j];
        }
    }
    // epilogue
    #pragma unroll
    for (int i = 0; i < 8; i++) {
        float inv = 1.f/l[i];
        int row = qb*128 + qy*8 + i;
        float* op = g_att + ((size_t)b*SS + row)*DD + h*64 + kx*8;
        float4 o0 = make_float4(O[i][0]*inv, O[i][1]*inv, O[i][2]*inv, O[i][3]*inv);
        float4 o1 = make_float4(O[i][4]*inv, O[i][5]*inv, O[i][6]*inv, O[i][7]*inv);
        *(float4*)&op[0] = o0;
        *(float4*)&op[4] = o1;
    }
}

// ---------------- router ----------------
__global__ void router_kernel(const float* __restrict__ rw) {
    int t = blockIdx.x*4 + (threadIdx.x >> 5);
    int lane = threadIdx.x & 31;
    const float* xr = g_x + (size_t)t*DD;
    float s = 0.f;
    for (int d = lane; d < DD; d += 32) s += xr[d]*rw[d];
    #pragma unroll
    for (int o = 16; o > 0; o >>= 1) s += __shfl_xor_sync(0xffffffffu, s, o);
    if (lane == 0) g_probs[t] = 1.f/(1.f + __expf(-s));
}

// ---------------- per-batch top-k via bitonic sort ----------------
__global__ void topk_kernel() {
    __shared__ float sv[2048];
    __shared__ int   si[2048];
    int bb = blockIdx.x;
    for (int i = threadIdx.x; i < 2048; i += 1024) { sv[i] = g_probs[(size_t)bb*SS + i]; si[i] = i; }
    __syncthreads();
    for (int k = 2; k <= 2048; k <<= 1) {
        for (int j = k >> 1; j > 0; j >>= 1) {
            for (int t = threadIdx.x; t < 2048; t += 1024) {
                int ixj = t ^ j;
                if (ixj > t) {
                    bool desc = ((t & k) == 0);
                    float a = sv[t], b2 = sv[ixj];
                    bool sw = desc ? (a < b2) : (a > b2);
                    if (sw) {
                        sv[t] = b2; sv[ixj] = a;
                        int tmp = si[t]; si[t] = si[ixj]; si[ixj] = tmp;
                    }
                }
            }
            __syncthreads();
        }
    }
    for (int i = threadIdx.x; i < KSEL; i += 1024) {
        g_tidx[(size_t)bb*KSEL + i] = si[i];
        g_tp[(size_t)bb*KSEL + i]   = sv[i];
    }
}

// ---------------- gather + rmsnorm ----------------
__global__ void gather_rmsnorm_kernel(const float* __restrict__ w) {
    int i = blockIdx.x;
    int b = i / KSEL;
    int tok = g_tidx[i];
    const float* xr = g_x + ((size_t)b*SS + tok)*DD;
    float ss = 0.f;
    for (int d = threadIdx.x; d < DD; d += 128) { float v = xr[d]; ss += v*v; }
    #pragma unroll
    for (int o = 16; o > 0; o >>= 1) ss += __shfl_xor_sync(0xffffffffu, ss, o);
    __shared__ float red[4];
    if ((threadIdx.x & 31) == 0) red[threadIdx.x >> 5] = ss;
    __syncthreads();
    float tot = red[0]+red[1]+red[2]+red[3];
    float sc = rsqrtf(tot*(1.f/DD) + EPSF);
    for (int d = threadIdx.x; d < DD; d += 128) g_hs[(size_t)i*DD + d] = w[d]*xr[d]*sc;
}

// ---------------- silu(gate)*up ----------------
__global__ void silu_kernel() {
    size_t i = (size_t)blockIdx.x*blockDim.x + threadIdx.x;
    if (i >= (size_t)M_SEL*FFF) return;
    float g = g_gate[i];
    float u = g_up[i];
    float sig = 1.f/(1.f + __expf(-g));
    g_gate[i] = g*sig*u;
}

// ---------------- scaled scatter-add ----------------
__global__ void scatter_kernel() {
    int i = blockIdx.x;
    int b = i / KSEL;
    int tok = g_tidx[i];
    float p = g_tp[i];
    float* xr = g_x + ((size_t)b*SS + tok)*DD;
    const float* mr = g_mlp + (size_t)i*DD;
    for (int d = threadIdx.x; d < DD; d += 128) xr[d] += mr[d]*p;
}

// ---------------- host orchestration ----------------
extern "C" void kernel_launch(void* const* d_in, const int* in_sizes, int n_in,
                              void* d_out, int out_size) {
    const int*   ids       = (const int*)d_in[0];
    const int*   iter      = (const int*)d_in[1];
    const float* emb       = (const float*)d_in[2];
    const float* iter_emb  = (const float*)d_in[3];
    const float* attn_norm = (const float*)d_in[4];
    const float* Wqkv      = (const float*)d_in[5];
    const float* wo        = (const float*)d_in[6];
    const float* router    = (const float*)d_in[7];
    const float* mlp_norm  = (const float*)d_in[8];
    const float* gate_w    = (const float*)d_in[9];
    const float* up_w      = (const float*)d_in[10];
    const float* down_w    = (const float*)d_in[11];
    const float* fnorm     = (const float*)d_in[12];

    float *px, *ph, *pqkv, *patt, *phs, *pgate, *pup, *pmlp;
    cudaGetSymbolAddress((void**)&px,   g_x);
    cudaGetSymbolAddress((void**)&ph,   g_h);
    cudaGetSymbolAddress((void**)&pqkv, g_qkv);
    cudaGetSymbolAddress((void**)&patt, g_att);
    cudaGetSymbolAddress((void**)&phs,  g_hs);
    cudaGetSymbolAddress((void**)&pgate,g_gate);
    cudaGetSymbolAddress((void**)&pup,  g_up);
    cudaGetSymbolAddress((void**)&pmlp, g_mlp);

    cudaFuncSetAttribute(flash2_kernel, cudaFuncAttributeMaxDynamicSharedMemorySize, 98304);

    rope_table_kernel<<<(SS*32 + 255)/256, 256>>>();
    embed_kernel<<<(M_TOK*DD + 255)/256, 256>>>(ids, iter, emb, iter_emb);

    for (int l = 0; l < NLL; l++) {
        rmsnorm_kernel<<<M_TOK, 128>>>(px, attn_norm + (size_t)l*DD, ph);
        sgemm128<false><<<dim3((3*DD+127)/128, M_TOK/128), 256>>>(ph, Wqkv + (size_t)l*3*DD*DD, pqkv, M_TOK, 3*DD, DD);
        rope_kernel<<<(M_TOK*NHH*32 + 255)/256, 256>>>();
        flash2_kernel<<<dim3(SS/128, NHH, BB), 128, 98304>>>();
        sgemm128<true><<<dim3((DD+127)/128, M_TOK/128), 256>>>(patt, wo + (size_t)l*DD*DD, px, M_TOK, DD, DD);
        router_kernel<<<M_TOK/4, 128>>>(router + (size_t)l*DD);
        topk_kernel<<<BB, 1024>>>();
        gather_rmsnorm_kernel<<<M_SEL, 128>>>(mlp_norm + (size_t)l*DD);
        sgemm128<false><<<dim3((FFF+127)/128, (M_SEL+127)/128), 256>>>(phs, gate_w + (size_t)l*FFF*DD, pgate, M_SEL, FFF, DD);
        sgemm128<false><<<dim3((FFF+127)/128, (M_SEL+127)/128), 256>>>(phs, up_w + (size_t)l*FFF*DD, pup, M_SEL, FFF, DD);
        silu_kernel<<<(int)(((size_t)M_SEL*FFF + 255)/256), 256>>>();
        sgemm128<false><<<dim3((DD+127)/128, (M_SEL+127)/128), 256>>>(pgate, down_w + (size_t)l*DD*FFF, pmlp, M_SEL, DD, FFF);
        scatter_kernel<<<M_SEL, 128>>>();
    }
    rmsnorm_kernel<<<M_TOK, 128>>>(px, fnorm, (float*)d_out);
}

// round 3
// speedup vs baseline: 1.7200x; 1.3865x over previous
#include <cuda_runtime.h>
#include <cuda_bf16.h>
#include <math.h>
#include <stdint.h>

#define BB 8
#define SS 2048
#define DD 320
#define NHH 5
#define HDD 64
#define FFF 864
#define NLL 6
#define KSEL 1638
#define M_TOK (BB*SS)      // 16384
#define M_SEL (BB*KSEL)    // 13104
#define EPSF 1e-6f

// ---------------- scratch (static device globals; no allocation) ----------------
__device__ float g_x[M_TOK*DD];
__device__ float g_h[M_TOK*DD];
__device__ float g_qkv[M_TOK*3*DD];
__device__ float g_q[M_TOK*DD];   // [B,NH,S,HD]
__device__ float g_k[M_TOK*DD];
__device__ float g_v[M_TOK*DD];
__device__ float g_att[M_TOK*DD]; // [B,S,D]
__device__ float g_probs[M_TOK];
__device__ int   g_tidx[M_SEL];
__device__ float g_tp[M_SEL];
__device__ float g_hs[M_SEL*DD];
__device__ float g_gate[M_SEL*FFF];
__device__ float g_up[M_SEL*FFF];
__device__ float g_mlp[M_SEL*DD];
__device__ float g_cos[SS*32];
__device__ float g_sin[SS*32];

// ---------------- rope tables ----------------
__global__ void rope_table_kernel() {
    int i = blockIdx.x*blockDim.x + threadIdx.x;
    if (i >= SS*32) return;
    int s = i / 32, d = i % 32;
    double freq = exp(-((double)(2*d)/64.0)*log(10000.0));
    double f = (double)s * freq;
    g_cos[i] = (float)cos(f);
    g_sin[i] = (float)sin(f);
}

// ---------------- embed ----------------
__global__ void embed_kernel(const int* __restrict__ ids, const int* __restrict__ iter,
                             const float* __restrict__ emb, const float* __restrict__ iter_emb) {
    int i = blockIdx.x*blockDim.x + threadIdx.x;
    if (i >= M_TOK*DD) return;
    int t = i / DD, d = i % DD;
    float v = emb[(size_t)ids[t]*DD + d];
    int it = iter[0];
    if (it < 8) v += iter_emb[(size_t)it*DD + d];
    g_x[i] = v;
}

// ---------------- rmsnorm (block per token) ----------------
__global__ void rmsnorm_kernel(const float* __restrict__ X, const float* __restrict__ w,
                               float* __restrict__ Y) {
    int t = blockIdx.x;
    const float* xr = X + (size_t)t*DD;
    float ss = 0.f;
    for (int d = threadIdx.x; d < DD; d += 128) { float v = xr[d]; ss += v*v; }
    #pragma unroll
    for (int o = 16; o > 0; o >>= 1) ss += __shfl_xor_sync(0xffffffffu, ss, o);
    __shared__ float red[4];
    if ((threadIdx.x & 31) == 0) red[threadIdx.x >> 5] = ss;
    __syncthreads();
    float tot = red[0]+red[1]+red[2]+red[3];
    float sc = rsqrtf(tot*(1.f/DD) + EPSF);
    for (int d = threadIdx.x; d < DD; d += 128) Y[(size_t)t*DD + d] = w[d]*xr[d]*sc;
}

// ================= tensor-core GEMM (bf16 split, error-compensated) =================
// C[M,N] (+)= A[M,K] * B[N,K]^T.  A,B fp32 row-major. Split x=h+l (bf16 each),
// C = Ah*Bh + Ah*Bl + Al*Bh (fp32 accum). 128x128x16 tiles, 8 warps (64x32 each).

__device__ __forceinline__ void ldsm_x4(uint32_t* r, const __nv_bfloat16* p) {
    uint32_t addr = (uint32_t)__cvta_generic_to_shared(p);
    asm volatile("ldmatrix.sync.aligned.m8n8.x4.shared.b16 {%0,%1,%2,%3}, [%4];"
                 : "=r"(r[0]), "=r"(r[1]), "=r"(r[2]), "=r"(r[3]) : "r"(addr));
}

__device__ __forceinline__ void mma_bf16(float* c, const uint32_t* a, uint32_t b0, uint32_t b1) {
    asm volatile(
        "mma.sync.aligned.m16n8k16.row.col.f32.bf16.bf16.f32 "
        "{%0,%1,%2,%3}, {%4,%5,%6,%7}, {%8,%9}, {%0,%1,%2,%3};\n"
        : "+f"(c[0]), "+f"(c[1]), "+f"(c[2]), "+f"(c[3])
        : "r"(a[0]), "r"(a[1]), "r"(a[2]), "r"(a[3]), "r"(b0), "r"(b1));
}

#define LDSTR 24   // smem row stride in halves (48B, /16 odd -> ldsm conflict-free)

template<bool ACCUM>
__global__ void __launch_bounds__(256) gemm_tc(const float* __restrict__ A, const float* __restrict__ Bm,
                                               float* __restrict__ C, int M, int N, int K) {
    __shared__ __nv_bfloat16 sm[4*128*LDSTR];
    __nv_bfloat16* sAh = sm;
    __nv_bfloat16* sAl = sm + 128*LDSTR;
    __nv_bfloat16* sBh = sm + 2*128*LDSTR;
    __nv_bfloat16* sBl = sm + 3*128*LDSTR;

    int tid = threadIdx.x;
    int lane = tid & 31, wid = tid >> 5;
    int wm = (wid & 1) * 64;       // warp m offset
    int wn = (wid >> 1) * 32;      // warp n offset
    int row0 = blockIdx.y * 128, col0 = blockIdx.x * 128;

    // staging: each thread loads 8 floats of A and 8 of B per k-stage
    int srow = tid >> 1;           // 0..127
    int scol = (tid & 1) * 8;      // 0 or 8
    const float* Ap = A + (size_t)(row0 + srow) * K + scol;
    const float* Bp = Bm + (size_t)(col0 + srow) * K + scol;
    bool aval = (row0 + srow) < M;
    bool bval = (col0 + srow) < N;

    float acc[4][4][4];
    #pragma unroll
    for (int i = 0; i < 4; i++)
        #pragma unroll
        for (int j = 0; j < 4; j++)
            #pragma unroll
            for (int r = 0; r < 4; r++) acc[i][j][r] = 0.f;

    // ldmatrix per-lane addresses
    int a_r = lane & 15;
    int a_c = ((lane >> 4) & 1) * 8;
    int b_r = (lane & 7) + ((lane >> 4) & 1) * 8;
    int b_c = ((lane >> 3) & 1) * 8;
    int aoff[4], boff[2];
    #pragma unroll
    for (int mt = 0; mt < 4; mt++) aoff[mt] = (wm + mt*16 + a_r)*LDSTR + a_c;
    #pragma unroll
    for (int pr = 0; pr < 2; pr++) boff[pr] = (wn + pr*16 + b_r)*LDSTR + b_c;

    const float4 fz = make_float4(0,0,0,0);
    float4 ra0, ra1, rb0, rb1;
    ra0 = aval ? *(const float4*)(Ap + 0) : fz;
    ra1 = aval ? *(const float4*)(Ap + 4) : fz;
    rb0 = bval ? *(const float4*)(Bp + 0) : fz;
    rb1 = bval ? *(const float4*)(Bp + 4) : fz;

    int nk = K >> 4;
    for (int ks = 0; ks < nk; ks++) {
        __syncthreads();
        {
            float av[8] = {ra0.x, ra0.y, ra0.z, ra0.w, ra1.x, ra1.y, ra1.z, ra1.w};
            float bv[8] = {rb0.x, rb0.y, rb0.z, rb0.w, rb1.x, rb1.y, rb1.z, rb1.w};
            #pragma unroll
            for (int p = 0; p < 4; p++) {
                float x0 = av[2*p], x1 = av[2*p+1];
                __nv_bfloat162 hh, ll;
                hh.x = __float2bfloat16_rn(x0);
                hh.y = __float2bfloat16_rn(x1);
                ll.x = __float2bfloat16_rn(x0 - __bfloat162float(hh.x));
                ll.y = __float2bfloat16_rn(x1 - __bfloat162float(hh.y));
                *(__nv_bfloat162*)&sAh[srow*LDSTR + scol + 2*p] = hh;
                *(__nv_bfloat162*)&sAl[srow*LDSTR + scol + 2*p] = ll;
                float y0 = bv[2*p], y1 = bv[2*p+1];
                __nv_bfloat162 gh, gl;
                gh.x = __float2bfloat16_rn(y0);
                gh.y = __float2bfloat16_rn(y1);
                gl.x = __float2bfloat16_rn(y0 - __bfloat162float(gh.x));
                gl.y = __float2bfloat16_rn(y1 - __bfloat162float(gh.y));
                *(__nv_bfloat162*)&sBh[srow*LDSTR + scol + 2*p] = gh;
                *(__nv_bfloat162*)&sBl[srow*LDSTR + scol + 2*p] = gl;
            }
        }
        __syncthreads();
        if (ks + 1 < nk) {
            int k0 = (ks + 1) << 4;
            ra0 = aval ? *(const float4*)(Ap + k0)     : fz;
            ra1 = aval ? *(const float4*)(Ap + k0 + 4) : fz;
            rb0 = bval ? *(const float4*)(Bp + k0)     : fz;
            rb1 = bval ? *(const float4*)(Bp + k0 + 4) : fz;
        }

        uint32_t Ah[4][4], Al[4][4], Bh[2][4], Bl[2][4];
        #pragma unroll
        for (int mt = 0; mt < 4; mt++) { ldsm_x4(Ah[mt], sAh + aoff[mt]); ldsm_x4(Al[mt], sAl + aoff[mt]); }
        #pragma unroll
        for (int pr = 0; pr < 2; pr++) { ldsm_x4(Bh[pr], sBh + boff[pr]); ldsm_x4(Bl[pr], sBl + boff[pr]); }

        #pragma unroll
        for (int mt = 0; mt < 4; mt++)
            #pragma unroll
            for (int nt = 0; nt < 4; nt++)
                mma_bf16(acc[mt][nt], Ah[mt], Bh[nt>>1][(nt&1)*2], Bh[nt>>1][(nt&1)*2+1]);
        #pragma unroll
        for (int mt = 0; mt < 4; mt++)
            #pragma unroll
            for (int nt = 0; nt < 4; nt++)
                mma_bf16(acc[mt][nt], Ah[mt], Bl[nt>>1][(nt&1)*2], Bl[nt>>1][(nt&1)*2+1]);
        #pragma unroll
        for (int mt = 0; mt < 4; mt++)
            #pragma unroll
            for (int nt = 0; nt < 4; nt++)
                mma_bf16(acc[mt][nt], Al[mt], Bh[nt>>1][(nt&1)*2], Bh[nt>>1][(nt&1)*2+1]);
    }

    // epilogue
    int erow = lane >> 2;
    int ecol = (lane & 3) * 2;
    #pragma unroll
    for (int mt = 0; mt < 4; mt++) {
        #pragma unroll
        for (int nt = 0; nt < 4; nt++) {
            int r = row0 + wm + mt*16 + erow;
            int c = col0 + wn + nt*8 + ecol;
            if (c < N) {
                if (r < M) {
                    float2* p = (float2*)&C[(size_t)r*N + c];
                    if (ACCUM) { float2 o = *p; o.x += acc[mt][nt][0]; o.y += acc[mt][nt][1]; *p = o; }
                    else { float2 o; o.x = acc[mt][nt][0]; o.y = acc[mt][nt][1]; *p = o; }
                }
                if (r + 8 < M) {
                    float2* p = (float2*)&C[(size_t)(r+8)*N + c];
                    if (ACCUM) { float2 o = *p; o.x += acc[mt][nt][2]; o.y += acc[mt][nt][3]; *p = o; }
                    else { float2 o; o.x = acc[mt][nt][2]; o.y = acc[mt][nt][3]; *p = o; }
                }
            }
        }
    }
}

// ---------------- rope + split to [B,NH,S,HD] ----------------
__global__ void rope_kernel() {
    int i = blockIdx.x*blockDim.x + threadIdx.x;
    if (i >= M_TOK*NHH*32) return;
    int t = i / (NHH*32);
    int r = i % (NHH*32);
    int h = r / 32, d = r % 32;
    int b = t / SS, s = t % SS;
    const float* base = g_qkv + (size_t)t*(3*DD) + h*HDD;
    float c = g_cos[s*32+d], sn = g_sin[s*32+d];
    float q1 = base[d],        q2 = base[d+32];
    float k1 = base[DD+d],     k2 = base[DD+d+32];
    size_t o = ((size_t)(b*NHH+h)*SS + s)*HDD;
    g_q[o+d]    = q1*c - q2*sn;
    g_q[o+d+32] = q2*c + q1*sn;
    g_k[o+d]    = k1*c - k2*sn;
    g_k[o+d+32] = k2*c + k1*sn;
    g_v[o+d]    = base[2*DD+d];
    g_v[o+d+32] = base[2*DD+d+32];
}

// ---------------- flash attention v2: GEMM-style, 128q x 64k tiles, 8x8/thread --------
__global__ void __launch_bounds__(128) flash2_kernel() {
    extern __shared__ float smf[];
    float* Qs = smf;
    float* Ks = smf + 64*128;
    float* Vs = smf + 64*128 + 64*64;
    float* Ps = smf + 64*128 + 2*64*64;
    int b = blockIdx.z, h = blockIdx.y;
    int qb = (int)(gridDim.x - 1u - blockIdx.x);
    int tid = threadIdx.x;
    int kx = tid & 7;
    int qy = tid >> 3;
    const float* Qp = g_q + ((size_t)(b*NHH+h)*SS)*HDD;
    const float* Kp = g_k + ((size_t)(b*NHH+h)*SS)*HDD;
    const float* Vp = g_v + ((size_t)(b*NHH+h)*SS)*HDD;

    for (int i = tid; i < 128*16; i += 128) {
        int r = i >> 4, dc = (i & 15) << 2;
        float4 v = *(const float4*)&Qp[(size_t)(qb*128 + r)*64 + dc];
        float vv[4] = {v.x, v.y, v.z, v.w};
        #pragma unroll
        for (int j = 0; j < 4; j++) {
            int d = dc + j;
            int g = ((d >> 2) & 7) << 3;
            Qs[d*128 + (r ^ g)] = vv[j]*0.125f;
        }
    }

    float O[8][8];
    float m[8], l[8];
    #pragma unroll
    for (int i = 0; i < 8; i++) {
        m[i] = -1e30f; l[i] = 0.f;
        #pragma unroll
        for (int j = 0; j < 8; j++) O[i][j] = 0.f;
    }

    int ntiles = 2*qb + 2;
    for (int kt = 0; kt < ntiles; kt++) {
        __syncthreads();
        for (int i = tid; i < 64*16; i += 128) {
            int r = i >> 4, dc = (i & 15) << 2;
            float4 kv = *(const float4*)&Kp[(size_t)(kt*64 + r)*64 + dc];
            float kk4[4] = {kv.x, kv.y, kv.z, kv.w};
            #pragma unroll
            for (int j = 0; j < 4; j++) {
                int d = dc + j;
                int g = ((d >> 2) & 7) << 3;
                Ks[d*64 + (r ^ g)] = kk4[j];
            }
            *(float4*)&Vs[r*64 + dc] = *(const float4*)&Vp[(size_t)(kt*64 + r)*64 + dc];
        }
        __syncthreads();

        float s[8][8];
        #pragma unroll
        for (int i = 0; i < 8; i++)
            #pragma unroll
            for (int j = 0; j < 8; j++) s[i][j] = 0.f;
        #pragma unroll 8
        for (int d = 0; d < 64; d++) {
            int g = ((d >> 2) & 7) << 3;
            float a[8], bv[8];
            *(float4*)&a[0]  = *(const float4*)&Qs[d*128 + ((qy*8) ^ g)];
            *(float4*)&a[4]  = *(const float4*)&Qs[d*128 + ((qy*8) ^ g) + 4];
            *(float4*)&bv[0] = *(const float4*)&Ks[d*64  + ((kx*8) ^ g)];
            *(float4*)&bv[4] = *(const float4*)&Ks[d*64  + ((kx*8) ^ g) + 4];
            #pragma unroll
            for (int i = 0; i < 8; i++)
                #pragma unroll
                for (int j = 0; j < 8; j++)
                    s[i][j] += a[i]*bv[j];
        }
        if (kt >= 2*qb) {
            int koff = (kt - 2*qb)*64;
            #pragma unroll
            for (int i = 0; i < 8; i++)
                #pragma unroll
                for (int j = 0; j < 8; j++)
                    if (koff + kx*8 + j > qy*8 + i) s[i][j] = -1e30f;
        }
        #pragma unroll
        for (int i = 0; i < 8; i++) {
            float rm = s[i][0];
            #pragma unroll
            for (int j = 1; j < 8; j++) rm = fmaxf(rm, s[i][j]);
            rm = fmaxf(rm, __shfl_xor_sync(0xffffffffu, rm, 1));
            rm = fmaxf(rm, __shfl_xor_sync(0xffffffffu, rm, 2));
            rm = fmaxf(rm, __shfl_xor_sync(0xffffffffu, rm, 4));
            float mn = fmaxf(m[i], rm);
            float cc = __expf(m[i] - mn);
            m[i] = mn;
            float rs = 0.f;
            #pragma unroll
            for (int j = 0; j < 8; j++) {
                float p = __expf(s[i][j] - mn);
                s[i][j] = p;
                rs += p;
            }
            rs += __shfl_xor_sync(0xffffffffu, rs, 1);
            rs += __shfl_xor_sync(0xffffffffu, rs, 2);
            rs += __shfl_xor_sync(0xffffffffu, rs, 4);
            l[i] = l[i]*cc + rs;
            #pragma unroll
            for (int j = 0; j < 8; j++) O[i][j] *= cc;
        }
        #pragma unroll
        for (int j = 0; j < 8; j++) {
            int k = kx*8 + j;
            int g = ((k >> 2) & 7) << 3;
            float4 p0 = make_float4(s[0][j], s[1][j], s[2][j], s[3][j]);
            float4 p1 = make_float4(s[4][j], s[5][j], s[6][j], s[7][j]);
            *(float4*)&Ps[k*128 + ((qy*8) ^ g)]     = p0;
            *(float4*)&Ps[k*128 + ((qy*8) ^ g) + 4] = p1;
        }
        __syncthreads();
        #pragma unroll 8
        for (int k = 0; k < 64; k++) {
            int g = ((k >> 2) & 7) << 3;
            float p[8], v[8];
            *(float4*)&p[0] = *(const float4*)&Ps[k*128 + ((qy*8) ^ g)];
            *(float4*)&p[4] = *(const float4*)&Ps[k*128 + ((qy*8) ^ g) + 4];
            *(float4*)&v[0] = *(const float4*)&Vs[k*64 + kx*8];
            *(float4*)&v[4] = *(const float4*)&Vs[k*64 + kx*8 + 4];
            #pragma unroll
            for (int i = 0; i < 8; i++)
                #pragma unroll
                for (int j = 0; j < 8; j++)
                    O[i][j] += p[i]*v[j];
        }
    }
    #pragma unroll
    for (int i = 0; i < 8; i++) {
        float inv = 1.f/l[i];
        int row = qb*128 + qy*8 + i;
        float* op = g_att + ((size_t)b*SS + row)*DD + h*64 + kx*8;
        float4 o0 = make_float4(O[i][0]*inv, O[i][1]*inv, O[i][2]*inv, O[i][3]*inv);
        float4 o1 = make_float4(O[i][4]*inv, O[i][5]*inv, O[i][6]*inv, O[i][7]*inv);
        *(float4*)&op[0] = o0;
        *(float4*)&op[4] = o1;
    }
}

// ---------------- router ----------------
__global__ void router_kernel(const float* __restrict__ rw) {
    int t = blockIdx.x*4 + (threadIdx.x >> 5);
    int lane = threadIdx.x & 31;
    const float* xr = g_x + (size_t)t*DD;
    float s = 0.f;
    for (int d = lane; d < DD; d += 32) s += xr[d]*rw[d];
    #pragma unroll
    for (int o = 16; o > 0; o >>= 1) s += __shfl_xor_sync(0xffffffffu, s, o);
    if (lane == 0) g_probs[t] = 1.f/(1.f + __expf(-s));
}

// ---------------- per-batch top-k via bitonic sort ----------------
__global__ void topk_kernel() {
    __shared__ float sv[2048];
    __shared__ int   si[2048];
    int bb = blockIdx.x;
    for (int i = threadIdx.x; i < 2048; i += 1024) { sv[i] = g_probs[(size_t)bb*SS + i]; si[i] = i; }
    __syncthreads();
    for (int k = 2; k <= 2048; k <<= 1) {
        for (int j = k >> 1; j > 0; j >>= 1) {
            for (int t = threadIdx.x; t < 2048; t += 1024) {
                int ixj = t ^ j;
                if (ixj > t) {
                    bool desc = ((t & k) == 0);
                    float a = sv[t], b2 = sv[ixj];
                    bool sw = desc ? (a < b2) : (a > b2);
                    if (sw) {
                        sv[t] = b2; sv[ixj] = a;
                        int tmp = si[t]; si[t] = si[ixj]; si[ixj] = tmp;
                    }
                }
            }
            __syncthreads();
        }
    }
    for (int i = threadIdx.x; i < KSEL; i += 1024) {
        g_tidx[(size_t)bb*KSEL + i] = si[i];
        g_tp[(size_t)bb*KSEL + i]   = sv[i];
    }
}

// ---------------- gather + rmsnorm ----------------
__global__ void gather_rmsnorm_kernel(const float* __restrict__ w) {
    int i = blockIdx.x;
    int b = i / KSEL;
    int tok = g_tidx[i];
    const float* xr = g_x + ((size_t)b*SS + tok)*DD;
    float ss = 0.f;
    for (int d = threadIdx.x; d < DD; d += 128) { float v = xr[d]; ss += v*v; }
    #pragma unroll
    for (int o = 16; o > 0; o >>= 1) ss += __shfl_xor_sync(0xffffffffu, ss, o);
    __shared__ float red[4];
    if ((threadIdx.x & 31) == 0) red[threadIdx.x >> 5] = ss;
    __syncthreads();
    float tot = red[0]+red[1]+red[2]+red[3];
    float sc = rsqrtf(tot*(1.f/DD) + EPSF);
    for (int d = threadIdx.x; d < DD; d += 128) g_hs[(size_t)i*DD + d] = w[d]*xr[d]*sc;
}

// ---------------- silu(gate)*up ----------------
__global__ void silu_kernel() {
    size_t i = (size_t)blockIdx.x*blockDim.x + threadIdx.x;
    if (i >= (size_t)M_SEL*FFF) return;
    float g = g_gate[i];
    float u = g_up[i];
    float sig = 1.f/(1.f + __expf(-g));
    g_gate[i] = g*sig*u;
}

// ---------------- scaled scatter-add ----------------
__global__ void scatter_kernel() {
    int i = blockIdx.x;
    int b = i / KSEL;
    int tok = g_tidx[i];
    float p = g_tp[i];
    float* xr = g_x + ((size_t)b*SS + tok)*DD;
    const float* mr = g_mlp + (size_t)i*DD;
    for (int d = threadIdx.x; d < 128 ? d < DD : false; d += 128) xr[d] += mr[d]*p;
}

// fixed scatter (explicit loop)
__global__ void scatter_kernel2() {
    int i = blockIdx.x;
    int b = i / KSEL;
    int tok = g_tidx[i];
    float p = g_tp[i];
    float* xr = g_x + ((size_t)b*SS + tok)*DD;
    const float* mr = g_mlp + (size_t)i*DD;
    for (int d = threadIdx.x; d < DD; d += 128) xr[d] += mr[d]*p;
}

// ---------------- host orchestration ----------------
extern "C" void kernel_launch(void* const* d_in, const int* in_sizes, int n_in,
                              void* d_out, int out_size) {
    const int*   ids       = (const int*)d_in[0];
    const int*   iter      = (const int*)d_in[1];
    const float* emb       = (const float*)d_in[2];
    const float* iter_emb  = (const float*)d_in[3];
    const float* attn_norm = (const float*)d_in[4];
    const float* Wqkv      = (const float*)d_in[5];
    const float* wo        = (const float*)d_in[6];
    const float* router    = (const float*)d_in[7];
    const float* mlp_norm  = (const float*)d_in[8];
    const float* gate_w    = (const float*)d_in[9];
    const float* up_w      = (const float*)d_in[10];
    const float* down_w    = (const float*)d_in[11];
    const float* fnorm     = (const float*)d_in[12];

    float *px, *ph, *pqkv, *patt, *phs, *pgate, *pup, *pmlp;
    cudaGetSymbolAddress((void**)&px,   g_x);
    cudaGetSymbolAddress((void**)&ph,   g_h);
    cudaGetSymbolAddress((void**)&pqkv, g_qkv);
    cudaGetSymbolAddress((void**)&patt, g_att);
    cudaGetSymbolAddress((void**)&phs,  g_hs);
    cudaGetSymbolAddress((void**)&pgate,g_gate);
    cudaGetSymbolAddress((void**)&pup,  g_up);
    cudaGetSymbolAddress((void**)&pmlp, g_mlp);

    cudaFuncSetAttribute(flash2_kernel, cudaFuncAttributeMaxDynamicSharedMemorySize, 98304);

    rope_table_kernel<<<(SS*32 + 255)/256, 256>>>();
    embed_kernel<<<(M_TOK*DD + 255)/256, 256>>>(ids, iter, emb, iter_emb);

    for (int l = 0; l < NLL; l++) {
        rmsnorm_kernel<<<M_TOK, 128>>>(px, attn_norm + (size_t)l*DD, ph);
        gemm_tc<false><<<dim3((3*DD+127)/128, M_TOK/128), 256>>>(ph, Wqkv + (size_t)l*3*DD*DD, pqkv, M_TOK, 3*DD, DD);
        rope_kernel<<<(M_TOK*NHH*32 + 255)/256, 256>>>();
        flash2_kernel<<<dim3(SS/128, NHH, BB), 128, 98304>>>();
        gemm_tc<true><<<dim3((DD+127)/128, M_TOK/128), 256>>>(patt, wo + (size_t)l*DD*DD, px, M_TOK, DD, DD);
        router_kernel<<<M_TOK/4, 128>>>(router + (size_t)l*DD);
        topk_kernel<<<BB, 1024>>>();
        gather_rmsnorm_kernel<<<M_SEL, 128>>>(mlp_norm + (size_t)l*DD);
        gemm_tc<false><<<dim3((FFF+127)/128, (M_SEL+127)/128), 256>>>(phs, gate_w + (size_t)l*FFF*DD, pgate, M_SEL, FFF, DD);
        gemm_tc<false><<<dim3((FFF+127)/128, (M_SEL+127)/128), 256>>>(phs, up_w + (size_t)l*FFF*DD, pup, M_SEL, FFF, DD);
        silu_kernel<<<(int)(((size_t)M_SEL*FFF + 255)/256), 256>>>();
        gemm_tc<false><<<dim3((DD+127)/128, (M_SEL+127)/128), 256>>>(pgate, down_w + (size_t)l*DD*FFF, pmlp, M_SEL, DD, FFF);
        scatter_kernel2<<<M_SEL, 128>>>();
    }
    rmsnorm_kernel<<<M_TOK, 128>>>(px, fnorm, (float*)d_out);
}

// round 4
// speedup vs baseline: 2.7819x; 1.6174x over previous
#include <cuda_runtime.h>
#include <cuda_bf16.h>
#include <math.h>
#include <stdint.h>

#define BB 8
#define SS 2048
#define DD 320
#define NHH 5
#define HDD 64
#define FFF 864
#define NLL 6
#define KSEL 1638
#define M_TOK (BB*SS)      // 16384
#define M_SEL (BB*KSEL)    // 13104
#define EPSF 1e-6f

// ---------------- scratch (static device globals; no allocation) ----------------
__device__ float g_x[M_TOK*DD];
__device__ float g_qkv[M_TOK*3*DD];
__device__ float g_probs[M_TOK];
__device__ int   g_tidx[M_SEL];
__device__ float g_tp[M_SEL];
__device__ float g_gate[M_SEL*FFF];
__device__ float g_up[M_SEL*FFF];
__device__ float g_mlp[M_SEL*DD];
__device__ float g_cos[SS*32];
__device__ float g_sin[SS*32];

// bf16 split activation buffers
__device__ __nv_bfloat16 g_hh[M_TOK*DD],  g_hl[M_TOK*DD];     // rmsnorm out (qkv A)
__device__ __nv_bfloat16 g_atth[M_TOK*DD], g_attl[M_TOK*DD];  // attention out (wo A)
__device__ __nv_bfloat16 g_hsh[M_SEL*DD], g_hsl[M_SEL*DD];    // gathered norm (gate/up A)
__device__ __nv_bfloat16 g_gah[M_SEL*FFF], g_gal[M_SEL*FFF];  // silu*up (down A)
// bf16 split q/k/v  ([B,NH,S,HD], q pre-scaled)
__device__ __nv_bfloat16 g_qh[M_TOK*DD], g_ql[M_TOK*DD];
__device__ __nv_bfloat16 g_kh[M_TOK*DD], g_kl[M_TOK*DD];
__device__ __nv_bfloat16 g_vh[M_TOK*DD], g_vl[M_TOK*DD];
// bf16 split weights
__device__ __nv_bfloat16 g_wqkvh[NLL*3*DD*DD], g_wqkvl[NLL*3*DD*DD];
__device__ __nv_bfloat16 g_woh[NLL*DD*DD],     g_wol[NLL*DD*DD];
__device__ __nv_bfloat16 g_wgh[NLL*FFF*DD],    g_wgl[NLL*FFF*DD];
__device__ __nv_bfloat16 g_wuh[NLL*FFF*DD],    g_wul[NLL*FFF*DD];
__device__ __nv_bfloat16 g_wdh[NLL*DD*FFF],    g_wdl[NLL*DD*FFF];

__device__ __forceinline__ void split2(float x, __nv_bfloat16& h, __nv_bfloat16& l) {
    h = __float2bfloat16_rn(x);
    l = __float2bfloat16_rn(x - __bfloat162float(h));
}
__device__ __forceinline__ void split_pack(float x, float y, uint32_t& hp, uint32_t& lp) {
    __nv_bfloat162 h2, l2;
    split2(x, h2.x, l2.x);
    split2(y, h2.y, l2.y);
    hp = *reinterpret_cast<uint32_t*>(&h2);
    lp = *reinterpret_cast<uint32_t*>(&l2);
}

// ---------------- weight split ----------------
__global__ void split_kernel(const float* __restrict__ src, __nv_bfloat16* __restrict__ h,
                             __nv_bfloat16* __restrict__ l, int n) {
    int i = blockIdx.x*blockDim.x + threadIdx.x;
    if (i >= n) return;
    split2(src[i], h[i], l[i]);
}

// ---------------- rope tables ----------------
__global__ void rope_table_kernel() {
    int i = blockIdx.x*blockDim.x + threadIdx.x;
    if (i >= SS*32) return;
    int s = i / 32, d = i % 32;
    double freq = exp(-((double)(2*d)/64.0)*log(10000.0));
    double f = (double)s * freq;
    g_cos[i] = (float)cos(f);
    g_sin[i] = (float)sin(f);
}

// ---------------- embed ----------------
__global__ void embed_kernel(const int* __restrict__ ids, const int* __restrict__ iter,
                             const float* __restrict__ emb, const float* __restrict__ iter_emb) {
    int i = blockIdx.x*blockDim.x + threadIdx.x;
    if (i >= M_TOK*DD) return;
    int t = i / DD, d = i % DD;
    float v = emb[(size_t)ids[t]*DD + d];
    int it = iter[0];
    if (it < 8) v += iter_emb[(size_t)it*DD + d];
    g_x[i] = v;
}

// ---------------- rmsnorm variants ----------------
__global__ void rmsnorm_f32_kernel(const float* __restrict__ X, const float* __restrict__ w,
                                   float* __restrict__ Y) {
    int t = blockIdx.x;
    const float* xr = X + (size_t)t*DD;
    float ss = 0.f;
    for (int d = threadIdx.x; d < DD; d += 128) { float v = xr[d]; ss += v*v; }
    #pragma unroll
    for (int o = 16; o > 0; o >>= 1) ss += __shfl_xor_sync(0xffffffffu, ss, o);
    __shared__ float red[4];
    if ((threadIdx.x & 31) == 0) red[threadIdx.x >> 5] = ss;
    __syncthreads();
    float tot = red[0]+red[1]+red[2]+red[3];
    float sc = rsqrtf(tot*(1.f/DD) + EPSF);
    for (int d = threadIdx.x; d < DD; d += 128) Y[(size_t)t*DD + d] = w[d]*xr[d]*sc;
}

__global__ void rmsnorm_split_kernel(const float* __restrict__ X, const float* __restrict__ w,
                                     __nv_bfloat16* __restrict__ Yh, __nv_bfloat16* __restrict__ Yl) {
    int t = blockIdx.x;
    const float* xr = X + (size_t)t*DD;
    float ss = 0.f;
    for (int d = threadIdx.x; d < DD; d += 128) { float v = xr[d]; ss += v*v; }
    #pragma unroll
    for (int o = 16; o > 0; o >>= 1) ss += __shfl_xor_sync(0xffffffffu, ss, o);
    __shared__ float red[4];
    if ((threadIdx.x & 31) == 0) red[threadIdx.x >> 5] = ss;
    __syncthreads();
    float tot = red[0]+red[1]+red[2]+red[3];
    float sc = rsqrtf(tot*(1.f/DD) + EPSF);
    for (int d = threadIdx.x; d < DD; d += 128) {
        float y = w[d]*xr[d]*sc;
        split2(y, Yh[(size_t)t*DD + d], Yl[(size_t)t*DD + d]);
    }
}

// ================= tensor-core GEMM (pre-split bf16 operands) =================
// C[M,N] (+)= (Ah+Al)[M,K] * (Bh+Bl)[N,K]^T ;  C = Ah*Bh + Ah*Bl + Al*Bh (fp32 accum)

__device__ __forceinline__ void ldsm_x4(uint32_t* r, const __nv_bfloat16* p) {
    uint32_t addr = (uint32_t)__cvta_generic_to_shared(p);
    asm volatile("ldmatrix.sync.aligned.m8n8.x4.shared.b16 {%0,%1,%2,%3}, [%4];"
                 : "=r"(r[0]), "=r"(r[1]), "=r"(r[2]), "=r"(r[3]) : "r"(addr));
}
__device__ __forceinline__ void ldsm_x4_t(uint32_t* r, const __nv_bfloat16* p) {
    uint32_t addr = (uint32_t)__cvta_generic_to_shared(p);
    asm volatile("ldmatrix.sync.aligned.m8n8.x4.trans.shared.b16 {%0,%1,%2,%3}, [%4];"
                 : "=r"(r[0]), "=r"(r[1]), "=r"(r[2]), "=r"(r[3]) : "r"(addr));
}
__device__ __forceinline__ void mma_bf16(float* c, const uint32_t* a, uint32_t b0, uint32_t b1) {
    asm volatile(
        "mma.sync.aligned.m16n8k16.row.col.f32.bf16.bf16.f32 "
        "{%0,%1,%2,%3}, {%4,%5,%6,%7}, {%8,%9}, {%0,%1,%2,%3};\n"
        : "+f"(c[0]), "+f"(c[1]), "+f"(c[2]), "+f"(c[3])
        : "r"(a[0]), "r"(a[1]), "r"(a[2]), "r"(a[3]), "r"(b0), "r"(b1));
}

#define LDSTR 24

template<bool ACCUM>
__global__ void __launch_bounds__(256) gemm_bf(const __nv_bfloat16* __restrict__ Ah, const __nv_bfloat16* __restrict__ Al,
                                               const __nv_bfloat16* __restrict__ Bh, const __nv_bfloat16* __restrict__ Bl,
                                               float* __restrict__ C, int M, int N, int K) {
    __shared__ __nv_bfloat16 sm[4*128*LDSTR];
    __nv_bfloat16* sAh = sm;
    __nv_bfloat16* sAl = sm + 128*LDSTR;
    __nv_bfloat16* sBh = sm + 2*128*LDSTR;
    __nv_bfloat16* sBl = sm + 3*128*LDSTR;

    int tid = threadIdx.x;
    int lane = tid & 31, wid = tid >> 5;
    int wm = (wid & 1) * 64;
    int wn = (wid >> 1) * 32;
    int row0 = blockIdx.y * 128, col0 = blockIdx.x * 128;

    int srow = tid >> 1;
    int scol = (tid & 1) * 8;
    size_t aoffg = (size_t)(row0 + srow) * K + scol;
    size_t boffg = (size_t)(col0 + srow) * K + scol;
    bool aval = (row0 + srow) < M;
    bool bval = (col0 + srow) < N;

    float acc[4][4][4];
    #pragma unroll
    for (int i = 0; i < 4; i++)
        #pragma unroll
        for (int j = 0; j < 4; j++)
            #pragma unroll
            for (int r = 0; r < 4; r++) acc[i][j][r] = 0.f;

    int a_r = lane & 15;
    int a_c = ((lane >> 4) & 1) * 8;
    int b_r = (lane & 7) + ((lane >> 4) & 1) * 8;
    int b_c = ((lane >> 3) & 1) * 8;
    int aoff[4], boff[2];
    #pragma unroll
    for (int mt = 0; mt < 4; mt++) aoff[mt] = (wm + mt*16 + a_r)*LDSTR + a_c;
    #pragma unroll
    for (int pr = 0; pr < 2; pr++) boff[pr] = (wn + pr*16 + b_r)*LDSTR + b_c;

    const uint4 uz = make_uint4(0,0,0,0);
    uint4 rAh, rAl, rBh, rBl;
    rAh = aval ? *(const uint4*)(Ah + aoffg) : uz;
    rAl = aval ? *(const uint4*)(Al + aoffg) : uz;
    rBh = bval ? *(const uint4*)(Bh + boffg) : uz;
    rBl = bval ? *(const uint4*)(Bl + boffg) : uz;

    int nk = K >> 4;
    for (int ks = 0; ks < nk; ks++) {
        __syncthreads();
        *(uint4*)&sAh[srow*LDSTR + scol] = rAh;
        *(uint4*)&sAl[srow*LDSTR + scol] = rAl;
        *(uint4*)&sBh[srow*LDSTR + scol] = rBh;
        *(uint4*)&sBl[srow*LDSTR + scol] = rBl;
        __syncthreads();
        if (ks + 1 < nk) {
            int k0 = (ks + 1) << 4;
            rAh = aval ? *(const uint4*)(Ah + aoffg + k0) : uz;
            rAl = aval ? *(const uint4*)(Al + aoffg + k0) : uz;
            rBh = bval ? *(const uint4*)(Bh + boffg + k0) : uz;
            rBl = bval ? *(const uint4*)(Bl + boffg + k0) : uz;
        }

        uint32_t fAh[4][4], fAl[4][4], fBh[2][4], fBl[2][4];
        #pragma unroll
        for (int mt = 0; mt < 4; mt++) { ldsm_x4(fAh[mt], sAh + aoff[mt]); ldsm_x4(fAl[mt], sAl + aoff[mt]); }
        #pragma unroll
        for (int pr = 0; pr < 2; pr++) { ldsm_x4(fBh[pr], sBh + boff[pr]); ldsm_x4(fBl[pr], sBl + boff[pr]); }

        #pragma unroll
        for (int mt = 0; mt < 4; mt++)
            #pragma unroll
            for (int nt = 0; nt < 4; nt++)
                mma_bf16(acc[mt][nt], fAh[mt], fBh[nt>>1][(nt&1)*2], fBh[nt>>1][(nt&1)*2+1]);
        #pragma unroll
        for (int mt = 0; mt < 4; mt++)
            #pragma unroll
            for (int nt = 0; nt < 4; nt++)
                mma_bf16(acc[mt][nt], fAh[mt], fBl[nt>>1][(nt&1)*2], fBl[nt>>1][(nt&1)*2+1]);
        #pragma unroll
        for (int mt = 0; mt < 4; mt++)
            #pragma unroll
            for (int nt = 0; nt < 4; nt++)
                mma_bf16(acc[mt][nt], fAl[mt], fBh[nt>>1][(nt&1)*2], fBh[nt>>1][(nt&1)*2+1]);
    }

    int erow = lane >> 2;
    int ecol = (lane & 3) * 2;
    #pragma unroll
    for (int mt = 0; mt < 4; mt++) {
        #pragma unroll
        for (int nt = 0; nt < 4; nt++) {
            int r = row0 + wm + mt*16 + erow;
            int c = col0 + wn + nt*8 + ecol;
            if (c < N) {
                if (r < M) {
                    float2* p = (float2*)&C[(size_t)r*N + c];
                    if (ACCUM) { float2 o = *p; o.x += acc[mt][nt][0]; o.y += acc[mt][nt][1]; *p = o; }
                    else { float2 o; o.x = acc[mt][nt][0]; o.y = acc[mt][nt][1]; *p = o; }
                }
                if (r + 8 < M) {
                    float2* p = (float2*)&C[(size_t)(r+8)*N + c];
                    if (ACCUM) { float2 o = *p; o.x += acc[mt][nt][2]; o.y += acc[mt][nt][3]; *p = o; }
                    else { float2 o; o.x = acc[mt][nt][2]; o.y = acc[mt][nt][3]; *p = o; }
                }
            }
        }
    }
}

// ---------------- rope + split to bf16 h/l [B,NH,S,HD] ----------------
__global__ void rope_kernel() {
    int i = blockIdx.x*blockDim.x + threadIdx.x;
    if (i >= M_TOK*NHH*32) return;
    int t = i / (NHH*32);
    int r = i % (NHH*32);
    int h = r / 32, d = r % 32;
    int b = t / SS, s = t % SS;
    const float* base = g_qkv + (size_t)t*(3*DD) + h*HDD;
    float c = g_cos[s*32+d], sn = g_sin[s*32+d];
    float q1 = base[d],        q2 = base[d+32];
    float k1 = base[DD+d],     k2 = base[DD+d+32];
    size_t o = ((size_t)(b*NHH+h)*SS + s)*HDD;
    float qa = (q1*c - q2*sn)*0.125f;
    float qb2 = (q2*c + q1*sn)*0.125f;
    float ka = k1*c - k2*sn;
    float kb = k2*c + k1*sn;
    split2(qa,  g_qh[o+d],    g_ql[o+d]);
    split2(qb2, g_qh[o+d+32], g_ql[o+d+32]);
    split2(ka,  g_kh[o+d],    g_kl[o+d]);
    split2(kb,  g_kh[o+d+32], g_kl[o+d+32]);
    split2(base[2*DD+d],    g_vh[o+d],    g_vl[o+d]);
    split2(base[2*DD+d+32], g_vh[o+d+32], g_vl[o+d+32]);
}

// ---------------- flash attention v3: tensor-core, 64q x 64k tiles, 4 warps ----------
#define ASTR 72
__global__ void __launch_bounds__(128) flash3_kernel() {
    extern __shared__ __nv_bfloat16 sb[];
    __nv_bfloat16* Qh = sb;
    __nv_bfloat16* Ql = sb + 64*ASTR;
    __nv_bfloat16* Kh = sb + 2*64*ASTR;
    __nv_bfloat16* Kl = sb + 3*64*ASTR;
    __nv_bfloat16* Vh = sb + 4*64*ASTR;
    __nv_bfloat16* Vl = sb + 5*64*ASTR;

    int b = blockIdx.z, hh = blockIdx.y;
    int qb = (int)(gridDim.x - 1u - blockIdx.x);   // heavy first
    int tid = threadIdx.x, lane = tid & 31, w = tid >> 5;
    size_t headoff = ((size_t)(b*NHH+hh)*SS)*HDD;
    const __nv_bfloat16 *Qhp = g_qh + headoff, *Qlp = g_ql + headoff;
    const __nv_bfloat16 *Khp = g_kh + headoff, *Klp = g_kl + headoff;
    const __nv_bfloat16 *Vhp = g_vh + headoff, *Vlp = g_vl + headoff;

    // load Q tile (64 x 64)
    {
        int r = tid >> 3, c = (tid & 7) * 8;
        #pragma unroll
        for (int i = 0; i < 4; i++) {
            int rr = r + i*16;
            *(uint4*)&Qh[rr*ASTR + c] = *(const uint4*)&Qhp[(size_t)(qb*64 + rr)*64 + c];
            *(uint4*)&Ql[rr*ASTR + c] = *(const uint4*)&Qlp[(size_t)(qb*64 + rr)*64 + c];
        }
    }

    int m0 = w * 16;
    int a_r = lane & 15;
    int a_c = ((lane >> 4) & 1) * 8;
    int b_r = (lane & 7) + ((lane >> 4) & 1) * 8;
    int b_c = ((lane >> 3) & 1) * 8;
    int v_r = ((lane >> 3) & 1) * 8 + (lane & 7);   // trans-ldsm: k row
    int v_c = ((lane >> 4) & 1) * 8;                // trans-ldsm: n col group

    float O[8][4];
    float mrow[2] = {-1e30f, -1e30f};
    float lrow[2] = {0.f, 0.f};
    #pragma unroll
    for (int nt = 0; nt < 8; nt++)
        #pragma unroll
        for (int r = 0; r < 4; r++) O[nt][r] = 0.f;

    for (int kt = 0; kt <= qb; kt++) {
        __syncthreads();
        {
            int r = tid >> 3, c = (tid & 7) * 8;
            #pragma unroll
            for (int i = 0; i < 4; i++) {
                int rr = r + i*16;
                *(uint4*)&Kh[rr*ASTR + c] = *(const uint4*)&Khp[(size_t)(kt*64 + rr)*64 + c];
                *(uint4*)&Kl[rr*ASTR + c] = *(const uint4*)&Klp[(size_t)(kt*64 + rr)*64 + c];
                *(uint4*)&Vh[rr*ASTR + c] = *(const uint4*)&Vhp[(size_t)(kt*64 + rr)*64 + c];
                *(uint4*)&Vl[rr*ASTR + c] = *(const uint4*)&Vlp[(size_t)(kt*64 + rr)*64 + c];
            }
        }
        __syncthreads();

        // ---- S = Q K^T (compensated) ----
        float s[8][4];
        #pragma unroll
        for (int nt = 0; nt < 8; nt++)
            #pragma unroll
            for (int r = 0; r < 4; r++) s[nt][r] = 0.f;
        #pragma unroll
        for (int kk = 0; kk < 4; kk++) {
            uint32_t QAh[4], QAl[4];
            ldsm_x4(QAh, Qh + (m0 + a_r)*ASTR + kk*16 + a_c);
            ldsm_x4(QAl, Ql + (m0 + a_r)*ASTR + kk*16 + a_c);
            #pragma unroll
            for (int bn = 0; bn < 4; bn++) {
                uint32_t KBh[4], KBl[4];
                ldsm_x4(KBh, Kh + (bn*16 + b_r)*ASTR + kk*16 + b_c);
                ldsm_x4(KBl, Kl + (bn*16 + b_r)*ASTR + kk*16 + b_c);
                mma_bf16(s[2*bn],   QAh, KBh[0], KBh[1]);
                mma_bf16(s[2*bn+1], QAh, KBh[2], KBh[3]);
                mma_bf16(s[2*bn],   QAh, KBl[0], KBl[1]);
                mma_bf16(s[2*bn+1], QAh, KBl[2], KBl[3]);
                mma_bf16(s[2*bn],   QAl, KBh[0], KBh[1]);
                mma_bf16(s[2*bn+1], QAl, KBh[2], KBh[3]);
            }
        }
        // ---- causal mask on diagonal tile ----
        if (kt == qb) {
            int r0l = m0 + (lane >> 2);
            int c0l = 2*(lane & 3);
            #pragma unroll
            for (int nt = 0; nt < 8; nt++) {
                int c = nt*8 + c0l;
                if (c     > r0l)     s[nt][0] = -1e30f;
                if (c + 1 > r0l)     s[nt][1] = -1e30f;
                if (c     > r0l + 8) s[nt][2] = -1e30f;
                if (c + 1 > r0l + 8) s[nt][3] = -1e30f;
            }
        }
        // ---- online softmax ----
        float rm0 = -1e30f, rm1 = -1e30f;
        #pragma unroll
        for (int nt = 0; nt < 8; nt++) {
            rm0 = fmaxf(rm0, fmaxf(s[nt][0], s[nt][1]));
            rm1 = fmaxf(rm1, fmaxf(s[nt][2], s[nt][3]));
        }
        rm0 = fmaxf(rm0, __shfl_xor_sync(0xffffffffu, rm0, 1));
        rm0 = fmaxf(rm0, __shfl_xor_sync(0xffffffffu, rm0, 2));
        rm1 = fmaxf(rm1, __shfl_xor_sync(0xffffffffu, rm1, 1));
        rm1 = fmaxf(rm1, __shfl_xor_sync(0xffffffffu, rm1, 2));
        float mn0 = fmaxf(mrow[0], rm0), mn1 = fmaxf(mrow[1], rm1);
        float cc0 = __expf(mrow[0] - mn0), cc1 = __expf(mrow[1] - mn1);
        mrow[0] = mn0; mrow[1] = mn1;
        float rs0 = 0.f, rs1 = 0.f;
        #pragma unroll
        for (int nt = 0; nt < 8; nt++) {
            s[nt][0] = __expf(s[nt][0] - mn0); rs0 += s[nt][0];
            s[nt][1] = __expf(s[nt][1] - mn0); rs0 += s[nt][1];
            s[nt][2] = __expf(s[nt][2] - mn1); rs1 += s[nt][2];
            s[nt][3] = __expf(s[nt][3] - mn1); rs1 += s[nt][3];
        }
        rs0 += __shfl_xor_sync(0xffffffffu, rs0, 1);
        rs0 += __shfl_xor_sync(0xffffffffu, rs0, 2);
        rs1 += __shfl_xor_sync(0xffffffffu, rs1, 1);
        rs1 += __shfl_xor_sync(0xffffffffu, rs1, 2);
        lrow[0] = lrow[0]*cc0 + rs0;
        lrow[1] = lrow[1]*cc1 + rs1;
        #pragma unroll
        for (int nt = 0; nt < 8; nt++) {
            O[nt][0] *= cc0; O[nt][1] *= cc0;
            O[nt][2] *= cc1; O[nt][3] *= cc1;
        }
        // ---- O += P V (P fragments direct from s; compensated) ----
        #pragma unroll
        for (int kk = 0; kk < 4; kk++) {
            uint32_t Ph[4], Pl[4];
            split_pack(s[2*kk][0],   s[2*kk][1],   Ph[0], Pl[0]);
            split_pack(s[2*kk][2],   s[2*kk][3],   Ph[1], Pl[1]);
            split_pack(s[2*kk+1][0], s[2*kk+1][1], Ph[2], Pl[2]);
            split_pack(s[2*kk+1][2], s[2*kk+1][3], Ph[3], Pl[3]);
            #pragma unroll
            for (int bn = 0; bn < 4; bn++) {
                uint32_t VBh[4], VBl[4];
                ldsm_x4_t(VBh, Vh + (kk*16 + v_r)*ASTR + bn*16 + v_c);
                ldsm_x4_t(VBl, Vl + (kk*16 + v_r)*ASTR + bn*16 + v_c);
                mma_bf16(O[2*bn],   Ph, VBh[0], VBh[1]);
                mma_bf16(O[2*bn+1], Ph, VBh[2], VBh[3]);
                mma_bf16(O[2*bn],   Ph, VBl[0], VBl[1]);
                mma_bf16(O[2*bn+1], Ph, VBl[2], VBl[3]);
                mma_bf16(O[2*bn],   Pl, VBh[0], VBh[1]);
                mma_bf16(O[2*bn+1], Pl, VBh[2], VBh[3]);
            }
        }
    }
    // epilogue: write att h/l
    float inv0 = 1.f/lrow[0], inv1 = 1.f/lrow[1];
    int row0 = qb*64 + m0 + (lane >> 2);
    int row1 = row0 + 8;
    #pragma unroll
    for (int nt = 0; nt < 8; nt++) {
        int col = hh*64 + nt*8 + 2*(lane & 3);
        size_t o0 = ((size_t)b*SS + row0)*DD + col;
        size_t o1 = ((size_t)b*SS + row1)*DD + col;
        uint32_t hp, lp;
        split_pack(O[nt][0]*inv0, O[nt][1]*inv0, hp, lp);
        *(uint32_t*)&g_atth[o0] = hp;
        *(uint32_t*)&g_attl[o0] = lp;
        split_pack(O[nt][2]*inv1, O[nt][3]*inv1, hp, lp);
        *(uint32_t*)&g_atth[o1] = hp;
        *(uint32_t*)&g_attl[o1] = lp;
    }
}

// ---------------- router ----------------
__global__ void router_kernel(const float* __restrict__ rw) {
    int t = blockIdx.x*4 + (threadIdx.x >> 5);
    int lane = threadIdx.x & 31;
    const float* xr = g_x + (size_t)t*DD;
    float s = 0.f;
    for (int d = lane; d < DD; d += 32) s += xr[d]*rw[d];
    #pragma unroll
    for (int o = 16; o > 0; o >>= 1) s += __shfl_xor_sync(0xffffffffu, s, o);
    if (lane == 0) g_probs[t] = 1.f/(1.f + __expf(-s));
}

// ---------------- per-batch top-k via bitonic sort ----------------
__global__ void topk_kernel() {
    __shared__ float sv[2048];
    __shared__ int   si[2048];
    int bb = blockIdx.x;
    for (int i = threadIdx.x; i < 2048; i += 1024) { sv[i] = g_probs[(size_t)bb*SS + i]; si[i] = i; }
    __syncthreads();
    for (int k = 2; k <= 2048; k <<= 1) {
        for (int j = k >> 1; j > 0; j >>= 1) {
            for (int t = threadIdx.x; t < 2048; t += 1024) {
                int ixj = t ^ j;
                if (ixj > t) {
                    bool desc = ((t & k) == 0);
                    float a = sv[t], b2 = sv[ixj];
                    bool sw = desc ? (a < b2) : (a > b2);
                    if (sw) {
                        sv[t] = b2; sv[ixj] = a;
                        int tmp = si[t]; si[t] = si[ixj]; si[ixj] = tmp;
                    }
                }
            }
            __syncthreads();
        }
    }
    for (int i = threadIdx.x; i < KSEL; i += 1024) {
        g_tidx[(size_t)bb*KSEL + i] = si[i];
        g_tp[(size_t)bb*KSEL + i]   = sv[i];
    }
}

// ---------------- gather + rmsnorm (split out) ----------------
__global__ void gather_rmsnorm_kernel(const float* __restrict__ w) {
    int i = blockIdx.x;
    int b = i / KSEL;
    int tok = g_tidx[i];
    const float* xr = g_x + ((size_t)b*SS + tok)*DD;
    float ss = 0.f;
    for (int d = threadIdx.x; d < DD; d += 128) { float v = xr[d]; ss += v*v; }
    #pragma unroll
    for (int o = 16; o > 0; o >>= 1) ss += __shfl_xor_sync(0xffffffffu, ss, o);
    __shared__ float red[4];
    if ((threadIdx.x & 31) == 0) red[threadIdx.x >> 5] = ss;
    __syncthreads();
    float tot = red[0]+red[1]+red[2]+red[3];
    float sc = rsqrtf(tot*(1.f/DD) + EPSF);
    for (int d = threadIdx.x; d < DD; d += 128) {
        float y = w[d]*xr[d]*sc;
        split2(y, g_hsh[(size_t)i*DD + d], g_hsl[(size_t)i*DD + d]);
    }
}

// ---------------- silu(gate)*up -> split ----------------
__global__ void silu_kernel() {
    size_t i = (size_t)blockIdx.x*blockDim.x + threadIdx.x;
    if (i >= (size_t)M_SEL*FFF) return;
    float g = g_gate[i];
    float u = g_up[i];
    float sig = 1.f/(1.f + __expf(-g));
    split2(g*sig*u, g_gah[i], g_gal[i]);
}

// ---------------- scaled scatter-add ----------------
__global__ void scatter_kernel2() {
    int i = blockIdx.x;
    int b = i / KSEL;
    int tok = g_tidx[i];
    float p = g_tp[i];
    float* xr = g_x + ((size_t)b*SS + tok)*DD;
    const float* mr = g_mlp + (size_t)i*DD;
    for (int d = threadIdx.x; d < DD; d += 128) xr[d] += mr[d]*p;
}

// ---------------- host orchestration ----------------
extern "C" void kernel_launch(void* const* d_in, const int* in_sizes, int n_in,
                              void* d_out, int out_size) {
    const int*   ids       = (const int*)d_in[0];
    const int*   iter      = (const int*)d_in[1];
    const float* emb       = (const float*)d_in[2];
    const float* iter_emb  = (const float*)d_in[3];
    const float* attn_norm = (const float*)d_in[4];
    const float* Wqkv      = (const float*)d_in[5];
    const float* wo        = (const float*)d_in[6];
    const float* router    = (const float*)d_in[7];
    const float* mlp_norm  = (const float*)d_in[8];
    const float* gate_w    = (const float*)d_in[9];
    const float* up_w      = (const float*)d_in[10];
    const float* down_w    = (const float*)d_in[11];
    const float* fnorm     = (const float*)d_in[12];

    float *px, *pqkv, *pgate, *pup, *pmlp;
    __nv_bfloat16 *phh, *phl, *patth, *pattl, *phsh, *phsl, *pgah, *pgal;
    __nv_bfloat16 *pwqkvh, *pwqkvl, *pwoh, *pwol, *pwgh, *pwgl, *pwuh, *pwul, *pwdh, *pwdl;
    cudaGetSymbolAddress((void**)&px,    g_x);
    cudaGetSymbolAddress((void**)&pqkv,  g_qkv);
    cudaGetSymbolAddress((void**)&pgate, g_gate);
    cudaGetSymbolAddress((void**)&pup,   g_up);
    cudaGetSymbolAddress((void**)&pmlp,  g_mlp);
    cudaGetSymbolAddress((void**)&phh,   g_hh);
    cudaGetSymbolAddress((void**)&phl,   g_hl);
    cudaGetSymbolAddress((void**)&patth, g_atth);
    cudaGetSymbolAddress((void**)&pattl, g_attl);
    cudaGetSymbolAddress((void**)&phsh,  g_hsh);
    cudaGetSymbolAddress((void**)&phsl,  g_hsl);
    cudaGetSymbolAddress((void**)&pgah,  g_gah);
    cudaGetSymbolAddress((void**)&pgal,  g_gal);
    cudaGetSymbolAddress((void**)&pwqkvh, g_wqkvh);
    cudaGetSymbolAddress((void**)&pwqkvl, g_wqkvl);
    cudaGetSymbolAddress((void**)&pwoh,  g_woh);
    cudaGetSymbolAddress((void**)&pwol,  g_wol);
    cudaGetSymbolAddress((void**)&pwgh,  g_wgh);
    cudaGetSymbolAddress((void**)&pwgl,  g_wgl);
    cudaGetSymbolAddress((void**)&pwuh,  g_wuh);
    cudaGetSymbolAddress((void**)&pwul,  g_wul);
    cudaGetSymbolAddress((void**)&pwdh,  g_wdh);
    cudaGetSymbolAddress((void**)&pwdl,  g_wdl);

    cudaFuncSetAttribute(flash3_kernel, cudaFuncAttributeMaxDynamicSharedMemorySize, 6*64*ASTR*2);

    rope_table_kernel<<<(SS*32 + 255)/256, 256>>>();
    embed_kernel<<<(M_TOK*DD + 255)/256, 256>>>(ids, iter, emb, iter_emb);
    // weight splits (once per launch)
    split_kernel<<<(NLL*3*DD*DD + 255)/256, 256>>>(Wqkv,   pwqkvh, pwqkvl, NLL*3*DD*DD);
    split_kernel<<<(NLL*DD*DD + 255)/256, 256>>>(wo,       pwoh,   pwol,   NLL*DD*DD);
    split_kernel<<<(NLL*FFF*DD + 255)/256, 256>>>(gate_w,  pwgh,   pwgl,   NLL*FFF*DD);
    split_kernel<<<(NLL*FFF*DD + 255)/256, 256>>>(up_w,    pwuh,   pwul,   NLL*FFF*DD);
    split_kernel<<<(NLL*DD*FFF + 255)/256, 256>>>(down_w,  pwdh,   pwdl,   NLL*DD*FFF);

    for (int l = 0; l < NLL; l++) {
        rmsnorm_split_kernel<<<M_TOK, 128>>>(px, attn_norm + (size_t)l*DD, phh, phl);
        gemm_bf<false><<<dim3((3*DD+127)/128, M_TOK/128), 256>>>(phh, phl,
            pwqkvh + (size_t)l*3*DD*DD, pwqkvl + (size_t)l*3*DD*DD, pqkv, M_TOK, 3*DD, DD);
        rope_kernel<<<(M_TOK*NHH*32 + 255)/256, 256>>>();
        flash3_kernel<<<dim3(SS/64, NHH, BB), 128, 6*64*ASTR*2>>>();
        gemm_bf<true><<<dim3((DD+127)/128, M_TOK/128), 256>>>(patth, pattl,
            pwoh + (size_t)l*DD*DD, pwol + (size_t)l*DD*DD, px, M_TOK, DD, DD);
        router_kernel<<<M_TOK/4, 128>>>(router + (size_t)l*DD);
        topk_kernel<<<BB, 1024>>>();
        gather_rmsnorm_kernel<<<M_SEL, 128>>>(mlp_norm + (size_t)l*DD);
        gemm_bf<false><<<dim3((FFF+127)/128, (M_SEL+127)/128), 256>>>(phsh, phsl,
            pwgh + (size_t)l*FFF*DD, pwgl + (size_t)l*FFF*DD, pgate, M_SEL, FFF, DD);
        gemm_bf<false><<<dim3((FFF+127)/128, (M_SEL+127)/128), 256>>>(phsh, phsl,
            pwuh + (size_t)l*FFF*DD, pwul + (size_t)l*FFF*DD, pup, M_SEL, FFF, DD);
        silu_kernel<<<(int)(((size_t)M_SEL*FFF + 255)/256), 256>>>();
        gemm_bf<false><<<dim3((DD+127)/128, (M_SEL+127)/128), 256>>>(pgah, pgal,
            pwdh + (size_t)l*DD*FFF, pwdl + (size_t)l*DD*FFF, pmlp, M_SEL, DD, FFF);
        scatter_kernel2<<<M_SEL, 128>>>();
    }
    rmsnorm_f32_kernel<<<M_TOK, 128>>>(px, fnorm, (float*)d_out);
}

// round 5
// speedup vs baseline: 3.0152x; 1.0838x over previous
#include <cuda_runtime.h>
#include <cuda_bf16.h>
#include <math.h>
#include <stdint.h>

#define BB 8
#define SS 2048
#define DD 320
#define NHH 5
#define HDD 64
#define FFF 864
#define NLL 6
#define KSEL 1638
#define M_TOK (BB*SS)      // 16384
#define M_SEL (BB*KSEL)    // 13104
#define EPSF 1e-6f

// ---------------- scratch (static device globals; no allocation) ----------------
__device__ float g_x[M_TOK*DD];
__device__ float g_qkv[M_TOK*3*DD];
__device__ float g_probs[M_TOK];
__device__ int   g_tidx[M_SEL];
__device__ float g_tp[M_SEL];
__device__ float g_gu[(size_t)M_SEL*2*FFF];   // merged gate|up fp32 out
__device__ float g_cos[SS*32];
__device__ float g_sin[SS*32];

// bf16 split activation buffers
__device__ __nv_bfloat16 g_hh[M_TOK*DD],  g_hl[M_TOK*DD];
__device__ __nv_bfloat16 g_atth[M_TOK*DD], g_attl[M_TOK*DD];
__device__ __nv_bfloat16 g_hsh[M_SEL*DD], g_hsl[M_SEL*DD];
__device__ __nv_bfloat16 g_gah[M_SEL*FFF], g_gal[M_SEL*FFF];
// bf16 split q/k/v  ([B,NH,S,HD], q pre-scaled)
__device__ __nv_bfloat16 g_qh[M_TOK*DD], g_ql[M_TOK*DD];
__device__ __nv_bfloat16 g_kh[M_TOK*DD], g_kl[M_TOK*DD];
__device__ __nv_bfloat16 g_vh[M_TOK*DD], g_vl[M_TOK*DD];
// bf16 split weights
__device__ __nv_bfloat16 g_wqkvh[NLL*3*DD*DD], g_wqkvl[NLL*3*DD*DD];
__device__ __nv_bfloat16 g_woh[NLL*DD*DD],     g_wol[NLL*DD*DD];
__device__ __nv_bfloat16 g_wguh[NLL*2*FFF*DD], g_wgul[NLL*2*FFF*DD]; // gate rows 0..FFF, up rows FFF..2FFF
__device__ __nv_bfloat16 g_wdh[NLL*DD*FFF],    g_wdl[NLL*DD*FFF];

__device__ __forceinline__ void split2(float x, __nv_bfloat16& h, __nv_bfloat16& l) {
    h = __float2bfloat16_rn(x);
    l = __float2bfloat16_rn(x - __bfloat162float(h));
}
__device__ __forceinline__ void split_pack(float x, float y, uint32_t& hp, uint32_t& lp) {
    __nv_bfloat162 h2, l2;
    split2(x, h2.x, l2.x);
    split2(y, h2.y, l2.y);
    hp = *reinterpret_cast<uint32_t*>(&h2);
    lp = *reinterpret_cast<uint32_t*>(&l2);
}

// ---------------- weight splits ----------------
__global__ void split_kernel(const float* __restrict__ src, __nv_bfloat16* __restrict__ h,
                             __nv_bfloat16* __restrict__ l, int n) {
    int i = blockIdx.x*blockDim.x + threadIdx.x;
    if (i >= n) return;
    split2(src[i], h[i], l[i]);
}
// gate/up -> merged [l][2*FFF][DD], ofs 0 for gate, FFF*DD for up
__global__ void split_gu_kernel(const float* __restrict__ src, __nv_bfloat16* __restrict__ h,
                                __nv_bfloat16* __restrict__ l, int ofs) {
    int i = blockIdx.x*blockDim.x + threadIdx.x;
    if (i >= NLL*FFF*DD) return;
    int lay = i / (FFF*DD), rem = i % (FFF*DD);
    size_t dst = (size_t)lay*2*FFF*DD + ofs + rem;
    split2(src[i], h[dst], l[dst]);
}

// ---------------- rope tables ----------------
__global__ void rope_table_kernel() {
    int i = blockIdx.x*blockDim.x + threadIdx.x;
    if (i >= SS*32) return;
    int s = i / 32, d = i % 32;
    double freq = exp(-((double)(2*d)/64.0)*log(10000.0));
    double f = (double)s * freq;
    g_cos[i] = (float)cos(f);
    g_sin[i] = (float)sin(f);
}

// ---------------- embed ----------------
__global__ void embed_kernel(const int* __restrict__ ids, const int* __restrict__ iter,
                             const float* __restrict__ emb, const float* __restrict__ iter_emb) {
    int i = blockIdx.x*blockDim.x + threadIdx.x;
    if (i >= M_TOK*DD) return;
    int t = i / DD, d = i % DD;
    float v = emb[(size_t)ids[t]*DD + d];
    int it = iter[0];
    if (it < 8) v += iter_emb[(size_t)it*DD + d];
    g_x[i] = v;
}

// ---------------- rmsnorm variants ----------------
__global__ void rmsnorm_f32_kernel(const float* __restrict__ X, const float* __restrict__ w,
                                   float* __restrict__ Y) {
    int t = blockIdx.x;
    const float* xr = X + (size_t)t*DD;
    float ss = 0.f;
    for (int d = threadIdx.x; d < DD; d += 128) { float v = xr[d]; ss += v*v; }
    #pragma unroll
    for (int o = 16; o > 0; o >>= 1) ss += __shfl_xor_sync(0xffffffffu, ss, o);
    __shared__ float red[4];
    if ((threadIdx.x & 31) == 0) red[threadIdx.x >> 5] = ss;
    __syncthreads();
    float tot = red[0]+red[1]+red[2]+red[3];
    float sc = rsqrtf(tot*(1.f/DD) + EPSF);
    for (int d = threadIdx.x; d < DD; d += 128) Y[(size_t)t*DD + d] = w[d]*xr[d]*sc;
}

__global__ void rmsnorm_split_kernel(const float* __restrict__ X, const float* __restrict__ w,
                                     __nv_bfloat16* __restrict__ Yh, __nv_bfloat16* __restrict__ Yl) {
    int t = blockIdx.x;
    const float* xr = X + (size_t)t*DD;
    float ss = 0.f;
    for (int d = threadIdx.x; d < DD; d += 128) { float v = xr[d]; ss += v*v; }
    #pragma unroll
    for (int o = 16; o > 0; o >>= 1) ss += __shfl_xor_sync(0xffffffffu, ss, o);
    __shared__ float red[4];
    if ((threadIdx.x & 31) == 0) red[threadIdx.x >> 5] = ss;
    __syncthreads();
    float tot = red[0]+red[1]+red[2]+red[3];
    float sc = rsqrtf(tot*(1.f/DD) + EPSF);
    for (int d = threadIdx.x; d < DD; d += 128) {
        float y = w[d]*xr[d]*sc;
        split2(y, Yh[(size_t)t*DD + d], Yl[(size_t)t*DD + d]);
    }
}

// ================= tensor-core GEMM (pre-split bf16, double-buffered) =================
__device__ __forceinline__ void ldsm_x4(uint32_t* r, const __nv_bfloat16* p) {
    uint32_t addr = (uint32_t)__cvta_generic_to_shared(p);
    asm volatile("ldmatrix.sync.aligned.m8n8.x4.shared.b16 {%0,%1,%2,%3}, [%4];"
                 : "=r"(r[0]), "=r"(r[1]), "=r"(r[2]), "=r"(r[3]) : "r"(addr));
}
__device__ __forceinline__ void ldsm_x4_t(uint32_t* r, const __nv_bfloat16* p) {
    uint32_t addr = (uint32_t)__cvta_generic_to_shared(p);
    asm volatile("ldmatrix.sync.aligned.m8n8.x4.trans.shared.b16 {%0,%1,%2,%3}, [%4];"
                 : "=r"(r[0]), "=r"(r[1]), "=r"(r[2]), "=r"(r[3]) : "r"(addr));
}
__device__ __forceinline__ void mma_bf16(float* c, const uint32_t* a, uint32_t b0, uint32_t b1) {
    asm volatile(
        "mma.sync.aligned.m16n8k16.row.col.f32.bf16.bf16.f32 "
        "{%0,%1,%2,%3}, {%4,%5,%6,%7}, {%8,%9}, {%0,%1,%2,%3};\n"
        : "+f"(c[0]), "+f"(c[1]), "+f"(c[2]), "+f"(c[3])
        : "r"(a[0]), "r"(a[1]), "r"(a[2]), "r"(a[3]), "r"(b0), "r"(b1));
}

#define LDSTR 24
#define STAGE (4*128*LDSTR)   // one stage: 4 arrays of 128xLDSTR halves

// MODE: 0 = store C, 1 = accumulate into C, 2 = scatter-add into x (C = g_x base)
template<int MODE>
__global__ void __launch_bounds__(256) gemm_bf(const __nv_bfloat16* __restrict__ Ah, const __nv_bfloat16* __restrict__ Al,
                                               const __nv_bfloat16* __restrict__ Bh, const __nv_bfloat16* __restrict__ Bl,
                                               float* __restrict__ C, int M, int N, int K) {
    __shared__ __nv_bfloat16 sm[2*STAGE];

    int tid = threadIdx.x;
    int lane = tid & 31, wid = tid >> 5;
    int wm = (wid & 1) * 64;
    int wn = (wid >> 1) * 32;
    int row0 = blockIdx.y * 128, col0 = blockIdx.x * 128;

    int srow = tid >> 1;
    int scol = (tid & 1) * 8;
    size_t aoffg = (size_t)(row0 + srow) * K + scol;
    size_t boffg = (size_t)(col0 + srow) * K + scol;
    bool aval = (row0 + srow) < M;
    bool bval = (col0 + srow) < N;
    int sput = srow*LDSTR + scol;

    float acc[4][4][4];
    #pragma unroll
    for (int i = 0; i < 4; i++)
        #pragma unroll
        for (int j = 0; j < 4; j++)
            #pragma unroll
            for (int r = 0; r < 4; r++) acc[i][j][r] = 0.f;

    int a_r = lane & 15;
    int a_c = ((lane >> 4) & 1) * 8;
    int b_r = (lane & 7) + ((lane >> 4) & 1) * 8;
    int b_c = ((lane >> 3) & 1) * 8;
    int aoff[4], boff[2];
    #pragma unroll
    for (int mt = 0; mt < 4; mt++) aoff[mt] = (wm + mt*16 + a_r)*LDSTR + a_c;
    #pragma unroll
    for (int pr = 0; pr < 2; pr++) boff[pr] = (wn + pr*16 + b_r)*LDSTR + b_c;

    const uint4 uz = make_uint4(0,0,0,0);
    uint4 rAh, rAl, rBh, rBl;
    rAh = aval ? *(const uint4*)(Ah + aoffg) : uz;
    rAl = aval ? *(const uint4*)(Al + aoffg) : uz;
    rBh = bval ? *(const uint4*)(Bh + boffg) : uz;
    rBl = bval ? *(const uint4*)(Bl + boffg) : uz;

    // prologue store stage 0
    *(uint4*)&sm[0*STAGE + 0*128*LDSTR + sput] = rAh;
    *(uint4*)&sm[0*STAGE + 1*128*LDSTR + sput] = rAl;
    *(uint4*)&sm[0*STAGE + 2*128*LDSTR + sput] = rBh;
    *(uint4*)&sm[0*STAGE + 3*128*LDSTR + sput] = rBl;
    __syncthreads();

    int nk = K >> 4;
    for (int ks = 0; ks < nk; ks++) {
        int cur = ks & 1;
        if (ks + 1 < nk) {
            int k0 = (ks + 1) << 4;
            rAh = aval ? *(const uint4*)(Ah + aoffg + k0) : uz;
            rAl = aval ? *(const uint4*)(Al + aoffg + k0) : uz;
            rBh = bval ? *(const uint4*)(Bh + boffg + k0) : uz;
            rBl = bval ? *(const uint4*)(Bl + boffg + k0) : uz;
        }
        const __nv_bfloat16* cAh = sm + cur*STAGE;
        const __nv_bfloat16* cAl = cAh + 128*LDSTR;
        const __nv_bfloat16* cBh = cAh + 2*128*LDSTR;
        const __nv_bfloat16* cBl = cAh + 3*128*LDSTR;

        uint32_t fAh[4][4], fAl[4][4], fBh[2][4], fBl[2][4];
        #pragma unroll
        for (int mt = 0; mt < 4; mt++) { ldsm_x4(fAh[mt], cAh + aoff[mt]); ldsm_x4(fAl[mt], cAl + aoff[mt]); }
        #pragma unroll
        for (int pr = 0; pr < 2; pr++) { ldsm_x4(fBh[pr], cBh + boff[pr]); ldsm_x4(fBl[pr], cBl + boff[pr]); }

        #pragma unroll
        for (int mt = 0; mt < 4; mt++)
            #pragma unroll
            for (int nt = 0; nt < 4; nt++)
                mma_bf16(acc[mt][nt], fAh[mt], fBh[nt>>1][(nt&1)*2], fBh[nt>>1][(nt&1)*2+1]);
        #pragma unroll
        for (int mt = 0; mt < 4; mt++)
            #pragma unroll
            for (int nt = 0; nt < 4; nt++)
                mma_bf16(acc[mt][nt], fAh[mt], fBl[nt>>1][(nt&1)*2], fBl[nt>>1][(nt&1)*2+1]);
        #pragma unroll
        for (int mt = 0; mt < 4; mt++)
            #pragma unroll
            for (int nt = 0; nt < 4; nt++)
                mma_bf16(acc[mt][nt], fAl[mt], fBh[nt>>1][(nt&1)*2], fBh[nt>>1][(nt&1)*2+1]);

        if (ks + 1 < nk) {
            __nv_bfloat16* nx = sm + (cur^1)*STAGE;
            *(uint4*)&nx[0*128*LDSTR + sput] = rAh;
            *(uint4*)&nx[1*128*LDSTR + sput] = rAl;
            *(uint4*)&nx[2*128*LDSTR + sput] = rBh;
            *(uint4*)&nx[3*128*LDSTR + sput] = rBl;
        }
        __syncthreads();
    }

    int erow = lane >> 2;
    int ecol = (lane & 3) * 2;
    #pragma unroll
    for (int mt = 0; mt < 4; mt++) {
        #pragma unroll
        for (int nt = 0; nt < 4; nt++) {
            int r = row0 + wm + mt*16 + erow;
            int c = col0 + wn + nt*8 + ecol;
            if (c < N) {
                if (MODE == 2) {
                    if (r < M) {
                        int b = r / KSEL;
                        int tok = g_tidx[r];
                        float p = g_tp[r];
                        float2* ptr = (float2*)&C[((size_t)b*SS + tok)*DD + c];
                        float2 o = *ptr; o.x += acc[mt][nt][0]*p; o.y += acc[mt][nt][1]*p; *ptr = o;
                    }
                    if (r + 8 < M) {
                        int r8 = r + 8;
                        int b = r8 / KSEL;
                        int tok = g_tidx[r8];
                        float p = g_tp[r8];
                        float2* ptr = (float2*)&C[((size_t)b*SS + tok)*DD + c];
                        float2 o = *ptr; o.x += acc[mt][nt][2]*p; o.y += acc[mt][nt][3]*p; *ptr = o;
                    }
                } else {
                    if (r < M) {
                        float2* p = (float2*)&C[(size_t)r*N + c];
                        if (MODE == 1) { float2 o = *p; o.x += acc[mt][nt][0]; o.y += acc[mt][nt][1]; *p = o; }
                        else { float2 o; o.x = acc[mt][nt][0]; o.y = acc[mt][nt][1]; *p = o; }
                    }
                    if (r + 8 < M) {
                        float2* p = (float2*)&C[(size_t)(r+8)*N + c];
                        if (MODE == 1) { float2 o = *p; o.x += acc[mt][nt][2]; o.y += acc[mt][nt][3]; *p = o; }
                        else { float2 o; o.x = acc[mt][nt][2]; o.y = acc[mt][nt][3]; *p = o; }
                    }
                }
            }
        }
    }
}

// ---------------- rope + split to bf16 h/l [B,NH,S,HD] ----------------
__global__ void rope_kernel() {
    int i = blockIdx.x*blockDim.x + threadIdx.x;
    if (i >= M_TOK*NHH*32) return;
    int t = i / (NHH*32);
    int r = i % (NHH*32);
    int h = r / 32, d = r % 32;
    int b = t / SS, s = t % SS;
    const float* base = g_qkv + (size_t)t*(3*DD) + h*HDD;
    float c = g_cos[s*32+d], sn = g_sin[s*32+d];
    float q1 = base[d],        q2 = base[d+32];
    float k1 = base[DD+d],     k2 = base[DD+d+32];
    size_t o = ((size_t)(b*NHH+h)*SS + s)*HDD;
    float qa = (q1*c - q2*sn)*0.125f;
    float qb2 = (q2*c + q1*sn)*0.125f;
    float ka = k1*c - k2*sn;
    float kb = k2*c + k1*sn;
    split2(qa,  g_qh[o+d],    g_ql[o+d]);
    split2(qb2, g_qh[o+d+32], g_ql[o+d+32]);
    split2(ka,  g_kh[o+d],    g_kl[o+d]);
    split2(kb,  g_kh[o+d+32], g_kl[o+d+32]);
    split2(base[2*DD+d],    g_vh[o+d],    g_vl[o+d]);
    split2(base[2*DD+d+32], g_vh[o+d+32], g_vl[o+d+32]);
}

// ---------------- flash attention v4: cp.async double-buffered K/V ----------
#define ASTR 72
__device__ __forceinline__ void cpa16(uint32_t saddr, const void* g) {
    asm volatile("cp.async.cg.shared.global [%0], [%1], 16;" :: "r"(saddr), "l"(g));
}

__global__ void __launch_bounds__(128) flash4_kernel() {
    extern __shared__ __nv_bfloat16 sb[];
    __nv_bfloat16* Qh = sb;
    __nv_bfloat16* Ql = sb + 64*ASTR;
    // stage st arrays at sb + (2 + 4*st + arr)*64*ASTR   arr: 0=Kh 1=Kl 2=Vh 3=Vl
    uint32_t smem_u32 = (uint32_t)__cvta_generic_to_shared(sb);

    int b = blockIdx.z, hh = blockIdx.y;
    int qb = (int)(gridDim.x - 1u - blockIdx.x);
    int tid = threadIdx.x, lane = tid & 31, w = tid >> 5;
    size_t headoff = ((size_t)(b*NHH+hh)*SS)*HDD;
    const __nv_bfloat16 *Qhp = g_qh + headoff, *Qlp = g_ql + headoff;
    const __nv_bfloat16* srcs[4] = {g_kh + headoff, g_kl + headoff, g_vh + headoff, g_vl + headoff};

    // load Q tile (64 x 64)
    {
        int r = tid >> 3, c = (tid & 7) * 8;
        #pragma unroll
        for (int i = 0; i < 4; i++) {
            int rr = r + i*16;
            *(uint4*)&Qh[rr*ASTR + c] = *(const uint4*)&Qhp[(size_t)(qb*64 + rr)*64 + c];
            *(uint4*)&Ql[rr*ASTR + c] = *(const uint4*)&Qlp[(size_t)(qb*64 + rr)*64 + c];
        }
    }
    // issue K/V tile 0 into stage 0
    {
        #pragma unroll
        for (int i = 0; i < 16; i++) {
            int cch = tid + i*128;
            int a = cch >> 9, rem = cch & 511;
            int row = rem >> 3, col = (rem & 7) * 8;
            uint32_t sa = smem_u32 + (uint32_t)(((2 + a)*64 + row)*ASTR + col)*2;
            cpa16(sa, srcs[a] + (size_t)row*64 + col);
        }
        asm volatile("cp.async.commit_group;");
    }
    asm volatile("cp.async.wait_group 0;");
    __syncthreads();

    int m0 = w * 16;
    int a_r = lane & 15;
    int a_c = ((lane >> 4) & 1) * 8;
    int b_r = (lane & 7) + ((lane >> 4) & 1) * 8;
    int b_c = ((lane >> 3) & 1) * 8;
    int v_r = ((lane >> 3) & 1) * 8 + (lane & 7);
    int v_c = ((lane >> 4) & 1) * 8;

    float O[8][4];
    float mrow[2] = {-1e30f, -1e30f};
    float lrow[2] = {0.f, 0.f};
    #pragma unroll
    for (int nt = 0; nt < 8; nt++)
        #pragma unroll
        for (int r = 0; r < 4; r++) O[nt][r] = 0.f;

    for (int kt = 0; kt <= qb; kt++) {
        int cur = kt & 1;
        // prefetch next tile into other stage
        if (kt < qb) {
            int st = cur ^ 1;
            #pragma unroll
            for (int i = 0; i < 16; i++) {
                int cch = tid + i*128;
                int a = cch >> 9, rem = cch & 511;
                int row = rem >> 3, col = (rem & 7) * 8;
                uint32_t sa = smem_u32 + (uint32_t)(((2 + 4*st + a)*64 + row)*ASTR + col)*2;
                cpa16(sa, srcs[a] + (size_t)((kt+1)*64 + row)*64 + col);
            }
            asm volatile("cp.async.commit_group;");
        }
        const __nv_bfloat16* Kh = sb + (2 + 4*cur)*64*ASTR;
        const __nv_bfloat16* Kl = Kh + 64*ASTR;
        const __nv_bfloat16* Vh = Kh + 2*64*ASTR;
        const __nv_bfloat16* Vl = Kh + 3*64*ASTR;

        // ---- S = Q K^T (compensated) ----
        float s[8][4];
        #pragma unroll
        for (int nt = 0; nt < 8; nt++)
            #pragma unroll
            for (int r = 0; r < 4; r++) s[nt][r] = 0.f;
        #pragma unroll
        for (int kk = 0; kk < 4; kk++) {
            uint32_t QAh[4], QAl[4];
            ldsm_x4(QAh, Qh + (m0 + a_r)*ASTR + kk*16 + a_c);
            ldsm_x4(QAl, Ql + (m0 + a_r)*ASTR + kk*16 + a_c);
            #pragma unroll
            for (int bn = 0; bn < 4; bn++) {
                uint32_t KBh[4], KBl[4];
                ldsm_x4(KBh, Kh + (bn*16 + b_r)*ASTR + kk*16 + b_c);
                ldsm_x4(KBl, Kl + (bn*16 + b_r)*ASTR + kk*16 + b_c);
                mma_bf16(s[2*bn],   QAh, KBh[0], KBh[1]);
                mma_bf16(s[2*bn+1], QAh, KBh[2], KBh[3]);
                mma_bf16(s[2*bn],   QAh, KBl[0], KBl[1]);
                mma_bf16(s[2*bn+1], QAh, KBl[2], KBl[3]);
                mma_bf16(s[2*bn],   QAl, KBh[0], KBh[1]);
                mma_bf16(s[2*bn+1], QAl, KBh[2], KBh[3]);
            }
        }
        // ---- causal mask on diagonal tile ----
        if (kt == qb) {
            int r0l = m0 + (lane >> 2);
            int c0l = 2*(lane & 3);
            #pragma unroll
            for (int nt = 0; nt < 8; nt++) {
                int c = nt*8 + c0l;
                if (c     > r0l)     s[nt][0] = -1e30f;
                if (c + 1 > r0l)     s[nt][1] = -1e30f;
                if (c     > r0l + 8) s[nt][2] = -1e30f;
                if (c + 1 > r0l + 8) s[nt][3] = -1e30f;
            }
        }
        // ---- online softmax ----
        float rm0 = -1e30f, rm1 = -1e30f;
        #pragma unroll
        for (int nt = 0; nt < 8; nt++) {
            rm0 = fmaxf(rm0, fmaxf(s[nt][0], s[nt][1]));
            rm1 = fmaxf(rm1, fmaxf(s[nt][2], s[nt][3]));
        }
        rm0 = fmaxf(rm0, __shfl_xor_sync(0xffffffffu, rm0, 1));
        rm0 = fmaxf(rm0, __shfl_xor_sync(0xffffffffu, rm0, 2));
        rm1 = fmaxf(rm1, __shfl_xor_sync(0xffffffffu, rm1, 1));
        rm1 = fmaxf(rm1, __shfl_xor_sync(0xffffffffu, rm1, 2));
        float mn0 = fmaxf(mrow[0], rm0), mn1 = fmaxf(mrow[1], rm1);
        float cc0 = __expf(mrow[0] - mn0), cc1 = __expf(mrow[1] - mn1);
        mrow[0] = mn0; mrow[1] = mn1;
        float rs0 = 0.f, rs1 = 0.f;
        #pragma unroll
        for (int nt = 0; nt < 8; nt++) {
            s[nt][0] = __expf(s[nt][0] - mn0); rs0 += s[nt][0];
            s[nt][1] = __expf(s[nt][1] - mn0); rs0 += s[nt][1];
            s[nt][2] = __expf(s[nt][2] - mn1); rs1 += s[nt][2];
            s[nt][3] = __expf(s[nt][3] - mn1); rs1 += s[nt][3];
        }
        rs0 += __shfl_xor_sync(0xffffffffu, rs0, 1);
        rs0 += __shfl_xor_sync(0xffffffffu, rs0, 2);
        rs1 += __shfl_xor_sync(0xffffffffu, rs1, 1);
        rs1 += __shfl_xor_sync(0xffffffffu, rs1, 2);
        lrow[0] = lrow[0]*cc0 + rs0;
        lrow[1] = lrow[1]*cc1 + rs1;
        #pragma unroll
        for (int nt = 0; nt < 8; nt++) {
            O[nt][0] *= cc0; O[nt][1] *= cc0;
            O[nt][2] *= cc1; O[nt][3] *= cc1;
        }
        // ---- O += P V ----
        #pragma unroll
        for (int kk = 0; kk < 4; kk++) {
            uint32_t Ph[4], Pl[4];
            split_pack(s[2*kk][0],   s[2*kk][1],   Ph[0], Pl[0]);
            split_pack(s[2*kk][2],   s[2*kk][3],   Ph[1], Pl[1]);
            split_pack(s[2*kk+1][0], s[2*kk+1][1], Ph[2], Pl[2]);
            split_pack(s[2*kk+1][2], s[2*kk+1][3], Ph[3], Pl[3]);
            #pragma unroll
            for (int bn = 0; bn < 4; bn++) {
                uint32_t VBh[4], VBl[4];
                ldsm_x4_t(VBh, Vh + (kk*16 + v_r)*ASTR + bn*16 + v_c);
                ldsm_x4_t(VBl, Vl + (kk*16 + v_r)*ASTR + bn*16 + v_c);
                mma_bf16(O[2*bn],   Ph, VBh[0], VBh[1]);
                mma_bf16(O[2*bn+1], Ph, VBh[2], VBh[3]);
                mma_bf16(O[2*bn],   Ph, VBl[0], VBl[1]);
                mma_bf16(O[2*bn+1], Ph, VBl[2], VBl[3]);
                mma_bf16(O[2*bn],   Pl, VBh[0], VBh[1]);
                mma_bf16(O[2*bn+1], Pl, VBh[2], VBh[3]);
            }
        }
        asm volatile("cp.async.wait_group 0;");
        __syncthreads();
    }
    // epilogue: write att h/l
    float inv0 = 1.f/lrow[0], inv1 = 1.f/lrow[1];
    int row0 = qb*64 + m0 + (lane >> 2);
    int row1 = row0 + 8;
    #pragma unroll
    for (int nt = 0; nt < 8; nt++) {
        int col = hh*64 + nt*8 + 2*(lane & 3);
        size_t o0 = ((size_t)b*SS + row0)*DD + col;
        size_t o1 = ((size_t)b*SS + row1)*DD + col;
        uint32_t hp, lp;
        split_pack(O[nt][0]*inv0, O[nt][1]*inv0, hp, lp);
        *(uint32_t*)&g_atth[o0] = hp;
        *(uint32_t*)&g_attl[o0] = lp;
        split_pack(O[nt][2]*inv1, O[nt][3]*inv1, hp, lp);
        *(uint32_t*)&g_atth[o1] = hp;
        *(uint32_t*)&g_attl[o1] = lp;
    }
}
#define FLASH_SMEM (10*64*ASTR*2)

// ---------------- router ----------------
__global__ void router_kernel(const float* __restrict__ rw) {
    int t = blockIdx.x*4 + (threadIdx.x >> 5);
    int lane = threadIdx.x & 31;
    const float* xr = g_x + (size_t)t*DD;
    float s = 0.f;
    for (int d = lane; d < DD; d += 32) s += xr[d]*rw[d];
    #pragma unroll
    for (int o = 16; o > 0; o >>= 1) s += __shfl_xor_sync(0xffffffffu, s, o);
    if (lane == 0) g_probs[t] = 1.f/(1.f + __expf(-s));
}

// ---------------- per-batch top-k via bitonic sort ----------------
__global__ void topk_kernel() {
    __shared__ float sv[2048];
    __shared__ int   si[2048];
    int bb = blockIdx.x;
    for (int i = threadIdx.x; i < 2048; i += 1024) { sv[i] = g_probs[(size_t)bb*SS + i]; si[i] = i; }
    __syncthreads();
    for (int k = 2; k <= 2048; k <<= 1) {
        for (int j = k >> 1; j > 0; j >>= 1) {
            for (int t = threadIdx.x; t < 2048; t += 1024) {
                int ixj = t ^ j;
                if (ixj > t) {
                    bool desc = ((t & k) == 0);
                    float a = sv[t], b2 = sv[ixj];
                    bool sw = desc ? (a < b2) : (a > b2);
                    if (sw) {
                        sv[t] = b2; sv[ixj] = a;
                        int tmp = si[t]; si[t] = si[ixj]; si[ixj] = tmp;
                    }
                }
            }
            __syncthreads();
        }
    }
    for (int i = threadIdx.x; i < KSEL; i += 1024) {
        g_tidx[(size_t)bb*KSEL + i] = si[i];
        g_tp[(size_t)bb*KSEL + i]   = sv[i];
    }
}

// ---------------- gather + rmsnorm (split out) ----------------
__global__ void gather_rmsnorm_kernel(const float* __restrict__ w) {
    int i = blockIdx.x;
    int b = i / KSEL;
    int tok = g_tidx[i];
    const float* xr = g_x + ((size_t)b*SS + tok)*DD;
    float ss = 0.f;
    for (int d = threadIdx.x; d < DD; d += 128) { float v = xr[d]; ss += v*v; }
    #pragma unroll
    for (int o = 16; o > 0; o >>= 1) ss += __shfl_xor_sync(0xffffffffu, ss, o);
    __shared__ float red[4];
    if ((threadIdx.x & 31) == 0) red[threadIdx.x >> 5] = ss;
    __syncthreads();
    float tot = red[0]+red[1]+red[2]+red[3];
    float sc = rsqrtf(tot*(1.f/DD) + EPSF);
    for (int d = threadIdx.x; d < DD; d += 128) {
        float y = w[d]*xr[d]*sc;
        split2(y, g_hsh[(size_t)i*DD + d], g_hsl[(size_t)i*DD + d]);
    }
}

// ---------------- silu(gate)*up -> split (reads merged g_gu) ----------------
__global__ void silu_kernel() {
    size_t i = (size_t)blockIdx.x*blockDim.x + threadIdx.x;
    if (i >= (size_t)M_SEL*FFF) return;
    size_t row = i / FFF, col = i % FFF;
    float g = g_gu[row*(2*FFF) + col];
    float u = g_gu[row*(2*FFF) + FFF + col];
    float sig = 1.f/(1.f + __expf(-g));
    split2(g*sig*u, g_gah[i], g_gal[i]);
}

// ---------------- host orchestration ----------------
extern "C" void kernel_launch(void* const* d_in, const int* in_sizes, int n_in,
                              void* d_out, int out_size) {
    const int*   ids       = (const int*)d_in[0];
    const int*   iter      = (const int*)d_in[1];
    const float* emb       = (const float*)d_in[2];
    const float* iter_emb  = (const float*)d_in[3];
    const float* attn_norm = (const float*)d_in[4];
    const float* Wqkv      = (const float*)d_in[5];
    const float* wo        = (const float*)d_in[6];
    const float* router    = (const float*)d_in[7];
    const float* mlp_norm  = (const float*)d_in[8];
    const float* gate_w    = (const float*)d_in[9];
    const float* up_w      = (const float*)d_in[10];
    const float* down_w    = (const float*)d_in[11];
    const float* fnorm     = (const float*)d_in[12];

    float *px, *pqkv, *pgu;
    __nv_bfloat16 *phh, *phl, *patth, *pattl, *phsh, *phsl, *pgah, *pgal;
    __nv_bfloat16 *pwqkvh, *pwqkvl, *pwoh, *pwol, *pwguh, *pwgul, *pwdh, *pwdl;
    cudaGetSymbolAddress((void**)&px,    g_x);
    cudaGetSymbolAddress((void**)&pqkv,  g_qkv);
    cudaGetSymbolAddress((void**)&pgu,   g_gu);
    cudaGetSymbolAddress((void**)&phh,   g_hh);
    cudaGetSymbolAddress((void**)&phl,   g_hl);
    cudaGetSymbolAddress((void**)&patth, g_atth);
    cudaGetSymbolAddress((void**)&pattl, g_attl);
    cudaGetSymbolAddress((void**)&phsh,  g_hsh);
    cudaGetSymbolAddress((void**)&phsl,  g_hsl);
    cudaGetSymbolAddress((void**)&pgah,  g_gah);
    cudaGetSymbolAddress((void**)&pgal,  g_gal);
    cudaGetSymbolAddress((void**)&pwqkvh, g_wqkvh);
    cudaGetSymbolAddress((void**)&pwqkvl, g_wqkvl);
    cudaGetSymbolAddress((void**)&pwoh,  g_woh);
    cudaGetSymbolAddress((void**)&pwol,  g_wol);
    cudaGetSymbolAddress((void**)&pwguh, g_wguh);
    cudaGetSymbolAddress((void**)&pwgul, g_wgul);
    cudaGetSymbolAddress((void**)&pwdh,  g_wdh);
    cudaGetSymbolAddress((void**)&pwdl,  g_wdl);

    cudaFuncSetAttribute(flash4_kernel, cudaFuncAttributeMaxDynamicSharedMemorySize, FLASH_SMEM);

    rope_table_kernel<<<(SS*32 + 255)/256, 256>>>();
    embed_kernel<<<(M_TOK*DD + 255)/256, 256>>>(ids, iter, emb, iter_emb);
    split_kernel<<<(NLL*3*DD*DD + 255)/256, 256>>>(Wqkv,  pwqkvh, pwqkvl, NLL*3*DD*DD);
    split_kernel<<<(NLL*DD*DD + 255)/256, 256>>>(wo,      pwoh,   pwol,   NLL*DD*DD);
    split_gu_kernel<<<(NLL*FFF*DD + 255)/256, 256>>>(gate_w, pwguh, pwgul, 0);
    split_gu_kernel<<<(NLL*FFF*DD + 255)/256, 256>>>(up_w,   pwguh, pwgul, FFF*DD);
    split_kernel<<<(NLL*DD*FFF + 255)/256, 256>>>(down_w, pwdh,   pwdl,   NLL*DD*FFF);

    for (int l = 0; l < NLL; l++) {
        rmsnorm_split_kernel<<<M_TOK, 128>>>(px, attn_norm + (size_t)l*DD, phh, phl);
        gemm_bf<0><<<dim3((3*DD+127)/128, M_TOK/128), 256>>>(phh, phl,
            pwqkvh + (size_t)l*3*DD*DD, pwqkvl + (size_t)l*3*DD*DD, pqkv, M_TOK, 3*DD, DD);
        rope_kernel<<<(M_TOK*NHH*32 + 255)/256, 256>>>();
        flash4_kernel<<<dim3(SS/64, NHH, BB), 128, FLASH_SMEM>>>();
        gemm_bf<1><<<dim3((DD+127)/128, M_TOK/128), 256>>>(patth, pattl,
            pwoh + (size_t)l*DD*DD, pwol + (size_t)l*DD*DD, px, M_TOK, DD, DD);
        router_kernel<<<M_TOK/4, 128>>>(router + (size_t)l*DD);
        topk_kernel<<<BB, 1024>>>();
        gather_rmsnorm_kernel<<<M_SEL, 128>>>(mlp_norm + (size_t)l*DD);
        gemm_bf<0><<<dim3((2*FFF+127)/128, (M_SEL+127)/128), 256>>>(phsh, phsl,
            pwguh + (size_t)l*2*FFF*DD, pwgul + (size_t)l*2*FFF*DD, pgu, M_SEL, 2*FFF, DD);
        silu_kernel<<<(int)(((size_t)M_SEL*FFF + 255)/256), 256>>>();
        gemm_bf<2><<<dim3((DD+127)/128, (M_SEL+127)/128), 256>>>(pgah, pgal,
            pwdh + (size_t)l*DD*FFF, pwdl + (size_t)l*DD*FFF, px, M_SEL, DD, FFF);
    }
    rmsnorm_f32_kernel<<<M_TOK, 128>>>(px, fnorm, (float*)d_out);
}

// round 7
// speedup vs baseline: 3.0963x; 1.0269x over previous
#include <cuda_runtime.h>
#include <cuda_bf16.h>
#include <math.h>
#include <stdint.h>

#define BB 8
#define SS 2048
#define DD 320
#define NHH 5
#define HDD 64
#define FFF 864
#define NLL 6
#define KSEL 1638
#define M_TOK (BB*SS)      // 16384
#define M_SEL (BB*KSEL)    // 13104
#define EPSF 1e-6f

// ---------------- scratch (static device globals; no allocation) ----------------
__device__ float g_x[M_TOK*DD];
__device__ float g_qkv[M_TOK*3*DD];
__device__ float g_probs[M_TOK];
__device__ int   g_tidx[M_SEL];
__device__ float g_tp[M_SEL];
__device__ float g_cos[SS*32];
__device__ float g_sin[SS*32];

// bf16 split activation buffers
__device__ __nv_bfloat16 g_hh[M_TOK*DD],  g_hl[M_TOK*DD];
__device__ __nv_bfloat16 g_atth[M_TOK*DD], g_attl[M_TOK*DD];
__device__ __nv_bfloat16 g_hsh[M_SEL*DD], g_hsl[M_SEL*DD];
__device__ __nv_bfloat16 g_gah[(size_t)M_SEL*FFF], g_gal[(size_t)M_SEL*FFF];
// bf16 split q/k/v  ([B,NH,S,HD], q pre-scaled)
__device__ __nv_bfloat16 g_qh[M_TOK*DD], g_ql[M_TOK*DD];
__device__ __nv_bfloat16 g_kh[M_TOK*DD], g_kl[M_TOK*DD];
__device__ __nv_bfloat16 g_vh[M_TOK*DD], g_vl[M_TOK*DD];
// bf16 split weights
__device__ __nv_bfloat16 g_wqkvh[NLL*3*DD*DD], g_wqkvl[NLL*3*DD*DD];
__device__ __nv_bfloat16 g_woh[NLL*DD*DD],     g_wol[NLL*DD*DD];
__device__ __nv_bfloat16 g_wguh[NLL*2*FFF*DD], g_wgul[NLL*2*FFF*DD]; // interleaved: row 2i=gate_i, 2i+1=up_i
__device__ __nv_bfloat16 g_wdh[NLL*DD*FFF],    g_wdl[NLL*DD*FFF];

__device__ __forceinline__ void split2(float x, __nv_bfloat16& h, __nv_bfloat16& l) {
    h = __float2bfloat16_rn(x);
    l = __float2bfloat16_rn(x - __bfloat162float(h));
}
__device__ __forceinline__ void split_pack(float x, float y, uint32_t& hp, uint32_t& lp) {
    __nv_bfloat162 h2, l2;
    split2(x, h2.x, l2.x);
    split2(y, h2.y, l2.y);
    hp = *reinterpret_cast<uint32_t*>(&h2);
    lp = *reinterpret_cast<uint32_t*>(&l2);
}

// ---------------- weight splits ----------------
__global__ void split_kernel(const float* __restrict__ src, __nv_bfloat16* __restrict__ h,
                             __nv_bfloat16* __restrict__ l, int n) {
    int i = blockIdx.x*blockDim.x + threadIdx.x;
    if (i >= n) return;
    split2(src[i], h[i], l[i]);
}
// interleave gate/up: src row i of layer -> dst row 2i+which
__global__ void split_gu_kernel(const float* __restrict__ src, __nv_bfloat16* __restrict__ h,
                                __nv_bfloat16* __restrict__ l, int which) {
    int i = blockIdx.x*blockDim.x + threadIdx.x;
    if (i >= NLL*FFF*DD) return;
    int lay = i / (FFF*DD), rem = i % (FFF*DD);
    int r = rem / DD, d = rem % DD;
    size_t dst = (size_t)lay*2*FFF*DD + (size_t)(2*r + which)*DD + d;
    split2(src[i], h[dst], l[dst]);
}

// ---------------- rope tables ----------------
__global__ void rope_table_kernel() {
    int i = blockIdx.x*blockDim.x + threadIdx.x;
    if (i >= SS*32) return;
    int s = i / 32, d = i % 32;
    double freq = exp(-((double)(2*d)/64.0)*log(10000.0));
    double f = (double)s * freq;
    g_cos[i] = (float)cos(f);
    g_sin[i] = (float)sin(f);
}

// ---------------- embed ----------------
__global__ void embed_kernel(const int* __restrict__ ids, const int* __restrict__ iter,
                             const float* __restrict__ emb, const float* __restrict__ iter_emb) {
    int i = blockIdx.x*blockDim.x + threadIdx.x;
    if (i >= M_TOK*DD) return;
    int t = i / DD, d = i % DD;
    float v = emb[(size_t)ids[t]*DD + d];
    int it = iter[0];
    if (it < 8) v += iter_emb[(size_t)it*DD + d];
    g_x[i] = v;
}

// ---------------- rmsnorm variants ----------------
__global__ void rmsnorm_f32_kernel(const float* __restrict__ X, const float* __restrict__ w,
                                   float* __restrict__ Y) {
    int t = blockIdx.x;
    const float* xr = X + (size_t)t*DD;
    float ss = 0.f;
    for (int d = threadIdx.x; d < DD; d += 128) { float v = xr[d]; ss += v*v; }
    #pragma unroll
    for (int o = 16; o > 0; o >>= 1) ss += __shfl_xor_sync(0xffffffffu, ss, o);
    __shared__ float red[4];
    if ((threadIdx.x & 31) == 0) red[threadIdx.x >> 5] = ss;
    __syncthreads();
    float tot = red[0]+red[1]+red[2]+red[3];
    float sc = rsqrtf(tot*(1.f/DD) + EPSF);
    for (int d = threadIdx.x; d < DD; d += 128) Y[(size_t)t*DD + d] = w[d]*xr[d]*sc;
}

__global__ void rmsnorm_split_kernel(const float* __restrict__ X, const float* __restrict__ w,
                                     __nv_bfloat16* __restrict__ Yh, __nv_bfloat16* __restrict__ Yl) {
    int t = blockIdx.x;
    const float* xr = X + (size_t)t*DD;
    float ss = 0.f;
    for (int d = threadIdx.x; d < DD; d += 128) { float v = xr[d]; ss += v*v; }
    #pragma unroll
    for (int o = 16; o > 0; o >>= 1) ss += __shfl_xor_sync(0xffffffffu, ss, o);
    __shared__ float red[4];
    if ((threadIdx.x & 31) == 0) red[threadIdx.x >> 5] = ss;
    __syncthreads();
    float tot = red[0]+red[1]+red[2]+red[3];
    float sc = rsqrtf(tot*(1.f/DD) + EPSF);
    for (int d = threadIdx.x; d < DD; d += 128) {
        float y = w[d]*xr[d]*sc;
        split2(y, Yh[(size_t)t*DD + d], Yl[(size_t)t*DD + d]);
    }
}

// ================= tensor-core GEMM (pre-split bf16, double-buffered) =================
__device__ __forceinline__ void ldsm_x4(uint32_t* r, const __nv_bfloat16* p) {
    uint32_t addr = (uint32_t)__cvta_generic_to_shared(p);
    asm volatile("ldmatrix.sync.aligned.m8n8.x4.shared.b16 {%0,%1,%2,%3}, [%4];"
                 : "=r"(r[0]), "=r"(r[1]), "=r"(r[2]), "=r"(r[3]) : "r"(addr));
}
__device__ __forceinline__ void ldsm_x4_t(uint32_t* r, const __nv_bfloat16* p) {
    uint32_t addr = (uint32_t)__cvta_generic_to_shared(p);
    asm volatile("ldmatrix.sync.aligned.m8n8.x4.trans.shared.b16 {%0,%1,%2,%3}, [%4];"
                 : "=r"(r[0]), "=r"(r[1]), "=r"(r[2]), "=r"(r[3]) : "r"(addr));
}
__device__ __forceinline__ void mma_bf16(float* c, const uint32_t* a, uint32_t b0, uint32_t b1) {
    asm volatile(
        "mma.sync.aligned.m16n8k16.row.col.f32.bf16.bf16.f32 "
        "{%0,%1,%2,%3}, {%4,%5,%6,%7}, {%8,%9}, {%0,%1,%2,%3};\n"
        : "+f"(c[0]), "+f"(c[1]), "+f"(c[2]), "+f"(c[3])
        : "r"(a[0]), "r"(a[1]), "r"(a[2]), "r"(a[3]), "r"(b0), "r"(b1));
}

#define LDSTR 24
#define STAGE (4*128*LDSTR)   // one stage: 4 arrays of 128xLDSTR halves

// MODE: 0 = store C, 1 = accumulate into C, 2 = scatter-add into x (C = g_x base),
// MODE: 3 = fused silu(gate)*up -> split bf16 into g_gah/g_gal (C unused)
template<int MODE>
__global__ void __launch_bounds__(256) gemm_bf(const __nv_bfloat16* __restrict__ Ah, const __nv_bfloat16* __restrict__ Al,
                                               const __nv_bfloat16* __restrict__ Bh, const __nv_bfloat16* __restrict__ Bl,
                                               float* __restrict__ C, int M, int N, int K) {
    __shared__ __nv_bfloat16 sm[2*STAGE];

    int tid = threadIdx.x;
    int lane = tid & 31, wid = tid >> 5;
    int wm = (wid & 1) * 64;
    int wn = (wid >> 1) * 32;
    int row0 = blockIdx.y * 128, col0 = blockIdx.x * 128;

    int srow = tid >> 1;
    int scol = (tid & 1) * 8;
    size_t aoffg = (size_t)(row0 + srow) * K + scol;
    size_t boffg = (size_t)(col0 + srow) * K + scol;
    bool aval = (row0 + srow) < M;
    bool bval = (col0 + srow) < N;
    int sput = srow*LDSTR + scol;

    float acc[4][4][4];
    #pragma unroll
    for (int i = 0; i < 4; i++)
        #pragma unroll
        for (int j = 0; j < 4; j++)
            #pragma unroll
            for (int r = 0; r < 4; r++) acc[i][j][r] = 0.f;

    int a_r = lane & 15;
    int a_c = ((lane >> 4) & 1) * 8;
    int b_r = (lane & 7) + ((lane >> 4) & 1) * 8;
    int b_c = ((lane >> 3) & 1) * 8;
    int aoff[4], boff[2];
    #pragma unroll
    for (int mt = 0; mt < 4; mt++) aoff[mt] = (wm + mt*16 + a_r)*LDSTR + a_c;
    #pragma unroll
    for (int pr = 0; pr < 2; pr++) boff[pr] = (wn + pr*16 + b_r)*LDSTR + b_c;

    const uint4 uz = make_uint4(0,0,0,0);
    uint4 rAh, rAl, rBh, rBl;
    rAh = aval ? *(const uint4*)(Ah + aoffg) : uz;
    rAl = aval ? *(const uint4*)(Al + aoffg) : uz;
    rBh = bval ? *(const uint4*)(Bh + boffg) : uz;
    rBl = bval ? *(const uint4*)(Bl + boffg) : uz;

    *(uint4*)&sm[0*STAGE + 0*128*LDSTR + sput] = rAh;
    *(uint4*)&sm[0*STAGE + 1*128*LDSTR + sput] = rAl;
    *(uint4*)&sm[0*STAGE + 2*128*LDSTR + sput] = rBh;
    *(uint4*)&sm[0*STAGE + 3*128*LDSTR + sput] = rBl;
    __syncthreads();

    int nk = K >> 4;
    for (int ks = 0; ks < nk; ks++) {
        int cur = ks & 1;
        if (ks + 1 < nk) {
            int k0 = (ks + 1) << 4;
            rAh = aval ? *(const uint4*)(Ah + aoffg + k0) : uz;
            rAl = aval ? *(const uint4*)(Al + aoffg + k0) : uz;
            rBh = bval ? *(const uint4*)(Bh + boffg + k0) : uz;
            rBl = bval ? *(const uint4*)(Bl + boffg + k0) : uz;
        }
        const __nv_bfloat16* cAh = sm + cur*STAGE;
        const __nv_bfloat16* cAl = cAh + 128*LDSTR;
        const __nv_bfloat16* cBh = cAh + 2*128*LDSTR;
        const __nv_bfloat16* cBl = cAh + 3*128*LDSTR;

        uint32_t fAh[4][4], fAl[4][4], fBh[2][4], fBl[2][4];
        #pragma unroll
        for (int mt = 0; mt < 4; mt++) { ldsm_x4(fAh[mt], cAh + aoff[mt]); ldsm_x4(fAl[mt], cAl + aoff[mt]); }
        #pragma unroll
        for (int pr = 0; pr < 2; pr++) { ldsm_x4(fBh[pr], cBh + boff[pr]); ldsm_x4(fBl[pr], cBl + boff[pr]); }

        #pragma unroll
        for (int mt = 0; mt < 4; mt++)
            #pragma unroll
            for (int nt = 0; nt < 4; nt++)
                mma_bf16(acc[mt][nt], fAh[mt], fBh[nt>>1][(nt&1)*2], fBh[nt>>1][(nt&1)*2+1]);
        #pragma unroll
        for (int mt = 0; mt < 4; mt++)
            #pragma unroll
            for (int nt = 0; nt < 4; nt++)
                mma_bf16(acc[mt][nt], fAh[mt], fBl[nt>>1][(nt&1)*2], fBl[nt>>1][(nt&1)*2+1]);
        #pragma unroll
        for (int mt = 0; mt < 4; mt++)
            #pragma unroll
            for (int nt = 0; nt < 4; nt++)
                mma_bf16(acc[mt][nt], fAl[mt], fBh[nt>>1][(nt&1)*2], fBh[nt>>1][(nt&1)*2+1]);

        if (ks + 1 < nk) {
            __nv_bfloat16* nx = sm + (cur^1)*STAGE;
            *(uint4*)&nx[0*128*LDSTR + sput] = rAh;
            *(uint4*)&nx[1*128*LDSTR + sput] = rAl;
            *(uint4*)&nx[2*128*LDSTR + sput] = rBh;
            *(uint4*)&nx[3*128*LDSTR + sput] = rBl;
        }
        __syncthreads();
    }

    int erow = lane >> 2;
    int ecol = (lane & 3) * 2;
    #pragma unroll
    for (int mt = 0; mt < 4; mt++) {
        #pragma unroll
        for (int nt = 0; nt < 4; nt++) {
            int r = row0 + wm + mt*16 + erow;
            int c = col0 + wn + nt*8 + ecol;
            if (c < N) {
                if (MODE == 3) {
                    // c is even; pair (gate, up) for ff index c/2
                    size_t i0 = (size_t)(c >> 1);
                    if (r < M) {
                        float g = acc[mt][nt][0], u = acc[mt][nt][1];
                        float v = g * (1.f/(1.f + __expf(-g))) * u;
                        split2(v, g_gah[(size_t)r*FFF + i0], g_gal[(size_t)r*FFF + i0]);
                    }
                    if (r + 8 < M) {
                        float g = acc[mt][nt][2], u = acc[mt][nt][3];
                        float v = g * (1.f/(1.f + __expf(-g))) * u;
                        split2(v, g_gah[(size_t)(r+8)*FFF + i0], g_gal[(size_t)(r+8)*FFF + i0]);
                    }
                } else if (MODE == 2) {
                    if (r < M) {
                        int b = r / KSEL;
                        int tok = g_tidx[r];
                        float p = g_tp[r];
                        float2* ptr = (float2*)&C[((size_t)b*SS + tok)*DD + c];
                        float2 o = *ptr; o.x += acc[mt][nt][0]*p; o.y += acc[mt][nt][1]*p; *ptr = o;
                    }
                    if (r + 8 < M) {
                        int r8 = r + 8;
                        int b = r8 / KSEL;
                        int tok = g_tidx[r8];
                        float p = g_tp[r8];
                        float2* ptr = (float2*)&C[((size_t)b*SS + tok)*DD + c];
                        float2 o = *ptr; o.x += acc[mt][nt][2]*p; o.y += acc[mt][nt][3]*p; *ptr = o;
                    }
                } else {
                    if (r < M) {
                        float2* p = (float2*)&C[(size_t)r*N + c];
                        if (MODE == 1) { float2 o = *p; o.x += acc[mt][nt][0]; o.y += acc[mt][nt][1]; *p = o; }
                        else { float2 o; o.x = acc[mt][nt][0]; o.y = acc[mt][nt][1]; *p = o; }
                    }
                    if (r + 8 < M) {
                        float2* p = (float2*)&C[(size_t)(r+8)*N + c];
                        if (MODE == 1) { float2 o = *p; o.x += acc[mt][nt][2]; o.y += acc[mt][nt][3]; *p = o; }
                        else { float2 o; o.x = acc[mt][nt][2]; o.y = acc[mt][nt][3]; *p = o; }
                    }
                }
            }
        }
    }
}

// ---------------- rope + split to bf16 h/l [B,NH,S,HD] ----------------
__global__ void rope_kernel() {
    int i = blockIdx.x*blockDim.x + threadIdx.x;
    if (i >= M_TOK*NHH*32) return;
    int t = i / (NHH*32);
    int r = i % (NHH*32);
    int h = r / 32, d = r % 32;
    int b = t / SS, s = t % SS;
    const float* base = g_qkv + (size_t)t*(3*DD) + h*HDD;
    float c = g_cos[s*32+d], sn = g_sin[s*32+d];
    float q1 = base[d],        q2 = base[d+32];
    float k1 = base[DD+d],     k2 = base[DD+d+32];
    size_t o = ((size_t)(b*NHH+h)*SS + s)*HDD;
    float qa = (q1*c - q2*sn)*0.125f;
    float qb2 = (q2*c + q1*sn)*0.125f;
    float ka = k1*c - k2*sn;
    float kb = k2*c + k1*sn;
    split2(qa,  g_qh[o+d],    g_ql[o+d]);
    split2(qb2, g_qh[o+d+32], g_ql[o+d+32]);
    split2(ka,  g_kh[o+d],    g_kl[o+d]);
    split2(kb,  g_kh[o+d+32], g_kl[o+d+32]);
    split2(base[2*DD+d],    g_vh[o+d],    g_vl[o+d]);
    split2(base[2*DD+d+32], g_vh[o+d+32], g_vl[o+d+32]);
}

// ---------------- flash attention v5: 128q x 64k tiles, 256 thr, cp.async double-buffered ----
#define ASTR 72
#define QHALVES (128*ASTR)             // per Q array
#define KVOFF (2*QHALVES)              // start of K/V stages (in halves)
__device__ __forceinline__ void cpa16(uint32_t saddr, const void* g) {
    asm volatile("cp.async.cg.shared.global [%0], [%1], 16;" :: "r"(saddr), "l"(g));
}

__global__ void __launch_bounds__(256) flash5_kernel() {
    extern __shared__ __nv_bfloat16 sb[];
    __nv_bfloat16* Qh = sb;
    __nv_bfloat16* Ql = sb + QHALVES;
    uint32_t smem_u32 = (uint32_t)__cvta_generic_to_shared(sb);

    int b = blockIdx.z, hh = blockIdx.y;
    int qb = (int)(gridDim.x - 1u - blockIdx.x);   // heavy first
    int tid = threadIdx.x, lane = tid & 31, w = tid >> 5;
    size_t headoff = ((size_t)(b*NHH+hh)*SS)*HDD;
    const __nv_bfloat16 *Qhp = g_qh + headoff, *Qlp = g_ql + headoff;
    const __nv_bfloat16* srcs[4] = {g_kh + headoff, g_kl + headoff, g_vh + headoff, g_vl + headoff};

    // load Q tile (128 x 64): 1024 uint4 per array, 4 per thread
    {
        #pragma unroll
        for (int i = 0; i < 4; i++) {
            int idx = i*256 + tid;
            int rr = idx >> 3, c = (idx & 7) * 8;
            *(uint4*)&Qh[rr*ASTR + c] = *(const uint4*)&Qhp[(size_t)(qb*128 + rr)*64 + c];
            *(uint4*)&Ql[rr*ASTR + c] = *(const uint4*)&Qlp[(size_t)(qb*128 + rr)*64 + c];
        }
    }
    // issue K/V tile 0 into stage 0 (2048 uint4 over 256 threads)
    {
        #pragma unroll
        for (int i = 0; i < 8; i++) {
            int u = i*256 + tid;
            int a = u >> 9, rem = u & 511;
            int row = rem >> 3, col = (rem & 7) * 8;
            uint32_t sa = smem_u32 + (uint32_t)(KVOFF + (a*64 + row)*ASTR + col)*2;
            cpa16(sa, srcs[a] + (size_t)row*64 + col);
        }
        asm volatile("cp.async.commit_group;");
    }
    asm volatile("cp.async.wait_group 0;");
    __syncthreads();

    int m0 = w * 16;
    int a_r = lane & 15;
    int a_c = ((lane >> 4) & 1) * 8;
    int b_r = (lane & 7) + ((lane >> 4) & 1) * 8;
    int b_c = ((lane >> 3) & 1) * 8;
    int v_r = ((lane >> 3) & 1) * 8 + (lane & 7);
    int v_c = ((lane >> 4) & 1) * 8;

    float O[8][4];
    float mrow[2] = {-1e30f, -1e30f};
    float lrow[2] = {0.f, 0.f};
    #pragma unroll
    for (int nt = 0; nt < 8; nt++)
        #pragma unroll
        for (int r = 0; r < 4; r++) O[nt][r] = 0.f;

    int ntiles = 2*qb + 2;
    for (int kt = 0; kt < ntiles; kt++) {
        int cur = kt & 1;
        if (kt + 1 < ntiles) {
            int st = cur ^ 1;
            #pragma unroll
            for (int i = 0; i < 8; i++) {
                int u = i*256 + tid;
                int a = u >> 9, rem = u & 511;
                int row = rem >> 3, col = (rem & 7) * 8;
                uint32_t sa = smem_u32 + (uint32_t)(KVOFF + ((4*st + a)*64 + row)*ASTR + col)*2;
                cpa16(sa, srcs[a] + (size_t)((kt+1)*64 + row)*64 + col);
            }
            asm volatile("cp.async.commit_group;");
        }
        const __nv_bfloat16* Kh = sb + KVOFF + (4*cur)*64*ASTR;
        const __nv_bfloat16* Kl = Kh + 64*ASTR;
        const __nv_bfloat16* Vh = Kh + 2*64*ASTR;
        const __nv_bfloat16* Vl = Kh + 3*64*ASTR;

        // ---- S = Q K^T (compensated) ----
        float s[8][4];
        #pragma unroll
        for (int nt = 0; nt < 8; nt++)
            #pragma unroll
            for (int r = 0; r < 4; r++) s[nt][r] = 0.f;
        #pragma unroll
        for (int kk = 0; kk < 4; kk++) {
            uint32_t QAh[4], QAl[4];
            ldsm_x4(QAh, Qh + (m0 + a_r)*ASTR + kk*16 + a_c);
            ldsm_x4(QAl, Ql + (m0 + a_r)*ASTR + kk*16 + a_c);
            #pragma unroll
            for (int bn = 0; bn < 4; bn++) {
                uint32_t KBh[4], KBl[4];
                ldsm_x4(KBh, Kh + (bn*16 + b_r)*ASTR + kk*16 + b_c);
                ldsm_x4(KBl, Kl + (bn*16 + b_r)*ASTR + kk*16 + b_c);
                mma_bf16(s[2*bn],   QAh, KBh[0], KBh[1]);
                mma_bf16(s[2*bn+1], QAh, KBh[2], KBh[3]);
                mma_bf16(s[2*bn],   QAh, KBl[0], KBl[1]);
                mma_bf16(s[2*bn+1], QAh, KBl[2], KBl[3]);
                mma_bf16(s[2*bn],   QAl, KBh[0], KBh[1]);
                mma_bf16(s[2*bn+1], QAl, KBh[2], KBh[3]);
            }
        }
        // ---- causal mask on diagonal band (last two k-tiles) ----
        if (kt >= 2*qb) {
            int r0l = m0 + (lane >> 2);          // local q row (block-relative): 0..127
            int c0l = (kt - 2*qb)*64 + 2*(lane & 3);  // local k col within 128-band
            #pragma unroll
            for (int nt = 0; nt < 8; nt++) {
                int c = nt*8 + c0l;
                if (c     > r0l)     s[nt][0] = -1e30f;
                if (c + 1 > r0l)     s[nt][1] = -1e30f;
                if (c     > r0l + 8) s[nt][2] = -1e30f;
                if (c + 1 > r0l + 8) s[nt][3] = -1e30f;
            }
        }
        // ---- online softmax ----
        float rm0 = -1e30f, rm1 = -1e30f;
        #pragma unroll
        for (int nt = 0; nt < 8; nt++) {
            rm0 = fmaxf(rm0, fmaxf(s[nt][0], s[nt][1]));
            rm1 = fmaxf(rm1, fmaxf(s[nt][2], s[nt][3]));
        }
        rm0 = fmaxf(rm0, __shfl_xor_sync(0xffffffffu, rm0, 1));
        rm0 = fmaxf(rm0, __shfl_xor_sync(0xffffffffu, rm0, 2));
        rm1 = fmaxf(rm1, __shfl_xor_sync(0xffffffffu, rm1, 1));
        rm1 = fmaxf(rm1, __shfl_xor_sync(0xffffffffu, rm1, 2));
        float mn0 = fmaxf(mrow[0], rm0), mn1 = fmaxf(mrow[1], rm1);
        float cc0 = __expf(mrow[0] - mn0), cc1 = __expf(mrow[1] - mn1);
        mrow[0] = mn0; mrow[1] = mn1;
        float rs0 = 0.f, rs1 = 0.f;
        #pragma unroll
        for (int nt = 0; nt < 8; nt++) {
            s[nt][0] = __expf(s[nt][0] - mn0); rs0 += s[nt][0];
            s[nt][1] = __expf(s[nt][1] - mn0); rs0 += s[nt][1];
            s[nt][2] = __expf(s[nt][2] - mn1); rs1 += s[nt][2];
            s[nt][3] = __expf(s[nt][3] - mn1); rs1 += s[nt][3];
        }
        rs0 += __shfl_xor_sync(0xffffffffu, rs0, 1);
        rs0 += __shfl_xor_sync(0xffffffffu, rs0, 2);
        rs1 += __shfl_xor_sync(0xffffffffu, rs1, 1);
        rs1 += __shfl_xor_sync(0xffffffffu, rs1, 2);
        lrow[0] = lrow[0]*cc0 + rs0;
        lrow[1] = lrow[1]*cc1 + rs1;
        #pragma unroll
        for (int nt = 0; nt < 8; nt++) {
            O[nt][0] *= cc0; O[nt][1] *= cc0;
            O[nt][2] *= cc1; O[nt][3] *= cc1;
        }
        // ---- O += P V (P fragments direct from s; compensated) ----
        #pragma unroll
        for (int kk = 0; kk < 4; kk++) {
            uint32_t Ph[4], Pl[4];
            split_pack(s[2*kk][0],   s[2*kk][1],   Ph[0], Pl[0]);
            split_pack(s[2*kk][2],   s[2*kk][3],   Ph[1], Pl[1]);
            split_pack(s[2*kk+1][0], s[2*kk+1][1], Ph[2], Pl[2]);
            split_pack(s[2*kk+1][2], s[2*kk+1][3], Ph[3], Pl[3]);
            #pragma unroll
            for (int bn = 0; bn < 4; bn++) {
                uint32_t VBh[4], VBl[4];
                ldsm_x4_t(VBh, Vh + (kk*16 + v_r)*ASTR + bn*16 + v_c);
                ldsm_x4_t(VBl, Vl + (kk*16 + v_r)*ASTR + bn*16 + v_c);
                mma_bf16(O[2*bn],   Ph, VBh[0], VBh[1]);
                mma_bf16(O[2*bn+1], Ph, VBh[2], VBh[3]);
                mma_bf16(O[2*bn],   Ph, VBl[0], VBl[1]);
                mma_bf16(O[2*bn+1], Ph, VBl[2], VBl[3]);
                mma_bf16(O[2*bn],   Pl, VBh[0], VBh[1]);
                mma_bf16(O[2*bn+1], Pl, VBh[2], VBh[3]);
            }
        }
        asm volatile("cp.async.wait_group 0;");
        __syncthreads();
    }
    // epilogue: write att h/l
    float inv0 = 1.f/lrow[0], inv1 = 1.f/lrow[1];
    int row0 = qb*128 + m0 + (lane >> 2);
    int row1 = row0 + 8;
    #pragma unroll
    for (int nt = 0; nt < 8; nt++) {
        int col = hh*64 + nt*8 + 2*(lane & 3);
        size_t o0 = ((size_t)b*SS + row0)*DD + col;
        size_t o1 = ((size_t)b*SS + row1)*DD + col;
        uint32_t hp, lp;
        split_pack(O[nt][0]*inv0, O[nt][1]*inv0, hp, lp);
        *(uint32_t*)&g_atth[o0] = hp;
        *(uint32_t*)&g_attl[o0] = lp;
        split_pack(O[nt][2]*inv1, O[nt][3]*inv1, hp, lp);
        *(uint32_t*)&g_atth[o1] = hp;
        *(uint32_t*)&g_attl[o1] = lp;
    }
}
#define FLASH_SMEM ((2*128 + 8*64)*ASTR*2)   // 110592 bytes

// ---------------- router ----------------
__global__ void router_kernel(const float* __restrict__ rw) {
    int t = blockIdx.x*4 + (threadIdx.x >> 5);
    int lane = threadIdx.x & 31;
    const float* xr = g_x + (size_t)t*DD;
    float s = 0.f;
    for (int d = lane; d < DD; d += 32) s += xr[d]*rw[d];
    #pragma unroll
    for (int o = 16; o > 0; o >>= 1) s += __shfl_xor_sync(0xffffffffu, s, o);
    if (lane == 0) g_probs[t] = 1.f/(1.f + __expf(-s));
}

// ---------------- per-batch top-k via bitonic sort ----------------
__global__ void topk_kernel() {
    __shared__ float sv[2048];
    __shared__ int   si[2048];
    int bb = blockIdx.x;
    for (int i = threadIdx.x; i < 2048; i += 1024) { sv[i] = g_probs[(size_t)bb*SS + i]; si[i] = i; }
    __syncthreads();
    for (int k = 2; k <= 2048; k <<= 1) {
        for (int j = k >> 1; j > 0; j >>= 1) {
            for (int t = threadIdx.x; t < 2048; t += 1024) {
                int ixj = t ^ j;
                if (ixj > t) {
                    bool desc = ((t & k) == 0);
                    float a = sv[t], b2 = sv[ixj];
                    bool sw = desc ? (a < b2) : (a > b2);
                    if (sw) {
                        sv[t] = b2; sv[ixj] = a;
                        int tmp = si[t]; si[t] = si[ixj]; si[ixj] = tmp;
                    }
                }
            }
            __syncthreads();
        }
    }
    for (int i = threadIdx.x; i < KSEL; i += 1024) {
        g_tidx[(size_t)bb*KSEL + i] = si[i];
        g_tp[(size_t)bb*KSEL + i]   = sv[i];
    }
}

// ---------------- gather + rmsnorm (split out) ----------------
__global__ void gather_rmsnorm_kernel(const float* __restrict__ w) {
    int i = blockIdx.x;
    int b = i / KSEL;
    int tok = g_tidx[i];
    const float* xr = g_x + ((size_t)b*SS + tok)*DD;
    float ss = 0.f;
    for (int d = threadIdx.x; d < DD; d += 128) { float v = xr[d]; ss += v*v; }
    #pragma unroll
    for (int o = 16; o > 0; o >>= 1) ss += __shfl_xor_sync(0xffffffffu, ss, o);
    __shared__ float red[4];
    if ((threadIdx.x & 31) == 0) red[threadIdx.x >> 5] = ss;
    __syncthreads();
    float tot = red[0]+red[1]+red[2]+red[3];
    float sc = rsqrtf(tot*(1.f/DD) + EPSF);
    for (int d = threadIdx.x; d < DD; d += 128) {
        float y = w[d]*xr[d]*sc;
        split2(y, g_hsh[(size_t)i*DD + d], g_hsl[(size_t)i*DD + d]);
    }
}

// ---------------- host orchestration ----------------
extern "C" void kernel_launch(void* const* d_in, const int* in_sizes, int n_in,
                              void* d_out, int out_size) {
    const int*   ids       = (const int*)d_in[0];
    const int*   iter      = (const int*)d_in[1];
    const float* emb       = (const float*)d_in[2];
    const float* iter_emb  = (const float*)d_in[3];
    const float* attn_norm = (const float*)d_in[4];
    const float* Wqkv      = (const float*)d_in[5];
    const float* wo        = (const float*)d_in[6];
    const float* router    = (const float*)d_in[7];
    const float* mlp_norm  = (const float*)d_in[8];
    const float* gate_w    = (const float*)d_in[9];
    const float* up_w      = (const float*)d_in[10];
    const float* down_w    = (const float*)d_in[11];
    const float* fnorm     = (const float*)d_in[12];

    float *px, *pqkv;
    __nv_bfloat16 *phh, *phl, *patth, *pattl, *phsh, *phsl, *pgah, *pgal;
    __nv_bfloat16 *pwqkvh, *pwqkvl, *pwoh, *pwol, *pwguh, *pwgul, *pwdh, *pwdl;
    cudaGetSymbolAddress((void**)&px,    g_x);
    cudaGetSymbolAddress((void**)&pqkv,  g_qkv);
    cudaGetSymbolAddress((void**)&phh,   g_hh);
    cudaGetSymbolAddress((void**)&phl,   g_hl);
    cudaGetSymbolAddress((void**)&patth, g_atth);
    cudaGetSymbolAddress((void**)&pattl, g_attl);
    cudaGetSymbolAddress((void**)&phsh,  g_hsh);
    cudaGetSymbolAddress((void**)&phsl,  g_hsl);
    cudaGetSymbolAddress((void**)&pgah,  g_gah);
    cudaGetSymbolAddress((void**)&pgal,  g_gal);
    cudaGetSymbolAddress((void**)&pwqkvh, g_wqkvh);
    cudaGetSymbolAddress((void**)&pwqkvl, g_wqkvl);
    cudaGetSymbolAddress((void**)&pwoh,  g_woh);
    cudaGetSymbolAddress((void**)&pwol,  g_wol);
    cudaGetSymbolAddress((void**)&pwguh, g_wguh);
    cudaGetSymbolAddress((void**)&pwgul, g_wgul);
    cudaGetSymbolAddress((void**)&pwdh,  g_wdh);
    cudaGetSymbolAddress((void**)&pwdl,  g_wdl);

    cudaFuncSetAttribute(flash5_kernel, cudaFuncAttributeMaxDynamicSharedMemorySize, FLASH_SMEM);

    rope_table_kernel<<<(SS*32 + 255)/256, 256>>>();
    embed_kernel<<<(M_TOK*DD + 255)/256, 256>>>(ids, iter, emb, iter_emb);
    split_kernel<<<(NLL*3*DD*DD + 255)/256, 256>>>(Wqkv,  pwqkvh, pwqkvl, NLL*3*DD*DD);
    split_kernel<<<(NLL*DD*DD + 255)/256, 256>>>(wo,      pwoh,   pwol,   NLL*DD*DD);
    split_gu_kernel<<<(NLL*FFF*DD + 255)/256, 256>>>(gate_w, pwguh, pwgul, 0);
    split_gu_kernel<<<(NLL*FFF*DD + 255)/256, 256>>>(up_w,   pwguh, pwgul, 1);
    split_kernel<<<(NLL*DD*FFF + 255)/256, 256>>>(down_w, pwdh,   pwdl,   NLL*DD*FFF);

    for (int l = 0; l < NLL; l++) {
        rmsnorm_split_kernel<<<M_TOK, 128>>>(px, attn_norm + (size_t)l*DD, phh, phl);
        gemm_bf<0><<<dim3((3*DD+127)/128, M_TOK/128), 256>>>(phh, phl,
            pwqkvh + (size_t)l*3*DD*DD, pwqkvl + (size_t)l*3*DD*DD, pqkv, M_TOK, 3*DD, DD);
        rope_kernel<<<(M_TOK*NHH*32 + 255)/256, 256>>>();
        flash5_kernel<<<dim3(SS/128, NHH, BB), 256, FLASH_SMEM>>>();
        gemm_bf<1><<<dim3((DD+127)/128, M_TOK/128), 256>>>(patth, pattl,
            pwoh + (size_t)l*DD*DD, pwol + (size_t)l*DD*DD, px, M_TOK, DD, DD);
        router_kernel<<<M_TOK/4, 128>>>(router + (size_t)l*DD);
        topk_kernel<<<BB, 1024>>>();
        gather_rmsnorm_kernel<<<M_SEL, 128>>>(mlp_norm + (size_t)l*DD);
        gemm_bf<3><<<dim3((2*FFF+127)/128, (M_SEL+127)/128), 256>>>(phsh, phsl,
            pwguh + (size_t)l*2*FFF*DD, pwgul + (size_t)l*2*FFF*DD, px /*unused*/, M_SEL, 2*FFF, DD);
        gemm_bf<2><<<dim3((DD+127)/128, (M_SEL+127)/128), 256>>>(pgah, pgal,
            pwdh + (size_t)l*DD*FFF, pwdl + (size_t)l*DD*FFF, px, M_SEL, DD, FFF);
    }
    rmsnorm_f32_kernel<<<M_TOK, 128>>>(px, fnorm, (float*)d_out);
}

// round 8
// speedup vs baseline: 3.6988x; 1.1946x over previous
#include <cuda_runtime.h>
#include <cuda_fp16.h>
#include <math.h>
#include <stdint.h>

#define BB 8
#define SS 2048
#define DD 320
#define NHH 5
#define HDD 64
#define FFF 864
#define NLL 6
#define KSEL 1638
#define M_TOK (BB*SS)      // 16384
#define M_SEL (BB*KSEL)    // 13104
#define EPSF 1e-6f

// ---------------- scratch (static device globals; no allocation) ----------------
__device__ float g_x[M_TOK*DD];
__device__ float g_qkv[M_TOK*3*DD];
__device__ float g_probs[M_TOK];
__device__ int   g_tidx[M_SEL];
__device__ float g_tp[M_SEL];
__device__ float g_cos[SS*32];
__device__ float g_sin[SS*32];

// fp16 split activation buffers (A-side: h + l)
__device__ __half g_hh[M_TOK*DD],  g_hl[M_TOK*DD];      // rmsnorm out (qkv A)
__device__ __half g_atth[M_TOK*DD], g_attl[M_TOK*DD];   // attention out (wo A)
__device__ __half g_hsh[M_SEL*DD], g_hsl[M_SEL*DD];     // gathered norm (gate/up A)
__device__ __half g_gah[(size_t)M_SEL*FFF], g_gal[(size_t)M_SEL*FFF]; // silu*up (down A)
// q split (A of QK^T), k/v single (B-side)  [B,NH,S,HD], q pre-scaled
__device__ __half g_qh[M_TOK*DD], g_ql[M_TOK*DD];
__device__ __half g_kh[M_TOK*DD];
__device__ __half g_vh[M_TOK*DD];
// fp16 weights (B-side: single)
__device__ __half g_wqkv[NLL*3*DD*DD];
__device__ __half g_wo[NLL*DD*DD];
__device__ __half g_wgu[NLL*2*FFF*DD];   // interleaved: row 2i=gate_i, 2i+1=up_i
__device__ __half g_wd[NLL*DD*FFF];

__device__ __forceinline__ void split2h(float x, __half& h, __half& l) {
    h = __float2half_rn(x);
    l = __float2half_rn(x - __half2float(h));
}
__device__ __forceinline__ void split_pack_h(float x, float y, uint32_t& hp, uint32_t& lp) {
    __half hx = __float2half_rn(x), hy = __float2half_rn(y);
    __half lx = __float2half_rn(x - __half2float(hx));
    __half ly = __float2half_rn(y - __half2float(hy));
    __half2 h2 = __halves2half2(hx, hy);
    __half2 l2 = __halves2half2(lx, ly);
    hp = *reinterpret_cast<uint32_t*>(&h2);
    lp = *reinterpret_cast<uint32_t*>(&l2);
}

// ---------------- weight rounding (B-side: single fp16) ----------------
__global__ void roundh_kernel(const float* __restrict__ src, __half* __restrict__ dst, int n) {
    int i = blockIdx.x*blockDim.x + threadIdx.x;
    if (i >= n) return;
    dst[i] = __float2half_rn(src[i]);
}
// interleave gate/up: src row i of layer -> dst row 2i+which
__global__ void round_gu_kernel(const float* __restrict__ src, __half* __restrict__ dst, int which) {
    int i = blockIdx.x*blockDim.x + threadIdx.x;
    if (i >= NLL*FFF*DD) return;
    int lay = i / (FFF*DD), rem = i % (FFF*DD);
    int r = rem / DD, d = rem % DD;
    size_t dsto = (size_t)lay*2*FFF*DD + (size_t)(2*r + which)*DD + d;
    dst[dsto] = __float2half_rn(src[i]);
}

// ---------------- rope tables ----------------
__global__ void rope_table_kernel() {
    int i = blockIdx.x*blockDim.x + threadIdx.x;
    if (i >= SS*32) return;
    int s = i / 32, d = i % 32;
    double freq = exp(-((double)(2*d)/64.0)*log(10000.0));
    double f = (double)s * freq;
    g_cos[i] = (float)cos(f);
    g_sin[i] = (float)sin(f);
}

// ---------------- embed ----------------
__global__ void embed_kernel(const int* __restrict__ ids, const int* __restrict__ iter,
                             const float* __restrict__ emb, const float* __restrict__ iter_emb) {
    int i = blockIdx.x*blockDim.x + threadIdx.x;
    if (i >= M_TOK*DD) return;
    int t = i / DD, d = i % DD;
    float v = emb[(size_t)ids[t]*DD + d];
    int it = iter[0];
    if (it < 8) v += iter_emb[(size_t)it*DD + d];
    g_x[i] = v;
}

// ---------------- rmsnorm variants ----------------
__global__ void rmsnorm_f32_kernel(const float* __restrict__ X, const float* __restrict__ w,
                                   float* __restrict__ Y) {
    int t = blockIdx.x;
    const float* xr = X + (size_t)t*DD;
    float ss = 0.f;
    for (int d = threadIdx.x; d < DD; d += 128) { float v = xr[d]; ss += v*v; }
    #pragma unroll
    for (int o = 16; o > 0; o >>= 1) ss += __shfl_xor_sync(0xffffffffu, ss, o);
    __shared__ float red[4];
    if ((threadIdx.x & 31) == 0) red[threadIdx.x >> 5] = ss;
    __syncthreads();
    float tot = red[0]+red[1]+red[2]+red[3];
    float sc = rsqrtf(tot*(1.f/DD) + EPSF);
    for (int d = threadIdx.x; d < DD; d += 128) Y[(size_t)t*DD + d] = w[d]*xr[d]*sc;
}

__global__ void rmsnorm_split_kernel(const float* __restrict__ X, const float* __restrict__ w,
                                     __half* __restrict__ Yh, __half* __restrict__ Yl) {
    int t = blockIdx.x;
    const float* xr = X + (size_t)t*DD;
    float ss = 0.f;
    for (int d = threadIdx.x; d < DD; d += 128) { float v = xr[d]; ss += v*v; }
    #pragma unroll
    for (int o = 16; o > 0; o >>= 1) ss += __shfl_xor_sync(0xffffffffu, ss, o);
    __shared__ float red[4];
    if ((threadIdx.x & 31) == 0) red[threadIdx.x >> 5] = ss;
    __syncthreads();
    float tot = red[0]+red[1]+red[2]+red[3];
    float sc = rsqrtf(tot*(1.f/DD) + EPSF);
    for (int d = threadIdx.x; d < DD; d += 128) {
        float y = w[d]*xr[d]*sc;
        split2h(y, Yh[(size_t)t*DD + d], Yl[(size_t)t*DD + d]);
    }
}

// ================= tensor-core GEMM (fp16 2-term, double-buffered) =================
__device__ __forceinline__ void ldsm_x4(uint32_t* r, const __half* p) {
    uint32_t addr = (uint32_t)__cvta_generic_to_shared(p);
    asm volatile("ldmatrix.sync.aligned.m8n8.x4.shared.b16 {%0,%1,%2,%3}, [%4];"
                 : "=r"(r[0]), "=r"(r[1]), "=r"(r[2]), "=r"(r[3]) : "r"(addr));
}
__device__ __forceinline__ void ldsm_x4_t(uint32_t* r, const __half* p) {
    uint32_t addr = (uint32_t)__cvta_generic_to_shared(p);
    asm volatile("ldmatrix.sync.aligned.m8n8.x4.trans.shared.b16 {%0,%1,%2,%3}, [%4];"
                 : "=r"(r[0]), "=r"(r[1]), "=r"(r[2]), "=r"(r[3]) : "r"(addr));
}
__device__ __forceinline__ void mma_f16(float* c, const uint32_t* a, uint32_t b0, uint32_t b1) {
    asm volatile(
        "mma.sync.aligned.m16n8k16.row.col.f32.f16.f16.f32 "
        "{%0,%1,%2,%3}, {%4,%5,%6,%7}, {%8,%9}, {%0,%1,%2,%3};\n"
        : "+f"(c[0]), "+f"(c[1]), "+f"(c[2]), "+f"(c[3])
        : "r"(a[0]), "r"(a[1]), "r"(a[2]), "r"(a[3]), "r"(b0), "r"(b1));
}

#define LDSTR 24
#define STAGE (3*128*LDSTR)   // one stage: Ah | Al | B, each 128xLDSTR halves

// MODE: 0 = store C, 1 = accumulate into C, 2 = scatter-add into x (C = g_x base),
// MODE: 3 = fused silu(gate)*up -> split fp16 into g_gah/g_gal (C unused)
template<int MODE>
__global__ void __launch_bounds__(256) gemm_hf(const __half* __restrict__ Ah, const __half* __restrict__ Al,
                                               const __half* __restrict__ Bm,
                                               float* __restrict__ C, int M, int N, int K) {
    __shared__ __half sm[2*STAGE];

    int tid = threadIdx.x;
    int lane = tid & 31, wid = tid >> 5;
    int wm = (wid & 1) * 64;
    int wn = (wid >> 1) * 32;
    int row0 = blockIdx.y * 128, col0 = blockIdx.x * 128;

    int srow = tid >> 1;
    int scol = (tid & 1) * 8;
    size_t aoffg = (size_t)(row0 + srow) * K + scol;
    size_t boffg = (size_t)(col0 + srow) * K + scol;
    bool aval = (row0 + srow) < M;
    bool bval = (col0 + srow) < N;
    int sput = srow*LDSTR + scol;

    float acc[4][4][4];
    #pragma unroll
    for (int i = 0; i < 4; i++)
        #pragma unroll
        for (int j = 0; j < 4; j++)
            #pragma unroll
            for (int r = 0; r < 4; r++) acc[i][j][r] = 0.f;

    int a_r = lane & 15;
    int a_c = ((lane >> 4) & 1) * 8;
    int b_r = (lane & 7) + ((lane >> 4) & 1) * 8;
    int b_c = ((lane >> 3) & 1) * 8;
    int aoff[4], boff[2];
    #pragma unroll
    for (int mt = 0; mt < 4; mt++) aoff[mt] = (wm + mt*16 + a_r)*LDSTR + a_c;
    #pragma unroll
    for (int pr = 0; pr < 2; pr++) boff[pr] = (wn + pr*16 + b_r)*LDSTR + b_c;

    const uint4 uz = make_uint4(0,0,0,0);
    uint4 rAh, rAl, rB;
    rAh = aval ? *(const uint4*)(Ah + aoffg) : uz;
    rAl = aval ? *(const uint4*)(Al + aoffg) : uz;
    rB  = bval ? *(const uint4*)(Bm + boffg) : uz;

    *(uint4*)&sm[0*STAGE + 0*128*LDSTR + sput] = rAh;
    *(uint4*)&sm[0*STAGE + 1*128*LDSTR + sput] = rAl;
    *(uint4*)&sm[0*STAGE + 2*128*LDSTR + sput] = rB;
    __syncthreads();

    int nk = K >> 4;
    for (int ks = 0; ks < nk; ks++) {
        int cur = ks & 1;
        if (ks + 1 < nk) {
            int k0 = (ks + 1) << 4;
            rAh = aval ? *(const uint4*)(Ah + aoffg + k0) : uz;
            rAl = aval ? *(const uint4*)(Al + aoffg + k0) : uz;
            rB  = bval ? *(const uint4*)(Bm + boffg + k0) : uz;
        }
        const __half* cAh = sm + cur*STAGE;
        const __half* cAl = cAh + 128*LDSTR;
        const __half* cB  = cAh + 2*128*LDSTR;

        uint32_t fAh[4][4], fAl[4][4], fB[2][4];
        #pragma unroll
        for (int mt = 0; mt < 4; mt++) { ldsm_x4(fAh[mt], cAh + aoff[mt]); ldsm_x4(fAl[mt], cAl + aoff[mt]); }
        #pragma unroll
        for (int pr = 0; pr < 2; pr++) ldsm_x4(fB[pr], cB + boff[pr]);

        #pragma unroll
        for (int mt = 0; mt < 4; mt++)
            #pragma unroll
            for (int nt = 0; nt < 4; nt++)
                mma_f16(acc[mt][nt], fAh[mt], fB[nt>>1][(nt&1)*2], fB[nt>>1][(nt&1)*2+1]);
        #pragma unroll
        for (int mt = 0; mt < 4; mt++)
            #pragma unroll
            for (int nt = 0; nt < 4; nt++)
                mma_f16(acc[mt][nt], fAl[mt], fB[nt>>1][(nt&1)*2], fB[nt>>1][(nt&1)*2+1]);

        if (ks + 1 < nk) {
            __half* nx = sm + (cur^1)*STAGE;
            *(uint4*)&nx[0*128*LDSTR + sput] = rAh;
            *(uint4*)&nx[1*128*LDSTR + sput] = rAl;
            *(uint4*)&nx[2*128*LDSTR + sput] = rB;
        }
        __syncthreads();
    }

    int erow = lane >> 2;
    int ecol = (lane & 3) * 2;
    #pragma unroll
    for (int mt = 0; mt < 4; mt++) {
        #pragma unroll
        for (int nt = 0; nt < 4; nt++) {
            int r = row0 + wm + mt*16 + erow;
            int c = col0 + wn + nt*8 + ecol;
            if (c < N) {
                if (MODE == 3) {
                    size_t i0 = (size_t)(c >> 1);   // c even: (gate, up) pair for ff index c/2
                    if (r < M) {
                        float g = acc[mt][nt][0], u = acc[mt][nt][1];
                        float v = g * (1.f/(1.f + __expf(-g))) * u;
                        split2h(v, g_gah[(size_t)r*FFF + i0], g_gal[(size_t)r*FFF + i0]);
                    }
                    if (r + 8 < M) {
                        float g = acc[mt][nt][2], u = acc[mt][nt][3];
                        float v = g * (1.f/(1.f + __expf(-g))) * u;
                        split2h(v, g_gah[(size_t)(r+8)*FFF + i0], g_gal[(size_t)(r+8)*FFF + i0]);
                    }
                } else if (MODE == 2) {
                    if (r < M) {
                        int b = r / KSEL;
                        int tok = g_tidx[r];
                        float p = g_tp[r];
                        float2* ptr = (float2*)&C[((size_t)b*SS + tok)*DD + c];
                        float2 o = *ptr; o.x += acc[mt][nt][0]*p; o.y += acc[mt][nt][1]*p; *ptr = o;
                    }
                    if (r + 8 < M) {
                        int r8 = r + 8;
                        int b = r8 / KSEL;
                        int tok = g_tidx[r8];
                        float p = g_tp[r8];
                        float2* ptr = (float2*)&C[((size_t)b*SS + tok)*DD + c];
                        float2 o = *ptr; o.x += acc[mt][nt][2]*p; o.y += acc[mt][nt][3]*p; *ptr = o;
                    }
                } else {
                    if (r < M) {
                        float2* p = (float2*)&C[(size_t)r*N + c];
                        if (MODE == 1) { float2 o = *p; o.x += acc[mt][nt][0]; o.y += acc[mt][nt][1]; *p = o; }
                        else { float2 o; o.x = acc[mt][nt][0]; o.y = acc[mt][nt][1]; *p = o; }
                    }
                    if (r + 8 < M) {
                        float2* p = (float2*)&C[(size_t)(r+8)*N + c];
                        if (MODE == 1) { float2 o = *p; o.x += acc[mt][nt][2]; o.y += acc[mt][nt][3]; *p = o; }
                        else { float2 o; o.x = acc[mt][nt][2]; o.y = acc[mt][nt][3]; *p = o; }
                    }
                }
            }
        }
    }
}

// ---------------- rope + split/round to fp16 [B,NH,S,HD] ----------------
__global__ void rope_kernel() {
    int i = blockIdx.x*blockDim.x + threadIdx.x;
    if (i >= M_TOK*NHH*32) return;
    int t = i / (NHH*32);
    int r = i % (NHH*32);
    int h = r / 32, d = r % 32;
    int b = t / SS, s = t % SS;
    const float* base = g_qkv + (size_t)t*(3*DD) + h*HDD;
    float c = g_cos[s*32+d], sn = g_sin[s*32+d];
    float q1 = base[d],        q2 = base[d+32];
    float k1 = base[DD+d],     k2 = base[DD+d+32];
    size_t o = ((size_t)(b*NHH+h)*SS + s)*HDD;
    float qa  = (q1*c - q2*sn)*0.125f;
    float qb2 = (q2*c + q1*sn)*0.125f;
    float ka = k1*c - k2*sn;
    float kb = k2*c + k1*sn;
    split2h(qa,  g_qh[o+d],    g_ql[o+d]);
    split2h(qb2, g_qh[o+d+32], g_ql[o+d+32]);
    g_kh[o+d]    = __float2half_rn(ka);
    g_kh[o+d+32] = __float2half_rn(kb);
    g_vh[o+d]    = __float2half_rn(base[2*DD+d]);
    g_vh[o+d+32] = __float2half_rn(base[2*DD+d+32]);
}

// ---------------- flash attention v6: fp16 2-term, 128q x 64k, 256 thr, cp.async ----
#define ASTR 72
#define QHALVES (128*ASTR)             // per Q array
#define KVOFF (2*QHALVES)              // start of K/V stages (in halves)
__device__ __forceinline__ void cpa16(uint32_t saddr, const void* g) {
    asm volatile("cp.async.cg.shared.global [%0], [%1], 16;" :: "r"(saddr), "l"(g));
}

__global__ void __launch_bounds__(256) flash6_kernel() {
    extern __shared__ __half sb[];
    __half* Qh = sb;
    __half* Ql = sb + QHALVES;
    uint32_t smem_u32 = (uint32_t)__cvta_generic_to_shared(sb);

    int b = blockIdx.z, hh = blockIdx.y;
    int qb = (int)(gridDim.x - 1u - blockIdx.x);   // heavy first
    int tid = threadIdx.x, lane = tid & 31, w = tid >> 5;
    size_t headoff = ((size_t)(b*NHH+hh)*SS)*HDD;
    const __half *Qhp = g_qh + headoff, *Qlp = g_ql + headoff;
    const __half* srcs[2] = {g_kh + headoff, g_vh + headoff};

    // load Q tile (128 x 64): 1024 uint4 per array, 4 per thread
    {
        #pragma unroll
        for (int i = 0; i < 4; i++) {
            int idx = i*256 + tid;
            int rr = idx >> 3, c = (idx & 7) * 8;
            *(uint4*)&Qh[rr*ASTR + c] = *(const uint4*)&Qhp[(size_t)(qb*128 + rr)*64 + c];
            *(uint4*)&Ql[rr*ASTR + c] = *(const uint4*)&Qlp[(size_t)(qb*128 + rr)*64 + c];
        }
    }
    // issue K/V tile 0 into stage 0 (1024 uint4 over 256 threads)
    {
        #pragma unroll
        for (int i = 0; i < 4; i++) {
            int u = i*256 + tid;
            int a = u >> 9, rem = u & 511;
            int row = rem >> 3, col = (rem & 7) * 8;
            uint32_t sa = smem_u32 + (uint32_t)(KVOFF + (a*64 + row)*ASTR + col)*2;
            cpa16(sa, srcs[a] + (size_t)row*64 + col);
        }
        asm volatile("cp.async.commit_group;");
    }
    asm volatile("cp.async.wait_group 0;");
    __syncthreads();

    int m0 = w * 16;
    int a_r = lane & 15;
    int a_c = ((lane >> 4) & 1) * 8;
    int b_r = (lane & 7) + ((lane >> 4) & 1) * 8;
    int b_c = ((lane >> 3) & 1) * 8;
    int v_r = ((lane >> 3) & 1) * 8 + (lane & 7);
    int v_c = ((lane >> 4) & 1) * 8;

    float O[8][4];
    float mrow[2] = {-1e30f, -1e30f};
    float lrow[2] = {0.f, 0.f};
    #pragma unroll
    for (int nt = 0; nt < 8; nt++)
        #pragma unroll
        for (int r = 0; r < 4; r++) O[nt][r] = 0.f;

    int ntiles = 2*qb + 2;
    for (int kt = 0; kt < ntiles; kt++) {
        int cur = kt & 1;
        if (kt + 1 < ntiles) {
            int st = cur ^ 1;
            #pragma unroll
            for (int i = 0; i < 4; i++) {
                int u = i*256 + tid;
                int a = u >> 9, rem = u & 511;
                int row = rem >> 3, col = (rem & 7) * 8;
                uint32_t sa = smem_u32 + (uint32_t)(KVOFF + ((2*st + a)*64 + row)*ASTR + col)*2;
                cpa16(sa, srcs[a] + (size_t)((kt+1)*64 + row)*64 + col);
            }
            asm volatile("cp.async.commit_group;");
        }
        const __half* Kt = sb + KVOFF + (2*cur)*64*ASTR;
        const __half* Vt = Kt + 64*ASTR;

        // ---- S = Q K^T (2-term) ----
        float s[8][4];
        #pragma unroll
        for (int nt = 0; nt < 8; nt++)
            #pragma unroll
            for (int r = 0; r < 4; r++) s[nt][r] = 0.f;
        #pragma unroll
        for (int kk = 0; kk < 4; kk++) {
            uint32_t QAh[4], QAl[4];
            ldsm_x4(QAh, Qh + (m0 + a_r)*ASTR + kk*16 + a_c);
            ldsm_x4(QAl, Ql + (m0 + a_r)*ASTR + kk*16 + a_c);
            #pragma unroll
            for (int bn = 0; bn < 4; bn++) {
                uint32_t KB[4];
                ldsm_x4(KB, Kt + (bn*16 + b_r)*ASTR + kk*16 + b_c);
                mma_f16(s[2*bn],   QAh, KB[0], KB[1]);
                mma_f16(s[2*bn+1], QAh, KB[2], KB[3]);
                mma_f16(s[2*bn],   QAl, KB[0], KB[1]);
                mma_f16(s[2*bn+1], QAl, KB[2], KB[3]);
            }
        }
        // ---- causal mask on diagonal band (last two k-tiles) ----
        if (kt >= 2*qb) {
            int r0l = m0 + (lane >> 2);
            int c0l = (kt - 2*qb)*64 + 2*(lane & 3);
            #pragma unroll
            for (int nt = 0; nt < 8; nt++) {
                int c = nt*8 + c0l;
                if (c     > r0l)     s[nt][0] = -1e30f;
                if (c + 1 > r0l)     s[nt][1] = -1e30f;
                if (c     > r0l + 8) s[nt][2] = -1e30f;
                if (c + 1 > r0l + 8) s[nt][3] = -1e30f;
            }
        }
        // ---- online softmax ----
        float rm0 = -1e30f, rm1 = -1e30f;
        #pragma unroll
        for (int nt = 0; nt < 8; nt++) {
            rm0 = fmaxf(rm0, fmaxf(s[nt][0], s[nt][1]));
            rm1 = fmaxf(rm1, fmaxf(s[nt][2], s[nt][3]));
        }
        rm0 = fmaxf(rm0, __shfl_xor_sync(0xffffffffu, rm0, 1));
        rm0 = fmaxf(rm0, __shfl_xor_sync(0xffffffffu, rm0, 2));
        rm1 = fmaxf(rm1, __shfl_xor_sync(0xffffffffu, rm1, 1));
        rm1 = fmaxf(rm1, __shfl_xor_sync(0xffffffffu, rm1, 2));
        float mn0 = fmaxf(mrow[0], rm0), mn1 = fmaxf(mrow[1], rm1);
        float cc0 = __expf(mrow[0] - mn0), cc1 = __expf(mrow[1] - mn1);
        mrow[0] = mn0; mrow[1] = mn1;
        float rs0 = 0.f, rs1 = 0.f;
        #pragma unroll
        for (int nt = 0; nt < 8; nt++) {
            s[nt][0] = __expf(s[nt][0] - mn0); rs0 += s[nt][0];
            s[nt][1] = __expf(s[nt][1] - mn0); rs0 += s[nt][1];
            s[nt][2] = __expf(s[nt][2] - mn1); rs1 += s[nt][2];
            s[nt][3] = __expf(s[nt][3] - mn1); rs1 += s[nt][3];
        }
        rs0 += __shfl_xor_sync(0xffffffffu, rs0, 1);
        rs0 += __shfl_xor_sync(0xffffffffu, rs0, 2);
        rs1 += __shfl_xor_sync(0xffffffffu, rs1, 1);
        rs1 += __shfl_xor_sync(0xffffffffu, rs1, 2);
        lrow[0] = lrow[0]*cc0 + rs0;
        lrow[1] = lrow[1]*cc1 + rs1;
        #pragma unroll
        for (int nt = 0; nt < 8; nt++) {
            O[nt][0] *= cc0; O[nt][1] *= cc0;
            O[nt][2] *= cc1; O[nt][3] *= cc1;
        }
        // ---- O += P V (P split fp16, V single) ----
        #pragma unroll
        for (int kk = 0; kk < 4; kk++) {
            uint32_t Ph[4], Pl[4];
            split_pack_h(s[2*kk][0],   s[2*kk][1],   Ph[0], Pl[0]);
            split_pack_h(s[2*kk][2],   s[2*kk][3],   Ph[1], Pl[1]);
            split_pack_h(s[2*kk+1][0], s[2*kk+1][1], Ph[2], Pl[2]);
            split_pack_h(s[2*kk+1][2], s[2*kk+1][3], Ph[3], Pl[3]);
            #pragma unroll
            for (int bn = 0; bn < 4; bn++) {
                uint32_t VB[4];
                ldsm_x4_t(VB, Vt + (kk*16 + v_r)*ASTR + bn*16 + v_c);
                mma_f16(O[2*bn],   Ph, VB[0], VB[1]);
                mma_f16(O[2*bn+1], Ph, VB[2], VB[3]);
                mma_f16(O[2*bn],   Pl, VB[0], VB[1]);
                mma_f16(O[2*bn+1], Pl, VB[2], VB[3]);
            }
        }
        asm volatile("cp.async.wait_group 0;");
        __syncthreads();
    }
    // epilogue: write att h/l (fp16)
    float inv0 = 1.f/lrow[0], inv1 = 1.f/lrow[1];
    int row0 = qb*128 + m0 + (lane >> 2);
    int row1 = row0 + 8;
    #pragma unroll
    for (int nt = 0; nt < 8; nt++) {
        int col = hh*64 + nt*8 + 2*(lane & 3);
        size_t o0 = ((size_t)b*SS + row0)*DD + col;
        size_t o1 = ((size_t)b*SS + row1)*DD + col;
        uint32_t hp, lp;
        split_pack_h(O[nt][0]*inv0, O[nt][1]*inv0, hp, lp);
        *(uint32_t*)&g_atth[o0] = hp;
        *(uint32_t*)&g_attl[o0] = lp;
        split_pack_h(O[nt][2]*inv1, O[nt][3]*inv1, hp, lp);
        *(uint32_t*)&g_atth[o1] = hp;
        *(uint32_t*)&g_attl[o1] = lp;
    }
}
#define FLASH_SMEM ((2*128 + 4*64)*ASTR*2)   // 73728 bytes

// ---------------- router ----------------
__global__ void router_kernel(const float* __restrict__ rw) {
    int t = blockIdx.x*4 + (threadIdx.x >> 5);
    int lane = threadIdx.x & 31;
    const float* xr = g_x + (size_t)t*DD;
    float s = 0.f;
    for (int d = lane; d < DD; d += 32) s += xr[d]*rw[d];
    #pragma unroll
    for (int o = 16; o > 0; o >>= 1) s += __shfl_xor_sync(0xffffffffu, s, o);
    if (lane == 0) g_probs[t] = 1.f/(1.f + __expf(-s));
}

// ---------------- per-batch top-k via bitonic sort ----------------
__global__ void topk_kernel() {
    __shared__ float sv[2048];
    __shared__ int   si[2048];
    int bb = blockIdx.x;
    for (int i = threadIdx.x; i < 2048; i += 1024) { sv[i] = g_probs[(size_t)bb*SS + i]; si[i] = i; }
    __syncthreads();
    for (int k = 2; k <= 2048; k <<= 1) {
        for (int j = k >> 1; j > 0; j >>= 1) {
            for (int t = threadIdx.x; t < 2048; t += 1024) {
                int ixj = t ^ j;
                if (ixj > t) {
                    bool desc = ((t & k) == 0);
                    float a = sv[t], b2 = sv[ixj];
                    bool sw = desc ? (a < b2) : (a > b2);
                    if (sw) {
                        sv[t] = b2; sv[ixj] = a;
                        int tmp = si[t]; si[t] = si[ixj]; si[ixj] = tmp;
                    }
                }
            }
            __syncthreads();
        }
    }
    for (int i = threadIdx.x; i < KSEL; i += 1024) {
        g_tidx[(size_t)bb*KSEL + i] = si[i];
        g_tp[(size_t)bb*KSEL + i]   = sv[i];
    }
}

// ---------------- gather + rmsnorm (split out) ----------------
__global__ void gather_rmsnorm_kernel(const float* __restrict__ w) {
    int i = blockIdx.x;
    int b = i / KSEL;
    int tok = g_tidx[i];
    const float* xr = g_x + ((size_t)b*SS + tok)*DD;
    float ss = 0.f;
    for (int d = threadIdx.x; d < DD; d += 128) { float v = xr[d]; ss += v*v; }
    #pragma unroll
    for (int o = 16; o > 0; o >>= 1) ss += __shfl_xor_sync(0xffffffffu, ss, o);
    __shared__ float red[4];
    if ((threadIdx.x & 31) == 0) red[threadIdx.x >> 5] = ss;
    __syncthreads();
    float tot = red[0]+red[1]+red[2]+red[3];
    float sc = rsqrtf(tot*(1.f/DD) + EPSF);
    for (int d = threadIdx.x; d < DD; d += 128) {
        float y = w[d]*xr[d]*sc;
        split2h(y, g_hsh[(size_t)i*DD + d], g_hsl[(size_t)i*DD + d]);
    }
}

// ---------------- host orchestration ----------------
extern "C" void kernel_launch(void* const* d_in, const int* in_sizes, int n_in,
                              void* d_out, int out_size) {
    const int*   ids       = (const int*)d_in[0];
    const int*   iter      = (const int*)d_in[1];
    const float* emb       = (const float*)d_in[2];
    const float* iter_emb  = (const float*)d_in[3];
    const float* attn_norm = (const float*)d_in[4];
    const float* Wqkv      = (const float*)d_in[5];
    const float* wo        = (const float*)d_in[6];
    const float* router    = (const float*)d_in[7];
    const float* mlp_norm  = (const float*)d_in[8];
    const float* gate_w    = (const float*)d_in[9];
    const float* up_w      = (const float*)d_in[10];
    const float* down_w    = (const float*)d_in[11];
    const float* fnorm     = (const float*)d_in[12];

    float *px, *pqkv;
    __half *phh, *phl, *patth, *pattl, *phsh, *phsl, *pgah, *pgal;
    __half *pwqkv, *pwo, *pwgu, *pwd;
    cudaGetSymbolAddress((void**)&px,    g_x);
    cudaGetSymbolAddress((void**)&pqkv,  g_qkv);
    cudaGetSymbolAddress((void**)&phh,   g_hh);
    cudaGetSymbolAddress((void**)&phl,   g_hl);
    cudaGetSymbolAddress((void**)&patth, g_atth);
    cudaGetSymbolAddress((void**)&pattl, g_attl);
    cudaGetSymbolAddress((void**)&phsh,  g_hsh);
    cudaGetSymbolAddress((void**)&phsl,  g_hsl);
    cudaGetSymbolAddress((void**)&pgah,  g_gah);
    cudaGetSymbolAddress((void**)&pgal,  g_gal);
    cudaGetSymbolAddress((void**)&pwqkv, g_wqkv);
    cudaGetSymbolAddress((void**)&pwo,   g_wo);
    cudaGetSymbolAddress((void**)&pwgu,  g_wgu);
    cudaGetSymbolAddress((void**)&pwd,   g_wd);

    cudaFuncSetAttribute(flash6_kernel, cudaFuncAttributeMaxDynamicSharedMemorySize, FLASH_SMEM);

    rope_table_kernel<<<(SS*32 + 255)/256, 256>>>();
    embed_kernel<<<(M_TOK*DD + 255)/256, 256>>>(ids, iter, emb, iter_emb);
    roundh_kernel<<<(NLL*3*DD*DD + 255)/256, 256>>>(Wqkv, pwqkv, NLL*3*DD*DD);
    roundh_kernel<<<(NLL*DD*DD + 255)/256, 256>>>(wo, pwo, NLL*DD*DD);
    round_gu_kernel<<<(NLL*FFF*DD + 255)/256, 256>>>(gate_w, pwgu, 0);
    round_gu_kernel<<<(NLL*FFF*DD + 255)/256, 256>>>(up_w,   pwgu, 1);
    roundh_kernel<<<(NLL*DD*FFF + 255)/256, 256>>>(down_w, pwd, NLL*DD*FFF);

    for (int l = 0; l < NLL; l++) {
        rmsnorm_split_kernel<<<M_TOK, 128>>>(px, attn_norm + (size_t)l*DD, phh, phl);
        gemm_hf<0><<<dim3((3*DD+127)/128, M_TOK/128), 256>>>(phh, phl,
            pwqkv + (size_t)l*3*DD*DD, pqkv, M_TOK, 3*DD, DD);
        rope_kernel<<<(M_TOK*NHH*32 + 255)/256, 256>>>();
        flash6_kernel<<<dim3(SS/128, NHH, BB), 256, FLASH_SMEM>>>();
        gemm_hf<1><<<dim3((DD+127)/128, M_TOK/128), 256>>>(patth, pattl,
            pwo + (size_t)l*DD*DD, px, M_TOK, DD, DD);
        router_kernel<<<M_TOK/4, 128>>>(router + (size_t)l*DD);
        topk_kernel<<<BB, 1024>>>();
        gather_rmsnorm_kernel<<<M_SEL, 128>>>(mlp_norm + (size_t)l*DD);
        gemm_hf<3><<<dim3((2*FFF+127)/128, (M_SEL+127)/128), 256>>>(phsh, phsl,
            pwgu + (size_t)l*2*FFF*DD, px /*unused*/, M_SEL, 2*FFF, DD);
        gemm_hf<2><<<dim3((DD+127)/128, (M_SEL+127)/128), 256>>>(pgah, pgal,
            pwd + (size_t)l*DD*FFF, px, M_SEL, DD, FFF);
    }
    rmsnorm_f32_kernel<<<M_TOK, 128>>>(px, fnorm, (float*)d_out);
}

// round 11
// speedup vs baseline: 4.3163x; 1.1669x over previous
#include <cuda_runtime.h>
#include <cuda_fp16.h>
#include <math.h>
#include <stdint.h>

#define BB 8
#define SS 2048
#define DD 320
#define NHH 5
#define HDD 64
#define FFF 864
#define NLL 6
#define KSEL 1638
#define M_TOK (BB*SS)      // 16384
#define M_SEL (BB*KSEL)    // 13104
#define EPSF 1e-6f

// ---------------- scratch (static device globals; no allocation) ----------------
__device__ float g_x[M_TOK*DD];
__device__ float g_qkv[M_TOK*3*DD];
__device__ float g_probs[M_TOK];
__device__ int   g_tidx[M_SEL];
__device__ float g_tp[M_SEL];
__device__ float g_cos[SS*32];
__device__ float g_sin[SS*32];

// fp16 split activation buffers (A-side: h + l)
__device__ __half g_hh[M_TOK*DD],  g_hl[M_TOK*DD];      // rmsnorm out (qkv A)
__device__ __half g_atth[M_TOK*DD], g_attl[M_TOK*DD];   // attention out (wo A)
__device__ __half g_hsh[M_SEL*DD], g_hsl[M_SEL*DD];     // gathered norm (gate/up A)
__device__ __half g_gah[(size_t)M_SEL*FFF], g_gal[(size_t)M_SEL*FFF]; // silu*up (down A)
// q split (A of QK^T), k/v single (B-side)  [B,NH,S,HD], q pre-scaled
__device__ __half g_qh[M_TOK*DD], g_ql[M_TOK*DD];
__device__ __half g_kh[M_TOK*DD];
__device__ __half g_vh[M_TOK*DD];
// fp16 weights (B-side: single)
__device__ __half g_wqkv[NLL*3*DD*DD];
__device__ __half g_wo[NLL*DD*DD];
__device__ __half g_wgu[NLL*2*FFF*DD];   // interleaved: row 2i=gate_i, 2i+1=up_i
__device__ __half g_wd[NLL*DD*FFF];

__device__ __forceinline__ void split2h(float x, __half& h, __half& l) {
    h = __float2half_rn(x);
    l = __float2half_rn(x - __half2float(h));
}
__device__ __forceinline__ void split_pack_h(float x, float y, uint32_t& hp, uint32_t& lp) {
    __half hx = __float2half_rn(x), hy = __float2half_rn(y);
    __half lx = __float2half_rn(x - __half2float(hx));
    __half ly = __float2half_rn(y - __half2float(hy));
    __half2 h2 = __halves2half2(hx, hy);
    __half2 l2 = __halves2half2(lx, ly);
    hp = *reinterpret_cast<uint32_t*>(&h2);
    lp = *reinterpret_cast<uint32_t*>(&l2);
}

// ---------------- weight rounding (B-side: single fp16) ----------------
__global__ void roundh_kernel(const float* __restrict__ src, __half* __restrict__ dst, int n) {
    int i = blockIdx.x*blockDim.x + threadIdx.x;
    if (i >= n) return;
    dst[i] = __float2half_rn(src[i]);
}
// interleave gate/up: src row i of layer -> dst row 2i+which
__global__ void round_gu_kernel(const float* __restrict__ src, __half* __restrict__ dst, int which) {
    int i = blockIdx.x*blockDim.x + threadIdx.x;
    if (i >= NLL*FFF*DD) return;
    int lay = i / (FFF*DD), rem = i % (FFF*DD);
    int r = rem / DD, d = rem % DD;
    size_t dsto = (size_t)lay*2*FFF*DD + (size_t)(2*r + which)*DD + d;
    dst[dsto] = __float2half_rn(src[i]);
}

// ---------------- rope tables ----------------
__global__ void rope_table_kernel() {
    int i = blockIdx.x*blockDim.x + threadIdx.x;
    if (i >= SS*32) return;
    int s = i / 32, d = i % 32;
    double freq = exp(-((double)(2*d)/64.0)*log(10000.0));
    double f = (double)s * freq;
    g_cos[i] = (float)cos(f);
    g_sin[i] = (float)sin(f);
}

// ---------------- embed ----------------
__global__ void embed_kernel(const int* __restrict__ ids, const int* __restrict__ iter,
                             const float* __restrict__ emb, const float* __restrict__ iter_emb) {
    int i = blockIdx.x*blockDim.x + threadIdx.x;
    if (i >= M_TOK*DD) return;
    int t = i / DD, d = i % DD;
    float v = emb[(size_t)ids[t]*DD + d];
    int it = iter[0];
    if (it < 8) v += iter_emb[(size_t)it*DD + d];
    g_x[i] = v;
}

// ---------------- rmsnorm variants ----------------
__global__ void rmsnorm_f32_kernel(const float* __restrict__ X, const float* __restrict__ w,
                                   float* __restrict__ Y) {
    int t = blockIdx.x;
    const float* xr = X + (size_t)t*DD;
    float ss = 0.f;
    for (int d = threadIdx.x; d < DD; d += 128) { float v = xr[d]; ss += v*v; }
    #pragma unroll
    for (int o = 16; o > 0; o >>= 1) ss += __shfl_xor_sync(0xffffffffu, ss, o);
    __shared__ float red[4];
    if ((threadIdx.x & 31) == 0) red[threadIdx.x >> 5] = ss;
    __syncthreads();
    float tot = red[0]+red[1]+red[2]+red[3];
    float sc = rsqrtf(tot*(1.f/DD) + EPSF);
    for (int d = threadIdx.x; d < DD; d += 128) Y[(size_t)t*DD + d] = w[d]*xr[d]*sc;
}

__global__ void rmsnorm_split_kernel(const float* __restrict__ X, const float* __restrict__ w,
                                     __half* __restrict__ Yh, __half* __restrict__ Yl) {
    int t = blockIdx.x;
    const float* xr = X + (size_t)t*DD;
    float ss = 0.f;
    for (int d = threadIdx.x; d < DD; d += 128) { float v = xr[d]; ss += v*v; }
    #pragma unroll
    for (int o = 16; o > 0; o >>= 1) ss += __shfl_xor_sync(0xffffffffu, ss, o);
    __shared__ float red[4];
    if ((threadIdx.x & 31) == 0) red[threadIdx.x >> 5] = ss;
    __syncthreads();
    float tot = red[0]+red[1]+red[2]+red[3];
    float sc = rsqrtf(tot*(1.f/DD) + EPSF);
    for (int d = threadIdx.x; d < DD; d += 128) {
        float y = w[d]*xr[d]*sc;
        split2h(y, Yh[(size_t)t*DD + d], Yl[(size_t)t*DD + d]);
    }
}

// ================= PTX helpers =================
__device__ __forceinline__ void ldsm_x4(uint32_t* r, const __half* p) {
    uint32_t addr = (uint32_t)__cvta_generic_to_shared(p);
    asm volatile("ldmatrix.sync.aligned.m8n8.x4.shared.b16 {%0,%1,%2,%3}, [%4];"
                 : "=r"(r[0]), "=r"(r[1]), "=r"(r[2]), "=r"(r[3]) : "r"(addr));
}
__device__ __forceinline__ void ldsm_x4_t(uint32_t* r, const __half* p) {
    uint32_t addr = (uint32_t)__cvta_generic_to_shared(p);
    asm volatile("ldmatrix.sync.aligned.m8n8.x4.trans.shared.b16 {%0,%1,%2,%3}, [%4];"
                 : "=r"(r[0]), "=r"(r[1]), "=r"(r[2]), "=r"(r[3]) : "r"(addr));
}
__device__ __forceinline__ void mma_f16(float* c, const uint32_t* a, uint32_t b0, uint32_t b1) {
    asm volatile(
        "mma.sync.aligned.m16n8k16.row.col.f32.f16.f16.f32 "
        "{%0,%1,%2,%3}, {%4,%5,%6,%7}, {%8,%9}, {%0,%1,%2,%3};\n"
        : "+f"(c[0]), "+f"(c[1]), "+f"(c[2]), "+f"(c[3])
        : "r"(a[0]), "r"(a[1]), "r"(a[2]), "r"(a[3]), "r"(b0), "r"(b1));
}
__device__ __forceinline__ void cpa16(uint32_t saddr, const void* g) {
    asm volatile("cp.async.cg.shared.global [%0], [%1], 16;" :: "r"(saddr), "l"(g));
}

// ================= tensor-core GEMM (fp16 2-term, 3-stage cp.async pipeline) ==========
// per stage: Ah | Al | B, each 128 rows x 32 halves (stride 40), 30720 bytes
#define GS_STR 40
#define GS_ARR (128*GS_STR)            // halves per array
#define GS_STAGE (3*GS_ARR)            // halves per stage
#define GS_BYTES (GS_STAGE*2)          // 30720
#define GSMEM (3*GS_BYTES)             // 92160

// MODE: 0 = store C, 1 = accumulate into C, 2 = scatter-add into x (C = g_x base),
// MODE: 3 = fused silu(gate)*up -> split fp16 into g_gah/g_gal (C unused)
template<int MODE>
__global__ void __launch_bounds__(256) gemm_hf(const __half* __restrict__ Ah, const __half* __restrict__ Al,
                                               const __half* __restrict__ Bm,
                                               float* __restrict__ C, int M, int N, int K) {
    extern __shared__ __half sm[];
    uint32_t smem_u32 = (uint32_t)__cvta_generic_to_shared(sm);

    int tid = threadIdx.x;
    int lane = tid & 31, wid = tid >> 5;
    int wm = (wid & 1) * 64;
    int wn = (wid >> 1) * 32;
    int row0 = blockIdx.y * 128, col0 = blockIdx.x * 128;

    float acc[4][4][4];
    #pragma unroll
    for (int i = 0; i < 4; i++)
        #pragma unroll
        for (int j = 0; j < 4; j++)
            #pragma unroll
            for (int r = 0; r < 4; r++) acc[i][j][r] = 0.f;

    int a_r = lane & 15;
    int a_c = ((lane >> 4) & 1) * 8;
    int b_r = (lane & 7) + ((lane >> 4) & 1) * 8;
    int b_c = ((lane >> 3) & 1) * 8;
    int aoff[4], boff[2];
    #pragma unroll
    for (int mt = 0; mt < 4; mt++) aoff[mt] = (wm + mt*16 + a_r)*GS_STR + a_c;
    #pragma unroll
    for (int pr = 0; pr < 2; pr++) boff[pr] = (wn + pr*16 + b_r)*GS_STR + b_c;

    // cp.async loader: 1536 16B units per stage, 6 per thread
    #define G_LOAD(cc, st) do {                                                   \
        uint32_t stg_ = smem_u32 + (uint32_t)(st)*GS_BYTES;                       \
        int k0_ = (cc) << 5;                                                      \
        _Pragma("unroll")                                                         \
        for (int i_ = 0; i_ < 6; i_++) {                                          \
            int u_ = i_*256 + tid;                                                \
            int arr_ = u_ >> 9, rem_ = u_ & 511;                                  \
            int row_ = rem_ >> 2, cb_ = (rem_ & 3) << 3;                          \
            uint32_t dst_ = stg_ + (uint32_t)(arr_*GS_ARR + row_*GS_STR + cb_)*2; \
            if (arr_ < 2) {                                                       \
                if (row0 + row_ < M) {                                            \
                    const __half* s_ = (arr_ ? Al : Ah) +                         \
                        (size_t)(row0 + row_)*K + k0_ + cb_;                      \
                    cpa16(dst_, s_);                                              \
                }                                                                 \
            } else {                                                              \
                if (col0 + row_ < N) {                                            \
                    const __half* s_ = Bm + (size_t)(col0 + row_)*K + k0_ + cb_;  \
                    cpa16(dst_, s_);                                              \
                }                                                                 \
            }                                                                     \
        }                                                                         \
        asm volatile("cp.async.commit_group;" ::: "memory");                      \
    } while (0)

    int nch = K >> 5;
    // prologue: 2 chunks in flight
    G_LOAD(0, 0);
    if (nch > 1) G_LOAD(1, 1);
    else asm volatile("cp.async.commit_group;" ::: "memory");

    for (int c = 0; c < nch; c++) {
        asm volatile("cp.async.wait_group 1;" ::: "memory");
        __syncthreads();
        // issue chunk c+2 into stage (c+2)%3 (that stage was consumed at iter c-1)
        if (c + 2 < nch) G_LOAD(c + 2, (c + 2) % 3);
        else asm volatile("cp.async.commit_group;" ::: "memory");

        const __half* cAh = sm + (c % 3)*GS_STAGE;
        const __half* cAl = cAh + GS_ARR;
        const __half* cB  = cAh + 2*GS_ARR;
        #pragma unroll
        for (int j = 0; j < 2; j++) {
            int kc = j*16;
            uint32_t fAh[4][4], fAl[4][4], fB[2][4];
            #pragma unroll
            for (int mt = 0; mt < 4; mt++) {
                ldsm_x4(fAh[mt], cAh + aoff[mt] + kc);
                ldsm_x4(fAl[mt], cAl + aoff[mt] + kc);
            }
            #pragma unroll
            for (int pr = 0; pr < 2; pr++) ldsm_x4(fB[pr], cB + boff[pr] + kc);

            #pragma unroll
            for (int mt = 0; mt < 4; mt++)
                #pragma unroll
                for (int nt = 0; nt < 4; nt++)
                    mma_f16(acc[mt][nt], fAh[mt], fB[nt>>1][(nt&1)*2], fB[nt>>1][(nt&1)*2+1]);
            #pragma unroll
            for (int mt = 0; mt < 4; mt++)
                #pragma unroll
                for (int nt = 0; nt < 4; nt++)
                    mma_f16(acc[mt][nt], fAl[mt], fB[nt>>1][(nt&1)*2], fB[nt>>1][(nt&1)*2+1]);
        }
    }
    #undef G_LOAD

    int erow = lane >> 2;
    int ecol = (lane & 3) * 2;
    #pragma unroll
    for (int mt = 0; mt < 4; mt++) {
        #pragma unroll
        for (int nt = 0; nt < 4; nt++) {
            int r = row0 + wm + mt*16 + erow;
            int c = col0 + wn + nt*8 + ecol;
            if (c < N) {
                if (MODE == 3) {
                    size_t i0 = (size_t)(c >> 1);   // c even: (gate, up) pair for ff index c/2
                    if (r < M) {
                        float g = acc[mt][nt][0], u = acc[mt][nt][1];
                        float v = g * (1.f/(1.f + __expf(-g))) * u;
                        split2h(v, g_gah[(size_t)r*FFF + i0], g_gal[(size_t)r*FFF + i0]);
                    }
                    if (r + 8 < M) {
                        float g = acc[mt][nt][2], u = acc[mt][nt][3];
                        float v = g * (1.f/(1.f + __expf(-g))) * u;
                        split2h(v, g_gah[(size_t)(r+8)*FFF + i0], g_gal[(size_t)(r+8)*FFF + i0]);
                    }
                } else if (MODE == 2) {
                    if (r < M) {
                        int b = r / KSEL;
                        int tok = g_tidx[r];
                        float p = g_tp[r];
                        float2* ptr = (float2*)&C[((size_t)b*SS + tok)*DD + c];
                        float2 o = *ptr; o.x += acc[mt][nt][0]*p; o.y += acc[mt][nt][1]*p; *ptr = o;
                    }
                    if (r + 8 < M) {
                        int r8 = r + 8;
                        int b = r8 / KSEL;
                        int tok = g_tidx[r8];
                        float p = g_tp[r8];
                        float2* ptr = (float2*)&C[((size_t)b*SS + tok)*DD + c];
                        float2 o = *ptr; o.x += acc[mt][nt][2]*p; o.y += acc[mt][nt][3]*p; *ptr = o;
                    }
                } else {
                    if (r < M) {
                        float2* p = (float2*)&C[(size_t)r*N + c];
                        if (MODE == 1) { float2 o = *p; o.x += acc[mt][nt][0]; o.y += acc[mt][nt][1]; *p = o; }
                        else { float2 o; o.x = acc[mt][nt][0]; o.y = acc[mt][nt][1]; *p = o; }
                    }
                    if (r + 8 < M) {
                        float2* p = (float2*)&C[(size_t)(r+8)*N + c];
                        if (MODE == 1) { float2 o = *p; o.x += acc[mt][nt][2]; o.y += acc[mt][nt][3]; *p = o; }
                        else { float2 o; o.x = acc[mt][nt][2]; o.y = acc[mt][nt][3]; *p = o; }
                    }
                }
            }
        }
    }
}

// ---------------- rope + split/round to fp16 [B,NH,S,HD] ----------------
__global__ void rope_kernel() {
    int i = blockIdx.x*blockDim.x + threadIdx.x;
    if (i >= M_TOK*NHH*32) return;
    int t = i / (NHH*32);
    int r = i % (NHH*32);
    int h = r / 32, d = r % 32;
    int b = t / SS, s = t % SS;
    const float* base = g_qkv + (size_t)t*(3*DD) + h*HDD;
    float c = g_cos[s*32+d], sn = g_sin[s*32+d];
    float q1 = base[d],        q2 = base[d+32];
    float k1 = base[DD+d],     k2 = base[DD+d+32];
    size_t o = ((size_t)(b*NHH+h)*SS + s)*HDD;
    float qa  = (q1*c - q2*sn)*0.125f;
    float qb2 = (q2*c + q1*sn)*0.125f;
    float ka = k1*c - k2*sn;
    float kb = k2*c + k1*sn;
    split2h(qa,  g_qh[o+d],    g_ql[o+d]);
    split2h(qb2, g_qh[o+d+32], g_ql[o+d+32]);
    g_kh[o+d]    = __float2half_rn(ka);
    g_kh[o+d+32] = __float2half_rn(kb);
    g_vh[o+d]    = __float2half_rn(base[2*DD+d]);
    g_vh[o+d+32] = __float2half_rn(base[2*DD+d+32]);
}

// ---------------- flash attention v6: fp16 2-term, 128q x 64k, 256 thr, cp.async ----
#define ASTR 72
#define QHALVES (128*ASTR)             // per Q array
#define KVOFF (2*QHALVES)              // start of K/V stages (in halves)

__global__ void __launch_bounds__(256) flash6_kernel() {
    extern __shared__ __half sb[];
    __half* Qh = sb;
    __half* Ql = sb + QHALVES;
    uint32_t smem_u32 = (uint32_t)__cvta_generic_to_shared(sb);

    int b = blockIdx.z, hh = blockIdx.y;
    int qb = (int)(gridDim.x - 1u - blockIdx.x);   // heavy first
    int tid = threadIdx.x, lane = tid & 31, w = tid >> 5;
    size_t headoff = ((size_t)(b*NHH+hh)*SS)*HDD;
    const __half *Qhp = g_qh + headoff, *Qlp = g_ql + headoff;
    const __half* srcs[2] = {g_kh + headoff, g_vh + headoff};

    {
        #pragma unroll
        for (int i = 0; i < 4; i++) {
            int idx = i*256 + tid;
            int rr = idx >> 3, c = (idx & 7) * 8;
            *(uint4*)&Qh[rr*ASTR + c] = *(const uint4*)&Qhp[(size_t)(qb*128 + rr)*64 + c];
            *(uint4*)&Ql[rr*ASTR + c] = *(const uint4*)&Qlp[(size_t)(qb*128 + rr)*64 + c];
        }
    }
    {
        #pragma unroll
        for (int i = 0; i < 4; i++) {
            int u = i*256 + tid;
            int a = u >> 9, rem = u & 511;
            int row = rem >> 3, col = (rem & 7) * 8;
            uint32_t sa = smem_u32 + (uint32_t)(KVOFF + (a*64 + row)*ASTR + col)*2;
            cpa16(sa, srcs[a] + (size_t)row*64 + col);
        }
        asm volatile("cp.async.commit_group;");
    }
    asm volatile("cp.async.wait_group 0;");
    __syncthreads();

    int m0 = w * 16;
    int a_r = lane & 15;
    int a_c = ((lane >> 4) & 1) * 8;
    int b_r = (lane & 7) + ((lane >> 4) & 1) * 8;
    int b_c = ((lane >> 3) & 1) * 8;
    int v_r = ((lane >> 3) & 1) * 8 + (lane & 7);
    int v_c = ((lane >> 4) & 1) * 8;

    float O[8][4];
    float mrow[2] = {-1e30f, -1e30f};
    float lrow[2] = {0.f, 0.f};
    #pragma unroll
    for (int nt = 0; nt < 8; nt++)
        #pragma unroll
        for (int r = 0; r < 4; r++) O[nt][r] = 0.f;

    int ntiles = 2*qb + 2;
    for (int kt = 0; kt < ntiles; kt++) {
        int cur = kt & 1;
        if (kt + 1 < ntiles) {
            int st = cur ^ 1;
            #pragma unroll
            for (int i = 0; i < 4; i++) {
                int u = i*256 + tid;
                int a = u >> 9, rem = u & 511;
                int row = rem >> 3, col = (rem & 7) * 8;
                uint32_t sa = smem_u32 + (uint32_t)(KVOFF + ((2*st + a)*64 + row)*ASTR + col)*2;
                cpa16(sa, srcs[a] + (size_t)((kt+1)*64 + row)*64 + col);
            }
            asm volatile("cp.async.commit_group;");
        }
        const __half* Kt = sb + KVOFF + (2*cur)*64*ASTR;
        const __half* Vt = Kt + 64*ASTR;

        float s[8][4];
        #pragma unroll
        for (int nt = 0; nt < 8; nt++)
            #pragma unroll
            for (int r = 0; r < 4; r++) s[nt][r] = 0.f;
        #pragma unroll
        for (int kk = 0; kk < 4; kk++) {
            uint32_t QAh[4], QAl[4];
            ldsm_x4(QAh, Qh + (m0 + a_r)*ASTR + kk*16 + a_c);
            ldsm_x4(QAl, Ql + (m0 + a_r)*ASTR + kk*16 + a_c);
            #pragma unroll
            for (int bn = 0; bn < 4; bn++) {
                uint32_t KB[4];
                ldsm_x4(KB, Kt + (bn*16 + b_r)*ASTR + kk*16 + b_c);
                mma_f16(s[2*bn],   QAh, KB[0], KB[1]);
                mma_f16(s[2*bn+1], QAh, KB[2], KB[3]);
                mma_f16(s[2*bn],   QAl, KB[0], KB[1]);
                mma_f16(s[2*bn+1], QAl, KB[2], KB[3]);
            }
        }
        if (kt >= 2*qb) {
            int r0l = m0 + (lane >> 2);
            int c0l = (kt - 2*qb)*64 + 2*(lane & 3);
            #pragma unroll
            for (int nt = 0; nt < 8; nt++) {
                int c = nt*8 + c0l;
                if (c     > r0l)     s[nt][0] = -1e30f;
                if (c + 1 > r0l)     s[nt][1] = -1e30f;
                if (c     > r0l + 8) s[nt][2] = -1e30f;
                if (c + 1 > r0l + 8) s[nt][3] = -1e30f;
            }
        }
        float rm0 = -1e30f, rm1 = -1e30f;
        #pragma unroll
        for (int nt = 0; nt < 8; nt++) {
            rm0 = fmaxf(rm0, fmaxf(s[nt][0], s[nt][1]));
            rm1 = fmaxf(rm1, fmaxf(s[nt][2], s[nt][3]));
        }
        rm0 = fmaxf(rm0, __shfl_xor_sync(0xffffffffu, rm0, 1));
        rm0 = fmaxf(rm0, __shfl_xor_sync(0xffffffffu, rm0, 2));
        rm1 = fmaxf(rm1, __shfl_xor_sync(0xffffffffu, rm1, 1));
        rm1 = fmaxf(rm1, __shfl_xor_sync(0xffffffffu, rm1, 2));
        float mn0 = fmaxf(mrow[0], rm0), mn1 = fmaxf(mrow[1], rm1);
        float cc0 = __expf(mrow[0] - mn0), cc1 = __expf(mrow[1] - mn1);
        mrow[0] = mn0; mrow[1] = mn1;
        float rs0 = 0.f, rs1 = 0.f;
        #pragma unroll
        for (int nt = 0; nt < 8; nt++) {
            s[nt][0] = __expf(s[nt][0] - mn0); rs0 += s[nt][0];
            s[nt][1] = __expf(s[nt][1] - mn0); rs0 += s[nt][1];
            s[nt][2] = __expf(s[nt][2] - mn1); rs1 += s[nt][2];
            s[nt][3] = __expf(s[nt][3] - mn1); rs1 += s[nt][3];
        }
        rs0 += __shfl_xor_sync(0xffffffffu, rs0, 1);
        rs0 += __shfl_xor_sync(0xffffffffu, rs0, 2);
        rs1 += __shfl_xor_sync(0xffffffffu, rs1, 1);
        rs1 += __shfl_xor_sync(0xffffffffu, rs1, 2);
        lrow[0] = lrow[0]*cc0 + rs0;
        lrow[1] = lrow[1]*cc1 + rs1;
        #pragma unroll
        for (int nt = 0; nt < 8; nt++) {
            O[nt][0] *= cc0; O[nt][1] *= cc0;
            O[nt][2] *= cc1; O[nt][3] *= cc1;
        }
        #pragma unroll
        for (int kk = 0; kk < 4; kk++) {
            uint32_t Ph[4], Pl[4];
            split_pack_h(s[2*kk][0],   s[2*kk][1],   Ph[0], Pl[0]);
            split_pack_h(s[2*kk][2],   s[2*kk][3],   Ph[1], Pl[1]);
            split_pack_h(s[2*kk+1][0], s[2*kk+1][1], Ph[2], Pl[2]);
            split_pack_h(s[2*kk+1][2], s[2*kk+1][3], Ph[3], Pl[3]);
            #pragma unroll
            for (int bn = 0; bn < 4; bn++) {
                uint32_t VB[4];
                ldsm_x4_t(VB, Vt + (kk*16 + v_r)*ASTR + bn*16 + v_c);
                mma_f16(O[2*bn],   Ph, VB[0], VB[1]);
                mma_f16(O[2*bn+1], Ph, VB[2], VB[3]);
                mma_f16(O[2*bn],   Pl, VB[0], VB[1]);
                mma_f16(O[2*bn+1], Pl, VB[2], VB[3]);
            }
        }
        asm volatile("cp.async.wait_group 0;");
        __syncthreads();
    }
    float inv0 = 1.f/lrow[0], inv1 = 1.f/lrow[1];
    int row0 = qb*128 + m0 + (lane >> 2);
    int row1 = row0 + 8;
    #pragma unroll
    for (int nt = 0; nt < 8; nt++) {
        int col = hh*64 + nt*8 + 2*(lane & 3);
        size_t o0 = ((size_t)b*SS + row0)*DD + col;
        size_t o1 = ((size_t)b*SS + row1)*DD + col;
        uint32_t hp, lp;
        split_pack_h(O[nt][0]*inv0, O[nt][1]*inv0, hp, lp);
        *(uint32_t*)&g_atth[o0] = hp;
        *(uint32_t*)&g_attl[o0] = lp;
        split_pack_h(O[nt][2]*inv1, O[nt][3]*inv1, hp, lp);
        *(uint32_t*)&g_atth[o1] = hp;
        *(uint32_t*)&g_attl[o1] = lp;
    }
}
#define FLASH_SMEM ((2*128 + 4*64)*ASTR*2)   // 73728 bytes

// ---------------- router ----------------
__global__ void router_kernel(const float* __restrict__ rw) {
    int t = blockIdx.x*4 + (threadIdx.x >> 5);
    int lane = threadIdx.x & 31;
    const float* xr = g_x + (size_t)t*DD;
    float s = 0.f;
    for (int d = lane; d < DD; d += 32) s += xr[d]*rw[d];
    #pragma unroll
    for (int o = 16; o > 0; o >>= 1) s += __shfl_xor_sync(0xffffffffu, s, o);
    if (lane == 0) g_probs[t] = 1.f/(1.f + __expf(-s));
}

// ---------------- per-batch top-k via bitonic sort ----------------
__global__ void topk_kernel() {
    __shared__ float sv[2048];
    __shared__ int   si[2048];
    int bb = blockIdx.x;
    for (int i = threadIdx.x; i < 2048; i += 1024) { sv[i] = g_probs[(size_t)bb*SS + i]; si[i] = i; }
    __syncthreads();
    for (int k = 2; k <= 2048; k <<= 1) {
        for (int j = k >> 1; j > 0; j >>= 1) {
            for (int t = threadIdx.x; t < 2048; t += 1024) {
                int ixj = t ^ j;
                if (ixj > t) {
                    bool desc = ((t & k) == 0);
                    float a = sv[t], b2 = sv[ixj];
                    bool sw = desc ? (a < b2) : (a > b2);
                    if (sw) {
                        sv[t] = b2; sv[ixj] = a;
                        int tmp = si[t]; si[t] = si[ixj]; si[ixj] = tmp;
                    }
                }
            }
            __syncthreads();
        }
    }
    for (int i = threadIdx.x; i < KSEL; i += 1024) {
        g_tidx[(size_t)bb*KSEL + i] = si[i];
        g_tp[(size_t)bb*KSEL + i]   = sv[i];
    }
}

// ---------------- gather + rmsnorm (split out) ----------------
__global__ void gather_rmsnorm_kernel(const float* __restrict__ w) {
    int i = blockIdx.x;
    int b = i / KSEL;
    int tok = g_tidx[i];
    const float* xr = g_x + ((size_t)b*SS + tok)*DD;
    float ss = 0.f;
    for (int d = threadIdx.x; d < DD; d += 128) { float v = xr[d]; ss += v*v; }
    #pragma unroll
    for (int o = 16; o > 0; o >>= 1) ss += __shfl_xor_sync(0xffffffffu, ss, o);
    __shared__ float red[4];
    if ((threadIdx.x & 31) == 0) red[threadIdx.x >> 5] = ss;
    __syncthreads();
    float tot = red[0]+red[1]+red[2]+red[3];
    float sc = rsqrtf(tot*(1.f/DD) + EPSF);
    for (int d = threadIdx.x; d < DD; d += 128) {
        float y = w[d]*xr[d]*sc;
        split2h(y, g_hsh[(size_t)i*DD + d], g_hsl[(size_t)i*DD + d]);
    }
}

// ---------------- host orchestration ----------------
extern "C" void kernel_launch(void* const* d_in, const int* in_sizes, int n_in,
                              void* d_out, int out_size) {
    const int*   ids       = (const int*)d_in[0];
    const int*   iter      = (const int*)d_in[1];
    const float* emb       = (const float*)d_in[2];
    const float* iter_emb  = (const float*)d_in[3];
    const float* attn_norm = (const float*)d_in[4];
    const float* Wqkv      = (const float*)d_in[5];
    const float* wo        = (const float*)d_in[6];
    const float* router    = (const float*)d_in[7];
    const float* mlp_norm  = (const float*)d_in[8];
    const float* gate_w    = (const float*)d_in[9];
    const float* up_w      = (const float*)d_in[10];
    const float* down_w    = (const float*)d_in[11];
    const float* fnorm     = (const float*)d_in[12];

    float *px, *pqkv;
    __half *phh, *phl, *patth, *pattl, *phsh, *phsl, *pgah, *pgal;
    __half *pwqkv, *pwo, *pwgu, *pwd;
    cudaGetSymbolAddress((void**)&px,    g_x);
    cudaGetSymbolAddress((void**)&pqkv,  g_qkv);
    cudaGetSymbolAddress((void**)&phh,   g_hh);
    cudaGetSymbolAddress((void**)&phl,   g_hl);
    cudaGetSymbolAddress((void**)&patth, g_atth);
    cudaGetSymbolAddress((void**)&pattl, g_attl);
    cudaGetSymbolAddress((void**)&phsh,  g_hsh);
    cudaGetSymbolAddress((void**)&phsl,  g_hsl);
    cudaGetSymbolAddress((void**)&pgah,  g_gah);
    cudaGetSymbolAddress((void**)&pgal,  g_gal);
    cudaGetSymbolAddress((void**)&pwqkv, g_wqkv);
    cudaGetSymbolAddress((void**)&pwo,   g_wo);
    cudaGetSymbolAddress((void**)&pwgu,  g_wgu);
    cudaGetSymbolAddress((void**)&pwd,   g_wd);

    cudaFuncSetAttribute(flash6_kernel, cudaFuncAttributeMaxDynamicSharedMemorySize, FLASH_SMEM);
    cudaFuncSetAttribute(gemm_hf<0>, cudaFuncAttributeMaxDynamicSharedMemorySize, GSMEM);
    cudaFuncSetAttribute(gemm_hf<1>, cudaFuncAttributeMaxDynamicSharedMemorySize, GSMEM);
    cudaFuncSetAttribute(gemm_hf<2>, cudaFuncAttributeMaxDynamicSharedMemorySize, GSMEM);
    cudaFuncSetAttribute(gemm_hf<3>, cudaFuncAttributeMaxDynamicSharedMemorySize, GSMEM);

    rope_table_kernel<<<(SS*32 + 255)/256, 256>>>();
    embed_kernel<<<(M_TOK*DD + 255)/256, 256>>>(ids, iter, emb, iter_emb);
    roundh_kernel<<<(NLL*3*DD*DD + 255)/256, 256>>>(Wqkv, pwqkv, NLL*3*DD*DD);
    roundh_kernel<<<(NLL*DD*DD + 255)/256, 256>>>(wo, pwo, NLL*DD*DD);
    round_gu_kernel<<<(NLL*FFF*DD + 255)/256, 256>>>(gate_w, pwgu, 0);
    round_gu_kernel<<<(NLL*FFF*DD + 255)/256, 256>>>(up_w,   pwgu, 1);
    roundh_kernel<<<(NLL*DD*FFF + 255)/256, 256>>>(down_w, pwd, NLL*DD*FFF);

    for (int l = 0; l < NLL; l++) {
        rmsnorm_split_kernel<<<M_TOK, 128>>>(px, attn_norm + (size_t)l*DD, phh, phl);
        gemm_hf<0><<<dim3((3*DD+127)/128, M_TOK/128), 256, GSMEM>>>(phh, phl,
            pwqkv + (size_t)l*3*DD*DD, pqkv, M_TOK, 3*DD, DD);
        rope_kernel<<<(M_TOK*NHH*32 + 255)/256, 256>>>();
        flash6_kernel<<<dim3(SS/128, NHH, BB), 256, FLASH_SMEM>>>();
        gemm_hf<1><<<dim3((DD+127)/128, M_TOK/128), 256, GSMEM>>>(patth, pattl,
            pwo + (size_t)l*DD*DD, px, M_TOK, DD, DD);
        router_kernel<<<M_TOK/4, 128>>>(router + (size_t)l*DD);
        topk_kernel<<<BB, 1024>>>();
        gather_rmsnorm_kernel<<<M_SEL, 128>>>(mlp_norm + (size_t)l*DD);
        gemm_hf<3><<<dim3((2*FFF+127)/128, (M_SEL+127)/128), 256, GSMEM>>>(phsh, phsl,
            pwgu + (size_t)l*2*FFF*DD, px /*unused*/, M_SEL, 2*FFF, DD);
        gemm_hf<2><<<dim3((DD+127)/128, (M_SEL+127)/128), 256, GSMEM>>>(pgah, pgal,
            pwd + (size_t)l*DD*FFF, px, M_SEL, DD, FFF);
    }
    rmsnorm_f32_kernel<<<M_TOK, 128>>>(px, fnorm, (float*)d_out);
}

// round 13
// speedup vs baseline: 4.6779x; 1.0838x over previous
#include <cuda_runtime.h>
#include <cuda_fp16.h>
#include <math.h>
#include <stdint.h>

#define BB 8
#define SS 2048
#define DD 320
#define NHH 5
#define HDD 64
#define FFF 864
#define NLL 6
#define KSEL 1638
#define M_TOK (BB*SS)      // 16384
#define M_SEL (BB*KSEL)    // 13104
#define EPSF 1e-6f

// ---------------- scratch (static device globals; no allocation) ----------------
__device__ float g_x[M_TOK*DD];
__device__ float g_qkv[M_TOK*3*DD];
__device__ float g_probs[M_TOK];
__device__ int   g_tidx[M_SEL];
__device__ float g_tp[M_SEL];
__device__ float g_cos[SS*32];
__device__ float g_sin[SS*32];

// fp16 split activation buffers (A-side: h + l)
__device__ __half g_hh[M_TOK*DD],  g_hl[M_TOK*DD];      // rmsnorm out (qkv A)
__device__ __half g_atth[M_TOK*DD], g_attl[M_TOK*DD];   // attention out (wo A)
__device__ __half g_hsh[M_SEL*DD], g_hsl[M_SEL*DD];     // gathered norm (gate/up A)
__device__ __half g_gah[(size_t)M_SEL*FFF], g_gal[(size_t)M_SEL*FFF]; // silu*up (down A)
// q split (A of QK^T), k/v single (B-side)  [B,NH,S,HD], q pre-scaled
__device__ __half g_qh[M_TOK*DD], g_ql[M_TOK*DD];
__device__ __half g_kh[M_TOK*DD];
__device__ __half g_vh[M_TOK*DD];
// fp16 weights (B-side: single)
__device__ __half g_wqkv[NLL*3*DD*DD];
__device__ __half g_wo[NLL*DD*DD];
__device__ __half g_wgu[NLL*2*FFF*DD];   // interleaved: row 2i=gate_i, 2i+1=up_i
__device__ __half g_wd[NLL*DD*FFF];

__device__ __forceinline__ void split2h(float x, __half& h, __half& l) {
    h = __float2half_rn(x);
    l = __float2half_rn(x - __half2float(h));
}
__device__ __forceinline__ void split_pack_h(float x, float y, uint32_t& hp, uint32_t& lp) {
    __half hx = __float2half_rn(x), hy = __float2half_rn(y);
    __half lx = __float2half_rn(x - __half2float(hx));
    __half ly = __float2half_rn(y - __half2float(hy));
    __half2 h2 = __halves2half2(hx, hy);
    __half2 l2 = __halves2half2(lx, ly);
    hp = *reinterpret_cast<uint32_t*>(&h2);
    lp = *reinterpret_cast<uint32_t*>(&l2);
}
__device__ __forceinline__ uint32_t pack_h2(float x, float y) {
    __half2 h = __halves2half2(__float2half_rn(x), __float2half_rn(y));
    return *reinterpret_cast<uint32_t*>(&h);
}

// ---------------- weight rounding (B-side: single fp16) ----------------
__global__ void roundh_kernel(const float* __restrict__ src, __half* __restrict__ dst, int n) {
    int i = blockIdx.x*blockDim.x + threadIdx.x;
    if (i >= n) return;
    dst[i] = __float2half_rn(src[i]);
}
// interleave gate/up: src row i of layer -> dst row 2i+which
__global__ void round_gu_kernel(const float* __restrict__ src, __half* __restrict__ dst, int which) {
    int i = blockIdx.x*blockDim.x + threadIdx.x;
    if (i >= NLL*FFF*DD) return;
    int lay = i / (FFF*DD), rem = i % (FFF*DD);
    int r = rem / DD, d = rem % DD;
    size_t dsto = (size_t)lay*2*FFF*DD + (size_t)(2*r + which)*DD + d;
    dst[dsto] = __float2half_rn(src[i]);
}

// ---------------- rope tables ----------------
__global__ void rope_table_kernel() {
    int i = blockIdx.x*blockDim.x + threadIdx.x;
    if (i >= SS*32) return;
    int s = i / 32, d = i % 32;
    double freq = exp(-((double)(2*d)/64.0)*log(10000.0));
    double f = (double)s * freq;
    g_cos[i] = (float)cos(f);
    g_sin[i] = (float)sin(f);
}

// ---------------- embed ----------------
__global__ void embed_kernel(const int* __restrict__ ids, const int* __restrict__ iter,
                             const float* __restrict__ emb, const float* __restrict__ iter_emb) {
    int i = blockIdx.x*blockDim.x + threadIdx.x;
    if (i >= M_TOK*DD) return;
    int t = i / DD, d = i % DD;
    float v = emb[(size_t)ids[t]*DD + d];
    int it = iter[0];
    if (it < 8) v += iter_emb[(size_t)it*DD + d];
    g_x[i] = v;
}

// ---------------- rmsnorm variants ----------------
__global__ void rmsnorm_f32_kernel(const float* __restrict__ X, const float* __restrict__ w,
                                   float* __restrict__ Y) {
    int t = blockIdx.x;
    const float* xr = X + (size_t)t*DD;
    float ss = 0.f;
    for (int d = threadIdx.x; d < DD; d += 128) { float v = xr[d]; ss += v*v; }
    #pragma unroll
    for (int o = 16; o > 0; o >>= 1) ss += __shfl_xor_sync(0xffffffffu, ss, o);
    __shared__ float red[4];
    if ((threadIdx.x & 31) == 0) red[threadIdx.x >> 5] = ss;
    __syncthreads();
    float tot = red[0]+red[1]+red[2]+red[3];
    float sc = rsqrtf(tot*(1.f/DD) + EPSF);
    for (int d = threadIdx.x; d < DD; d += 128) Y[(size_t)t*DD + d] = w[d]*xr[d]*sc;
}

__global__ void rmsnorm_split_kernel(const float* __restrict__ X, const float* __restrict__ w,
                                     __half* __restrict__ Yh, __half* __restrict__ Yl) {
    int t = blockIdx.x;
    const float* xr = X + (size_t)t*DD;
    float ss = 0.f;
    for (int d = threadIdx.x; d < DD; d += 128) { float v = xr[d]; ss += v*v; }
    #pragma unroll
    for (int o = 16; o > 0; o >>= 1) ss += __shfl_xor_sync(0xffffffffu, ss, o);
    __shared__ float red[4];
    if ((threadIdx.x & 31) == 0) red[threadIdx.x >> 5] = ss;
    __syncthreads();
    float tot = red[0]+red[1]+red[2]+red[3];
    float sc = rsqrtf(tot*(1.f/DD) + EPSF);
    for (int d = threadIdx.x; d < DD; d += 128) {
        float y = w[d]*xr[d]*sc;
        split2h(y, Yh[(size_t)t*DD + d], Yl[(size_t)t*DD + d]);
    }
}

// ================= PTX helpers =================
__device__ __forceinline__ void ldsm_x4(uint32_t* r, const __half* p) {
    uint32_t addr = (uint32_t)__cvta_generic_to_shared(p);
    asm volatile("ldmatrix.sync.aligned.m8n8.x4.shared.b16 {%0,%1,%2,%3}, [%4];"
                 : "=r"(r[0]), "=r"(r[1]), "=r"(r[2]), "=r"(r[3]) : "r"(addr));
}
__device__ __forceinline__ void ldsm_x4_t(uint32_t* r, const __half* p) {
    uint32_t addr = (uint32_t)__cvta_generic_to_shared(p);
    asm volatile("ldmatrix.sync.aligned.m8n8.x4.trans.shared.b16 {%0,%1,%2,%3}, [%4];"
                 : "=r"(r[0]), "=r"(r[1]), "=r"(r[2]), "=r"(r[3]) : "r"(addr));
}
__device__ __forceinline__ void mma_f16(float* c, const uint32_t* a, uint32_t b0, uint32_t b1) {
    asm volatile(
        "mma.sync.aligned.m16n8k16.row.col.f32.f16.f16.f32 "
        "{%0,%1,%2,%3}, {%4,%5,%6,%7}, {%8,%9}, {%0,%1,%2,%3};\n"
        : "+f"(c[0]), "+f"(c[1]), "+f"(c[2]), "+f"(c[3])
        : "r"(a[0]), "r"(a[1]), "r"(a[2]), "r"(a[3]), "r"(b0), "r"(b1));
}
__device__ __forceinline__ void cpa16(uint32_t saddr, const void* g) {
    asm volatile("cp.async.cg.shared.global [%0], [%1], 16;" :: "r"(saddr), "l"(g));
}

// ================= tensor-core GEMM (fp16 2-term, 3-stage cp.async pipeline) ==========
#define GS_STR 40
#define GS_ARR (128*GS_STR)            // halves per array
#define GS_STAGE (3*GS_ARR)            // halves per stage
#define GS_BYTES (GS_STAGE*2)          // 30720
#define GSMEM (3*GS_BYTES)             // 92160

// MODE: 0 = store C, 1 = accumulate into C, 2 = scatter-add into x (C = g_x base),
// MODE: 3 = fused silu(gate)*up -> split fp16 into g_gah/g_gal (C unused)
template<int MODE>
__global__ void __launch_bounds__(256) gemm_hf(const __half* __restrict__ Ah, const __half* __restrict__ Al,
                                               const __half* __restrict__ Bm,
                                               float* __restrict__ C, int M, int N, int K) {
    extern __shared__ __half sm[];
    uint32_t smem_u32 = (uint32_t)__cvta_generic_to_shared(sm);

    int tid = threadIdx.x;
    int lane = tid & 31, wid = tid >> 5;
    int wm = (wid & 1) * 64;
    int wn = (wid >> 1) * 32;
    int row0 = blockIdx.y * 128, col0 = blockIdx.x * 128;

    float acc[4][4][4];
    #pragma unroll
    for (int i = 0; i < 4; i++)
        #pragma unroll
        for (int j = 0; j < 4; j++)
            #pragma unroll
            for (int r = 0; r < 4; r++) acc[i][j][r] = 0.f;

    int a_r = lane & 15;
    int a_c = ((lane >> 4) & 1) * 8;
    int b_r = (lane & 7) + ((lane >> 4) & 1) * 8;
    int b_c = ((lane >> 3) & 1) * 8;
    int aoff[4], boff[2];
    #pragma unroll
    for (int mt = 0; mt < 4; mt++) aoff[mt] = (wm + mt*16 + a_r)*GS_STR + a_c;
    #pragma unroll
    for (int pr = 0; pr < 2; pr++) boff[pr] = (wn + pr*16 + b_r)*GS_STR + b_c;

    #define G_LOAD(cc, st) do {                                                   \
        uint32_t stg_ = smem_u32 + (uint32_t)(st)*GS_BYTES;                       \
        int k0_ = (cc) << 5;                                                      \
        _Pragma("unroll")                                                         \
        for (int i_ = 0; i_ < 6; i_++) {                                          \
            int u_ = i_*256 + tid;                                                \
            int arr_ = u_ >> 9, rem_ = u_ & 511;                                  \
            int row_ = rem_ >> 2, cb_ = (rem_ & 3) << 3;                          \
            uint32_t dst_ = stg_ + (uint32_t)(arr_*GS_ARR + row_*GS_STR + cb_)*2; \
            if (arr_ < 2) {                                                       \
                if (row0 + row_ < M) {                                            \
                    const __half* s_ = (arr_ ? Al : Ah) +                         \
                        (size_t)(row0 + row_)*K + k0_ + cb_;                      \
                    cpa16(dst_, s_);                                              \
                }                                                                 \
            } else {                                                              \
                if (col0 + row_ < N) {                                            \
                    const __half* s_ = Bm + (size_t)(col0 + row_)*K + k0_ + cb_;  \
                    cpa16(dst_, s_);                                              \
                }                                                                 \
            }                                                                     \
        }                                                                         \
        asm volatile("cp.async.commit_group;" ::: "memory");                      \
    } while (0)

    int nch = K >> 5;
    G_LOAD(0, 0);
    if (nch > 1) G_LOAD(1, 1);
    else asm volatile("cp.async.commit_group;" ::: "memory");

    for (int c = 0; c < nch; c++) {
        asm volatile("cp.async.wait_group 1;" ::: "memory");
        __syncthreads();
        if (c + 2 < nch) G_LOAD(c + 2, (c + 2) % 3);
        else asm volatile("cp.async.commit_group;" ::: "memory");

        const __half* cAh = sm + (c % 3)*GS_STAGE;
        const __half* cAl = cAh + GS_ARR;
        const __half* cB  = cAh + 2*GS_ARR;
        #pragma unroll
        for (int j = 0; j < 2; j++) {
            int kc = j*16;
            uint32_t fAh[4][4], fAl[4][4], fB[2][4];
            #pragma unroll
            for (int mt = 0; mt < 4; mt++) {
                ldsm_x4(fAh[mt], cAh + aoff[mt] + kc);
                ldsm_x4(fAl[mt], cAl + aoff[mt] + kc);
            }
            #pragma unroll
            for (int pr = 0; pr < 2; pr++) ldsm_x4(fB[pr], cB + boff[pr] + kc);

            #pragma unroll
            for (int mt = 0; mt < 4; mt++)
                #pragma unroll
                for (int nt = 0; nt < 4; nt++)
                    mma_f16(acc[mt][nt], fAh[mt], fB[nt>>1][(nt&1)*2], fB[nt>>1][(nt&1)*2+1]);
            #pragma unroll
            for (int mt = 0; mt < 4; mt++)
                #pragma unroll
                for (int nt = 0; nt < 4; nt++)
                    mma_f16(acc[mt][nt], fAl[mt], fB[nt>>1][(nt&1)*2], fB[nt>>1][(nt&1)*2+1]);
        }
    }
    #undef G_LOAD

    int erow = lane >> 2;
    int ecol = (lane & 3) * 2;
    #pragma unroll
    for (int mt = 0; mt < 4; mt++) {
        #pragma unroll
        for (int nt = 0; nt < 4; nt++) {
            int r = row0 + wm + mt*16 + erow;
            int c = col0 + wn + nt*8 + ecol;
            if (c < N) {
                if (MODE == 3) {
                    size_t i0 = (size_t)(c >> 1);
                    if (r < M) {
                        float g = acc[mt][nt][0], u = acc[mt][nt][1];
                        float v = g * (1.f/(1.f + __expf(-g))) * u;
                        split2h(v, g_gah[(size_t)r*FFF + i0], g_gal[(size_t)r*FFF + i0]);
                    }
                    if (r + 8 < M) {
                        float g = acc[mt][nt][2], u = acc[mt][nt][3];
                        float v = g * (1.f/(1.f + __expf(-g))) * u;
                        split2h(v, g_gah[(size_t)(r+8)*FFF + i0], g_gal[(size_t)(r+8)*FFF + i0]);
                    }
                } else if (MODE == 2) {
                    if (r < M) {
                        int b = r / KSEL;
                        int tok = g_tidx[r];
                        float p = g_tp[r];
                        float2* ptr = (float2*)&C[((size_t)b*SS + tok)*DD + c];
                        float2 o = *ptr; o.x += acc[mt][nt][0]*p; o.y += acc[mt][nt][1]*p; *ptr = o;
                    }
                    if (r + 8 < M) {
                        int r8 = r + 8;
                        int b = r8 / KSEL;
                        int tok = g_tidx[r8];
                        float p = g_tp[r8];
                        float2* ptr = (float2*)&C[((size_t)b*SS + tok)*DD + c];
                        float2 o = *ptr; o.x += acc[mt][nt][2]*p; o.y += acc[mt][nt][3]*p; *ptr = o;
                    }
                } else {
                    if (r < M) {
                        float2* p = (float2*)&C[(size_t)r*N + c];
                        if (MODE == 1) { float2 o = *p; o.x += acc[mt][nt][0]; o.y += acc[mt][nt][1]; *p = o; }
                        else { float2 o; o.x = acc[mt][nt][0]; o.y = acc[mt][nt][1]; *p = o; }
                    }
                    if (r + 8 < M) {
                        float2* p = (float2*)&C[(size_t)(r+8)*N + c];
                        if (MODE == 1) { float2 o = *p; o.x += acc[mt][nt][2]; o.y += acc[mt][nt][3]; *p = o; }
                        else { float2 o; o.x = acc[mt][nt][2]; o.y = acc[mt][nt][3]; *p = o; }
                    }
                }
            }
        }
    }
}

// ---------------- rope + split/round to fp16 [B,NH,S,HD] ----------------
__global__ void rope_kernel() {
    int i = blockIdx.x*blockDim.x + threadIdx.x;
    if (i >= M_TOK*NHH*32) return;
    int t = i / (NHH*32);
    int r = i % (NHH*32);
    int h = r / 32, d = r % 32;
    int b = t / SS, s = t % SS;
    const float* base = g_qkv + (size_t)t*(3*DD) + h*HDD;
    float c = g_cos[s*32+d], sn = g_sin[s*32+d];
    float q1 = base[d],        q2 = base[d+32];
    float k1 = base[DD+d],     k2 = base[DD+d+32];
    size_t o = ((size_t)(b*NHH+h)*SS + s)*HDD;
    float qa  = (q1*c - q2*sn)*0.125f;
    float qb2 = (q2*c + q1*sn)*0.125f;
    float ka = k1*c - k2*sn;
    float kb = k2*c + k1*sn;
    split2h(qa,  g_qh[o+d],    g_ql[o+d]);
    split2h(qb2, g_qh[o+d+32], g_ql[o+d+32]);
    g_kh[o+d]    = __float2half_rn(ka);
    g_kh[o+d+32] = __float2half_rn(kb);
    g_vh[o+d]    = __float2half_rn(base[2*DD+d]);
    g_vh[o+d+32] = __float2half_rn(base[2*DD+d+32]);
}

// ---------------- flash attention v7: fp16, P single-term, 128q x 64k, 256 thr ----
#define ASTR 72
#define QHALVES (128*ASTR)
#define KVOFF (2*QHALVES)

__global__ void __launch_bounds__(256) flash7_kernel() {
    extern __shared__ __half sb[];
    __half* Qh = sb;
    __half* Ql = sb + QHALVES;
    uint32_t smem_u32 = (uint32_t)__cvta_generic_to_shared(sb);

    int b = blockIdx.z, hh = blockIdx.y;
    int qb = (int)(gridDim.x - 1u - blockIdx.x);   // heavy first
    int tid = threadIdx.x, lane = tid & 31, w = tid >> 5;
    size_t headoff = ((size_t)(b*NHH+hh)*SS)*HDD;
    const __half *Qhp = g_qh + headoff, *Qlp = g_ql + headoff;
    const __half* srcs[2] = {g_kh + headoff, g_vh + headoff};

    {
        #pragma unroll
        for (int i = 0; i < 4; i++) {
            int idx = i*256 + tid;
            int rr = idx >> 3, c = (idx & 7) * 8;
            *(uint4*)&Qh[rr*ASTR + c] = *(const uint4*)&Qhp[(size_t)(qb*128 + rr)*64 + c];
            *(uint4*)&Ql[rr*ASTR + c] = *(const uint4*)&Qlp[(size_t)(qb*128 + rr)*64 + c];
        }
    }
    {
        #pragma unroll
        for (int i = 0; i < 4; i++) {
            int u = i*256 + tid;
            int a = u >> 9, rem = u & 511;
            int row = rem >> 3, col = (rem & 7) * 8;
            uint32_t sa = smem_u32 + (uint32_t)(KVOFF + (a*64 + row)*ASTR + col)*2;
            cpa16(sa, srcs[a] + (size_t)row*64 + col);
        }
        asm volatile("cp.async.commit_group;");
    }
    asm volatile("cp.async.wait_group 0;");
    __syncthreads();

    int m0 = w * 16;
    int a_r = lane & 15;
    int a_c = ((lane >> 4) & 1) * 8;
    int b_r = (lane & 7) + ((lane >> 4) & 1) * 8;
    int b_c = ((lane >> 3) & 1) * 8;
    int v_r = ((lane >> 3) & 1) * 8 + (lane & 7);
    int v_c = ((lane >> 4) & 1) * 8;

    float O[8][4];
    float mrow[2] = {-1e30f, -1e30f};
    float lrow[2] = {0.f, 0.f};
    #pragma unroll
    for (int nt = 0; nt < 8; nt++)
        #pragma unroll
        for (int r = 0; r < 4; r++) O[nt][r] = 0.f;

    int ntiles = 2*qb + 2;
    for (int kt = 0; kt < ntiles; kt++) {
        int cur = kt & 1;
        if (kt + 1 < ntiles) {
            int st = cur ^ 1;
            #pragma unroll
            for (int i = 0; i < 4; i++) {
                int u = i*256 + tid;
                int a = u >> 9, rem = u & 511;
                int row = rem >> 3, col = (rem & 7) * 8;
                uint32_t sa = smem_u32 + (uint32_t)(KVOFF + ((2*st + a)*64 + row)*ASTR + col)*2;
                cpa16(sa, srcs[a] + (size_t)((kt+1)*64 + row)*64 + col);
            }
            asm volatile("cp.async.commit_group;");
        }
        const __half* Kt = sb + KVOFF + (2*cur)*64*ASTR;
        const __half* Vt = Kt + 64*ASTR;

        float s[8][4];
        #pragma unroll
        for (int nt = 0; nt < 8; nt++)
            #pragma unroll
            for (int r = 0; r < 4; r++) s[nt][r] = 0.f;
        #pragma unroll
        for (int kk = 0; kk < 4; kk++) {
            uint32_t QAh[4], QAl[4];
            ldsm_x4(QAh, Qh + (m0 + a_r)*ASTR + kk*16 + a_c);
            ldsm_x4(QAl, Ql + (m0 + a_r)*ASTR + kk*16 + a_c);
            #pragma unroll
            for (int bn = 0; bn < 4; bn++) {
                uint32_t KB[4];
                ldsm_x4(KB, Kt + (bn*16 + b_r)*ASTR + kk*16 + b_c);
                mma_f16(s[2*bn],   QAh, KB[0], KB[1]);
                mma_f16(s[2*bn+1], QAh, KB[2], KB[3]);
                mma_f16(s[2*bn],   QAl, KB[0], KB[1]);
                mma_f16(s[2*bn+1], QAl, KB[2], KB[3]);
            }
        }
        if (kt >= 2*qb) {
            int r0l = m0 + (lane >> 2);
            int c0l = (kt - 2*qb)*64 + 2*(lane & 3);
            #pragma unroll
            for (int nt = 0; nt < 8; nt++) {
                int c = nt*8 + c0l;
                if (c     > r0l)     s[nt][0] = -1e30f;
                if (c + 1 > r0l)     s[nt][1] = -1e30f;
                if (c     > r0l + 8) s[nt][2] = -1e30f;
                if (c + 1 > r0l + 8) s[nt][3] = -1e30f;
            }
        }
        float rm0 = -1e30f, rm1 = -1e30f;
        #pragma unroll
        for (int nt = 0; nt < 8; nt++) {
            rm0 = fmaxf(rm0, fmaxf(s[nt][0], s[nt][1]));
            rm1 = fmaxf(rm1, fmaxf(s[nt][2], s[nt][3]));
        }
        rm0 = fmaxf(rm0, __shfl_xor_sync(0xffffffffu, rm0, 1));
        rm0 = fmaxf(rm0, __shfl_xor_sync(0xffffffffu, rm0, 2));
        rm1 = fmaxf(rm1, __shfl_xor_sync(0xffffffffu, rm1, 1));
        rm1 = fmaxf(rm1, __shfl_xor_sync(0xffffffffu, rm1, 2));
        float mn0 = fmaxf(mrow[0], rm0), mn1 = fmaxf(mrow[1], rm1);
        float cc0 = __expf(mrow[0] - mn0), cc1 = __expf(mrow[1] - mn1);
        mrow[0] = mn0; mrow[1] = mn1;
        float rs0 = 0.f, rs1 = 0.f;
        #pragma unroll
        for (int nt = 0; nt < 8; nt++) {
            s[nt][0] = __expf(s[nt][0] - mn0); rs0 += s[nt][0];
            s[nt][1] = __expf(s[nt][1] - mn0); rs0 += s[nt][1];
            s[nt][2] = __expf(s[nt][2] - mn1); rs1 += s[nt][2];
            s[nt][3] = __expf(s[nt][3] - mn1); rs1 += s[nt][3];
        }
        rs0 += __shfl_xor_sync(0xffffffffu, rs0, 1);
        rs0 += __shfl_xor_sync(0xffffffffu, rs0, 2);
        rs1 += __shfl_xor_sync(0xffffffffu, rs1, 1);
        rs1 += __shfl_xor_sync(0xffffffffu, rs1, 2);
        lrow[0] = lrow[0]*cc0 + rs0;
        lrow[1] = lrow[1]*cc1 + rs1;
        #pragma unroll
        for (int nt = 0; nt < 8; nt++) {
            O[nt][0] *= cc0; O[nt][1] *= cc0;
            O[nt][2] *= cc1; O[nt][3] *= cc1;
        }
        // ---- O += P V (P single fp16: P in [0,1], rounding error ~2^-12 incoherent) ----
        #pragma unroll
        for (int kk = 0; kk < 4; kk++) {
            uint32_t Ph[4];
            Ph[0] = pack_h2(s[2*kk][0],   s[2*kk][1]);
            Ph[1] = pack_h2(s[2*kk][2],   s[2*kk][3]);
            Ph[2] = pack_h2(s[2*kk+1][0], s[2*kk+1][1]);
            Ph[3] = pack_h2(s[2*kk+1][2], s[2*kk+1][3]);
            #pragma unroll
            for (int bn = 0; bn < 4; bn++) {
                uint32_t VB[4];
                ldsm_x4_t(VB, Vt + (kk*16 + v_r)*ASTR + bn*16 + v_c);
                mma_f16(O[2*bn],   Ph, VB[0], VB[1]);
                mma_f16(O[2*bn+1], Ph, VB[2], VB[3]);
            }
        }
        asm volatile("cp.async.wait_group 0;");
        __syncthreads();
    }
    float inv0 = 1.f/lrow[0], inv1 = 1.f/lrow[1];
    int row0 = qb*128 + m0 + (lane >> 2);
    int row1 = row0 + 8;
    #pragma unroll
    for (int nt = 0; nt < 8; nt++) {
        int col = hh*64 + nt*8 + 2*(lane & 3);
        size_t o0 = ((size_t)b*SS + row0)*DD + col;
        size_t o1 = ((size_t)b*SS + row1)*DD + col;
        uint32_t hp, lp;
        split_pack_h(O[nt][0]*inv0, O[nt][1]*inv0, hp, lp);
        *(uint32_t*)&g_atth[o0] = hp;
        *(uint32_t*)&g_attl[o0] = lp;
        split_pack_h(O[nt][2]*inv1, O[nt][3]*inv1, hp, lp);
        *(uint32_t*)&g_atth[o1] = hp;
        *(uint32_t*)&g_attl[o1] = lp;
    }
}
#define FLASH_SMEM ((2*128 + 4*64)*ASTR*2)   // 73728 bytes

// ---------------- router ----------------
__global__ void router_kernel(const float* __restrict__ rw) {
    int t = blockIdx.x*4 + (threadIdx.x >> 5);
    int lane = threadIdx.x & 31;
    const float* xr = g_x + (size_t)t*DD;
    float s = 0.f;
    for (int d = lane; d < DD; d += 32) s += xr[d]*rw[d];
    #pragma unroll
    for (int o = 16; o > 0; o >>= 1) s += __shfl_xor_sync(0xffffffffu, s, o);
    if (lane == 0) g_probs[t] = 1.f/(1.f + __expf(-s));
}

// ---------------- per-batch top-k via 4-pass radix select + compaction ----------------
// probs are positive floats -> uint32 bit pattern is order-isomorphic.
// Selected SET is exact; output order is arbitrary (downstream is permutation-invariant).
__global__ void __launch_bounds__(1024) topk_kernel() {
    __shared__ int hist[256];
    __shared__ int sh_bin, sh_acc;
    __shared__ int pos_gt, pos_eq;
    int bb = blockIdx.x, tid = threadIdx.x;
    uint32_t key0 = __float_as_uint(g_probs[(size_t)bb*SS + tid]);
    uint32_t key1 = __float_as_uint(g_probs[(size_t)bb*SS + tid + 1024]);
    uint32_t prefix = 0;
    int need = KSEL;
    #pragma unroll
    for (int shift = 24; shift >= 0; shift -= 8) {
        uint32_t maskhi = (shift < 24) ? (0xFFFFFFFFu << (shift + 8)) : 0u;
        if (tid < 256) hist[tid] = 0;
        __syncthreads();
        if ((key0 & maskhi) == prefix) atomicAdd(&hist[(key0 >> shift) & 255], 1);
        if ((key1 & maskhi) == prefix) atomicAdd(&hist[(key1 >> shift) & 255], 1);
        __syncthreads();
        if (tid == 0) {
            int acc = 0, b = 255;
            for (; b > 0; b--) {
                int h = hist[b];
                if (acc + h >= need) break;
                acc += h;
            }
            sh_bin = b; sh_acc = acc;
        }
        __syncthreads();
        prefix |= ((uint32_t)sh_bin) << shift;
        need -= sh_acc;
        __syncthreads();
    }
    // prefix = exact threshold value T; need = how many ==T to include
    if (tid == 0) { pos_gt = 0; pos_eq = KSEL - need; }
    __syncthreads();
    float v0 = __uint_as_float(key0), v1 = __uint_as_float(key1);
    if (key0 > prefix) {
        int p = atomicAdd(&pos_gt, 1);
        g_tidx[(size_t)bb*KSEL + p] = tid;      g_tp[(size_t)bb*KSEL + p] = v0;
    } else if (key0 == prefix) {
        int p = atomicAdd(&pos_eq, 1);
        if (p < KSEL) { g_tidx[(size_t)bb*KSEL + p] = tid;      g_tp[(size_t)bb*KSEL + p] = v0; }
    }
    if (key1 > prefix) {
        int p = atomicAdd(&pos_gt, 1);
        g_tidx[(size_t)bb*KSEL + p] = tid + 1024; g_tp[(size_t)bb*KSEL + p] = v1;
    } else if (key1 == prefix) {
        int p = atomicAdd(&pos_eq, 1);
        if (p < KSEL) { g_tidx[(size_t)bb*KSEL + p] = tid + 1024; g_tp[(size_t)bb*KSEL + p] = v1; }
    }
}

// ---------------- gather + rmsnorm (split out) ----------------
__global__ void gather_rmsnorm_kernel(const float* __restrict__ w) {
    int i = blockIdx.x;
    int b = i / KSEL;
    int tok = g_tidx[i];
    const float* xr = g_x + ((size_t)b*SS + tok)*DD;
    float ss = 0.f;
    for (int d = threadIdx.x; d < DD; d += 128) { float v = xr[d]; ss += v*v; }
    #pragma unroll
    for (int o = 16; o > 0; o >>= 1) ss += __shfl_xor_sync(0xffffffffu, ss, o);
    __shared__ float red[4];
    if ((threadIdx.x & 31) == 0) red[threadIdx.x >> 5] = ss;
    __syncthreads();
    float tot = red[0]+red[1]+red[2]+red[3];
    float sc = rsqrtf(tot*(1.f/DD) + EPSF);
    for (int d = threadIdx.x; d < DD; d += 128) {
        float y = w[d]*xr[d]*sc;
        split2h(y, g_hsh[(size_t)i*DD + d], g_hsl[(size_t)i*DD + d]);
    }
}

// ---------------- host orchestration ----------------
extern "C" void kernel_launch(void* const* d_in, const int* in_sizes, int n_in,
                              void* d_out, int out_size) {
    const int*   ids       = (const int*)d_in[0];
    const int*   iter      = (const int*)d_in[1];
    const float* emb       = (const float*)d_in[2];
    const float* iter_emb  = (const float*)d_in[3];
    const float* attn_norm = (const float*)d_in[4];
    const float* Wqkv      = (const float*)d_in[5];
    const float* wo        = (const float*)d_in[6];
    const float* router    = (const float*)d_in[7];
    const float* mlp_norm  = (const float*)d_in[8];
    const float* gate_w    = (const float*)d_in[9];
    const float* up_w      = (const float*)d_in[10];
    const float* down_w    = (const float*)d_in[11];
    const float* fnorm     = (const float*)d_in[12];

    float *px, *pqkv;
    __half *phh, *phl, *patth, *pattl, *phsh, *phsl, *pgah, *pgal;
    __half *pwqkv, *pwo, *pwgu, *pwd;
    cudaGetSymbolAddress((void**)&px,    g_x);
    cudaGetSymbolAddress((void**)&pqkv,  g_qkv);
    cudaGetSymbolAddress((void**)&phh,   g_hh);
    cudaGetSymbolAddress((void**)&phl,   g_hl);
    cudaGetSymbolAddress((void**)&patth, g_atth);
    cudaGetSymbolAddress((void**)&pattl, g_attl);
    cudaGetSymbolAddress((void**)&phsh,  g_hsh);
    cudaGetSymbolAddress((void**)&phsl,  g_hsl);
    cudaGetSymbolAddress((void**)&pgah,  g_gah);
    cudaGetSymbolAddress((void**)&pgal,  g_gal);
    cudaGetSymbolAddress((void**)&pwqkv, g_wqkv);
    cudaGetSymbolAddress((void**)&pwo,   g_wo);
    cudaGetSymbolAddress((void**)&pwgu,  g_wgu);
    cudaGetSymbolAddress((void**)&pwd,   g_wd);

    cudaFuncSetAttribute(flash7_kernel, cudaFuncAttributeMaxDynamicSharedMemorySize, FLASH_SMEM);
    cudaFuncSetAttribute(gemm_hf<0>, cudaFuncAttributeMaxDynamicSharedMemorySize, GSMEM);
    cudaFuncSetAttribute(gemm_hf<1>, cudaFuncAttributeMaxDynamicSharedMemorySize, GSMEM);
    cudaFuncSetAttribute(gemm_hf<2>, cudaFuncAttributeMaxDynamicSharedMemorySize, GSMEM);
    cudaFuncSetAttribute(gemm_hf<3>, cudaFuncAttributeMaxDynamicSharedMemorySize, GSMEM);

    rope_table_kernel<<<(SS*32 + 255)/256, 256>>>();
    embed_kernel<<<(M_TOK*DD + 255)/256, 256>>>(ids, iter, emb, iter_emb);
    roundh_kernel<<<(NLL*3*DD*DD + 255)/256, 256>>>(Wqkv, pwqkv, NLL*3*DD*DD);
    roundh_kernel<<<(NLL*DD*DD + 255)/256, 256>>>(wo, pwo, NLL*DD*DD);
    round_gu_kernel<<<(NLL*FFF*DD + 255)/256, 256>>>(gate_w, pwgu, 0);
    round_gu_kernel<<<(NLL*FFF*DD + 255)/256, 256>>>(up_w,   pwgu, 1);
    roundh_kernel<<<(NLL*DD*FFF + 255)/256, 256>>>(down_w, pwd, NLL*DD*FFF);

    for (int l = 0; l < NLL; l++) {
        rmsnorm_split_kernel<<<M_TOK, 128>>>(px, attn_norm + (size_t)l*DD, phh, phl);
        gemm_hf<0><<<dim3((3*DD+127)/128, M_TOK/128), 256, GSMEM>>>(phh, phl,
            pwqkv + (size_t)l*3*DD*DD, pqkv, M_TOK, 3*DD, DD);
        rope_kernel<<<(M_TOK*NHH*32 + 255)/256, 256>>>();
        flash7_kernel<<<dim3(SS/128, NHH, BB), 256, FLASH_SMEM>>>();
        gemm_hf<1><<<dim3((DD+127)/128, M_TOK/128), 256, GSMEM>>>(patth, pattl,
            pwo + (size_t)l*DD*DD, px, M_TOK, DD, DD);
        router_kernel<<<M_TOK/4, 128>>>(router + (size_t)l*DD);
        topk_kernel<<<BB, 1024>>>();
        gather_rmsnorm_kernel<<<M_SEL, 128>>>(mlp_norm + (size_t)l*DD);
        gemm_hf<3><<<dim3((2*FFF+127)/128, (M_SEL+127)/128), 256, GSMEM>>>(phsh, phsl,
            pwgu + (size_t)l*2*FFF*DD, px /*unused*/, M_SEL, 2*FFF, DD);
        gemm_hf<2><<<dim3((DD+127)/128, (M_SEL+127)/128), 256, GSMEM>>>(pgah, pgal,
            pwd + (size_t)l*DD*FFF, px, M_SEL, DD, FFF);
    }
    rmsnorm_f32_kernel<<<M_TOK, 128>>>(px, fnorm, (float*)d_out);
}

// round 15
// speedup vs baseline: 6.3210x; 1.3512x over previous
#include <cuda_runtime.h>
#include <cuda_fp16.h>
#include <math.h>
#include <stdint.h>

#define BB 8
#define SS 2048
#define DD 320
#define NHH 5
#define HDD 64
#define FFF 864
#define NLL 6
#define KSEL 1638
#define M_TOK (BB*SS)      // 16384
#define M_SEL (BB*KSEL)    // 13104
#define EPSF 1e-6f

// ---------------- scratch (static device globals; no allocation) ----------------
__device__ float g_x[M_TOK*DD];
__device__ float g_qkv[M_TOK*3*DD];
__device__ float g_probs[M_TOK];
__device__ int   g_tidx[M_SEL];
__device__ float g_tp[M_SEL];
__device__ float g_cos[SS*32];
__device__ float g_sin[SS*32];

// fp16 activation buffers (single precision each side; error incoherent over K)
__device__ __half g_h[M_TOK*DD];                    // rmsnorm out (qkv A)
__device__ __half g_att[M_TOK*DD];                  // attention out (wo A)
__device__ __half g_hs[M_SEL*DD];                   // gathered norm (gate/up A)
__device__ __half g_ga[(size_t)M_SEL*FFF];          // silu*up (down A)
// q/k/v fp16  [B,NH,S,HD], q pre-scaled
__device__ __half g_q[M_TOK*DD];
__device__ __half g_k[M_TOK*DD];
__device__ __half g_v[M_TOK*DD];
// fp16 weights
__device__ __half g_wqkv[NLL*3*DD*DD];
__device__ __half g_wo[NLL*DD*DD];
__device__ __half g_wgu[NLL*2*FFF*DD];   // interleaved: row 2i=gate_i, 2i+1=up_i
__device__ __half g_wd[NLL*DD*FFF];

__device__ __forceinline__ uint32_t pack_h2(float x, float y) {
    __half2 h = __halves2half2(__float2half_rn(x), __float2half_rn(y));
    return *reinterpret_cast<uint32_t*>(&h);
}

// ---------------- weight rounding ----------------
__global__ void roundh_kernel(const float* __restrict__ src, __half* __restrict__ dst, int n) {
    int i = blockIdx.x*blockDim.x + threadIdx.x;
    if (i >= n) return;
    dst[i] = __float2half_rn(src[i]);
}
// interleave gate/up: src row i of layer -> dst row 2i+which
__global__ void round_gu_kernel(const float* __restrict__ src, __half* __restrict__ dst, int which) {
    int i = blockIdx.x*blockDim.x + threadIdx.x;
    if (i >= NLL*FFF*DD) return;
    int lay = i / (FFF*DD), rem = i % (FFF*DD);
    int r = rem / DD, d = rem % DD;
    size_t dsto = (size_t)lay*2*FFF*DD + (size_t)(2*r + which)*DD + d;
    dst[dsto] = __float2half_rn(src[i]);
}

// ---------------- rope tables ----------------
__global__ void rope_table_kernel() {
    int i = blockIdx.x*blockDim.x + threadIdx.x;
    if (i >= SS*32) return;
    int s = i / 32, d = i % 32;
    double freq = exp(-((double)(2*d)/64.0)*log(10000.0));
    double f = (double)s * freq;
    g_cos[i] = (float)cos(f);
    g_sin[i] = (float)sin(f);
}

// ---------------- embed ----------------
__global__ void embed_kernel(const int* __restrict__ ids, const int* __restrict__ iter,
                             const float* __restrict__ emb, const float* __restrict__ iter_emb) {
    int i = blockIdx.x*blockDim.x + threadIdx.x;
    if (i >= M_TOK*DD) return;
    int t = i / DD, d = i % DD;
    float v = emb[(size_t)ids[t]*DD + d];
    int it = iter[0];
    if (it < 8) v += iter_emb[(size_t)it*DD + d];
    g_x[i] = v;
}

// ---------------- rmsnorm variants ----------------
__global__ void rmsnorm_f32_kernel(const float* __restrict__ X, const float* __restrict__ w,
                                   float* __restrict__ Y) {
    int t = blockIdx.x;
    const float* xr = X + (size_t)t*DD;
    float ss = 0.f;
    for (int d = threadIdx.x; d < DD; d += 128) { float v = xr[d]; ss += v*v; }
    #pragma unroll
    for (int o = 16; o > 0; o >>= 1) ss += __shfl_xor_sync(0xffffffffu, ss, o);
    __shared__ float red[4];
    if ((threadIdx.x & 31) == 0) red[threadIdx.x >> 5] = ss;
    __syncthreads();
    float tot = red[0]+red[1]+red[2]+red[3];
    float sc = rsqrtf(tot*(1.f/DD) + EPSF);
    for (int d = threadIdx.x; d < DD; d += 128) Y[(size_t)t*DD + d] = w[d]*xr[d]*sc;
}

__global__ void rmsnorm_h_kernel(const float* __restrict__ X, const float* __restrict__ w,
                                 __half* __restrict__ Y) {
    int t = blockIdx.x;
    const float* xr = X + (size_t)t*DD;
    float ss = 0.f;
    for (int d = threadIdx.x; d < DD; d += 128) { float v = xr[d]; ss += v*v; }
    #pragma unroll
    for (int o = 16; o > 0; o >>= 1) ss += __shfl_xor_sync(0xffffffffu, ss, o);
    __shared__ float red[4];
    if ((threadIdx.x & 31) == 0) red[threadIdx.x >> 5] = ss;
    __syncthreads();
    float tot = red[0]+red[1]+red[2]+red[3];
    float sc = rsqrtf(tot*(1.f/DD) + EPSF);
    for (int d = threadIdx.x; d < DD; d += 128)
        Y[(size_t)t*DD + d] = __float2half_rn(w[d]*xr[d]*sc);
}

// ================= PTX helpers =================
__device__ __forceinline__ void ldsm_x4(uint32_t* r, const __half* p) {
    uint32_t addr = (uint32_t)__cvta_generic_to_shared(p);
    asm volatile("ldmatrix.sync.aligned.m8n8.x4.shared.b16 {%0,%1,%2,%3}, [%4];"
                 : "=r"(r[0]), "=r"(r[1]), "=r"(r[2]), "=r"(r[3]) : "r"(addr));
}
__device__ __forceinline__ void ldsm_x4_t(uint32_t* r, const __half* p) {
    uint32_t addr = (uint32_t)__cvta_generic_to_shared(p);
    asm volatile("ldmatrix.sync.aligned.m8n8.x4.trans.shared.b16 {%0,%1,%2,%3}, [%4];"
                 : "=r"(r[0]), "=r"(r[1]), "=r"(r[2]), "=r"(r[3]) : "r"(addr));
}
__device__ __forceinline__ void mma_f16(float* c, const uint32_t* a, uint32_t b0, uint32_t b1) {
    asm volatile(
        "mma.sync.aligned.m16n8k16.row.col.f32.f16.f16.f32 "
        "{%0,%1,%2,%3}, {%4,%5,%6,%7}, {%8,%9}, {%0,%1,%2,%3};\n"
        : "+f"(c[0]), "+f"(c[1]), "+f"(c[2]), "+f"(c[3])
        : "r"(a[0]), "r"(a[1]), "r"(a[2]), "r"(a[3]), "r"(b0), "r"(b1));
}
__device__ __forceinline__ void cpa16(uint32_t saddr, const void* g) {
    asm volatile("cp.async.cg.shared.global [%0], [%1], 16;" :: "r"(saddr), "l"(g));
}

// ================= tensor-core GEMM (fp16 single-term, 3-stage cp.async pipeline) =====
#define GS_STR 40
#define GS_ARR (128*GS_STR)            // halves per array
#define GS_STAGE (2*GS_ARR)            // halves per stage: A | B
#define GS_BYTES (GS_STAGE*2)          // 20480
#define GSMEM (3*GS_BYTES)             // 61440

// MODE: 0 = store C, 1 = accumulate into C, 2 = scatter-add into x (C = g_x base),
// MODE: 3 = fused silu(gate)*up -> fp16 into g_ga (C unused)
template<int MODE>
__global__ void __launch_bounds__(256) gemm_hf(const __half* __restrict__ Am,
                                               const __half* __restrict__ Bm,
                                               float* __restrict__ C, int M, int N, int K) {
    extern __shared__ __half sm[];
    uint32_t smem_u32 = (uint32_t)__cvta_generic_to_shared(sm);

    int tid = threadIdx.x;
    int lane = tid & 31, wid = tid >> 5;
    int wm = (wid & 1) * 64;
    int wn = (wid >> 1) * 32;
    int row0 = blockIdx.y * 128, col0 = blockIdx.x * 128;

    float acc[4][4][4];
    #pragma unroll
    for (int i = 0; i < 4; i++)
        #pragma unroll
        for (int j = 0; j < 4; j++)
            #pragma unroll
            for (int r = 0; r < 4; r++) acc[i][j][r] = 0.f;

    int a_r = lane & 15;
    int a_c = ((lane >> 4) & 1) * 8;
    int b_r = (lane & 7) + ((lane >> 4) & 1) * 8;
    int b_c = ((lane >> 3) & 1) * 8;
    int aoff[4], boff[2];
    #pragma unroll
    for (int mt = 0; mt < 4; mt++) aoff[mt] = (wm + mt*16 + a_r)*GS_STR + a_c;
    #pragma unroll
    for (int pr = 0; pr < 2; pr++) boff[pr] = (wn + pr*16 + b_r)*GS_STR + b_c;

    // cp.async loader: 1024 16B units per stage (A 512, B 512), 4 per thread
    #define G_LOAD(cc, st) do {                                                   \
        uint32_t stg_ = smem_u32 + (uint32_t)(st)*GS_BYTES;                       \
        int k0_ = (cc) << 5;                                                      \
        _Pragma("unroll")                                                         \
        for (int i_ = 0; i_ < 4; i_++) {                                          \
            int u_ = i_*256 + tid;                                                \
            int arr_ = u_ >> 9, rem_ = u_ & 511;                                  \
            int row_ = rem_ >> 2, cb_ = (rem_ & 3) << 3;                          \
            uint32_t dst_ = stg_ + (uint32_t)(arr_*GS_ARR + row_*GS_STR + cb_)*2; \
            if (arr_ == 0) {                                                      \
                if (row0 + row_ < M)                                              \
                    cpa16(dst_, Am + (size_t)(row0 + row_)*K + k0_ + cb_);        \
            } else {                                                              \
                if (col0 + row_ < N)                                              \
                    cpa16(dst_, Bm + (size_t)(col0 + row_)*K + k0_ + cb_);        \
            }                                                                     \
        }                                                                         \
        asm volatile("cp.async.commit_group;" ::: "memory");                      \
    } while (0)

    int nch = K >> 5;
    G_LOAD(0, 0);
    if (nch > 1) G_LOAD(1, 1);
    else asm volatile("cp.async.commit_group;" ::: "memory");

    for (int c = 0; c < nch; c++) {
        asm volatile("cp.async.wait_group 1;" ::: "memory");
        __syncthreads();
        if (c + 2 < nch) G_LOAD(c + 2, (c + 2) % 3);
        else asm volatile("cp.async.commit_group;" ::: "memory");

        const __half* cA = sm + (c % 3)*GS_STAGE;
        const __half* cB = cA + GS_ARR;
        #pragma unroll
        for (int j = 0; j < 2; j++) {
            int kc = j*16;
            uint32_t fA[4][4], fB[2][4];
            #pragma unroll
            for (int mt = 0; mt < 4; mt++) ldsm_x4(fA[mt], cA + aoff[mt] + kc);
            #pragma unroll
            for (int pr = 0; pr < 2; pr++) ldsm_x4(fB[pr], cB + boff[pr] + kc);

            #pragma unroll
            for (int mt = 0; mt < 4; mt++)
                #pragma unroll
                for (int nt = 0; nt < 4; nt++)
                    mma_f16(acc[mt][nt], fA[mt], fB[nt>>1][(nt&1)*2], fB[nt>>1][(nt&1)*2+1]);
        }
    }
    #undef G_LOAD

    int erow = lane >> 2;
    int ecol = (lane & 3) * 2;
    #pragma unroll
    for (int mt = 0; mt < 4; mt++) {
        #pragma unroll
        for (int nt = 0; nt < 4; nt++) {
            int r = row0 + wm + mt*16 + erow;
            int c = col0 + wn + nt*8 + ecol;
            if (c < N) {
                if (MODE == 3) {
                    size_t i0 = (size_t)(c >> 1);   // c even: (gate, up) pair for ff index c/2
                    if (r < M) {
                        float g = acc[mt][nt][0], u = acc[mt][nt][1];
                        float v = g * (1.f/(1.f + __expf(-g))) * u;
                        g_ga[(size_t)r*FFF + i0] = __float2half_rn(v);
                    }
                    if (r + 8 < M) {
                        float g = acc[mt][nt][2], u = acc[mt][nt][3];
                        float v = g * (1.f/(1.f + __expf(-g))) * u;
                        g_ga[(size_t)(r+8)*FFF + i0] = __float2half_rn(v);
                    }
                } else if (MODE == 2) {
                    if (r < M) {
                        int b = r / KSEL;
                        int tok = g_tidx[r];
                        float p = g_tp[r];
                        float2* ptr = (float2*)&C[((size_t)b*SS + tok)*DD + c];
                        float2 o = *ptr; o.x += acc[mt][nt][0]*p; o.y += acc[mt][nt][1]*p; *ptr = o;
                    }
                    if (r + 8 < M) {
                        int r8 = r + 8;
                        int b = r8 / KSEL;
                        int tok = g_tidx[r8];
                        float p = g_tp[r8];
                        float2* ptr = (float2*)&C[((size_t)b*SS + tok)*DD + c];
                        float2 o = *ptr; o.x += acc[mt][nt][2]*p; o.y += acc[mt][nt][3]*p; *ptr = o;
                    }
                } else {
                    if (r < M) {
                        float2* p = (float2*)&C[(size_t)r*N + c];
                        if (MODE == 1) { float2 o = *p; o.x += acc[mt][nt][0]; o.y += acc[mt][nt][1]; *p = o; }
                        else { float2 o; o.x = acc[mt][nt][0]; o.y = acc[mt][nt][1]; *p = o; }
                    }
                    if (r + 8 < M) {
                        float2* p = (float2*)&C[(size_t)(r+8)*N + c];
                        if (MODE == 1) { float2 o = *p; o.x += acc[mt][nt][2]; o.y += acc[mt][nt][3]; *p = o; }
                        else { float2 o; o.x = acc[mt][nt][2]; o.y = acc[mt][nt][3]; *p = o; }
                    }
                }
            }
        }
    }
}

// ---------------- rope + round to fp16 [B,NH,S,HD] ----------------
__global__ void rope_kernel() {
    int i = blockIdx.x*blockDim.x + threadIdx.x;
    if (i >= M_TOK*NHH*32) return;
    int t = i / (NHH*32);
    int r = i % (NHH*32);
    int h = r / 32, d = r % 32;
    int b = t / SS, s = t % SS;
    const float* base = g_qkv + (size_t)t*(3*DD) + h*HDD;
    float c = g_cos[s*32+d], sn = g_sin[s*32+d];
    float q1 = base[d],        q2 = base[d+32];
    float k1 = base[DD+d],     k2 = base[DD+d+32];
    size_t o = ((size_t)(b*NHH+h)*SS + s)*HDD;
    g_q[o+d]    = __float2half_rn((q1*c - q2*sn)*0.125f);
    g_q[o+d+32] = __float2half_rn((q2*c + q1*sn)*0.125f);
    g_k[o+d]    = __float2half_rn(k1*c - k2*sn);
    g_k[o+d+32] = __float2half_rn(k2*c + k1*sn);
    g_v[o+d]    = __float2half_rn(base[2*DD+d]);
    g_v[o+d+32] = __float2half_rn(base[2*DD+d+32]);
}

// ---------------- flash attention v8: fp16 single everywhere, 128q x 64k, 256 thr ----
#define ASTR 72
#define QHALVES (128*ASTR)
#define KVOFF QHALVES

__global__ void __launch_bounds__(256) flash8_kernel() {
    extern __shared__ __half sb[];
    __half* Qs = sb;
    uint32_t smem_u32 = (uint32_t)__cvta_generic_to_shared(sb);

    int b = blockIdx.z, hh = blockIdx.y;
    int qb = (int)(gridDim.x - 1u - blockIdx.x);   // heavy first
    int tid = threadIdx.x, lane = tid & 31, w = tid >> 5;
    size_t headoff = ((size_t)(b*NHH+hh)*SS)*HDD;
    const __half* Qp = g_q + headoff;
    const __half* srcs[2] = {g_k + headoff, g_v + headoff};

    // load Q tile (128 x 64): 1024 uint4, 4 per thread
    {
        #pragma unroll
        for (int i = 0; i < 4; i++) {
            int idx = i*256 + tid;
            int rr = idx >> 3, c = (idx & 7) * 8;
            *(uint4*)&Qs[rr*ASTR + c] = *(const uint4*)&Qp[(size_t)(qb*128 + rr)*64 + c];
        }
    }
    // issue K/V tile 0 into stage 0
    {
        #pragma unroll
        for (int i = 0; i < 4; i++) {
            int u = i*256 + tid;
            int a = u >> 9, rem = u & 511;
            int row = rem >> 3, col = (rem & 7) * 8;
            uint32_t sa = smem_u32 + (uint32_t)(KVOFF + (a*64 + row)*ASTR + col)*2;
            cpa16(sa, srcs[a] + (size_t)row*64 + col);
        }
        asm volatile("cp.async.commit_group;");
    }
    asm volatile("cp.async.wait_group 0;");
    __syncthreads();

    int m0 = w * 16;
    int a_r = lane & 15;
    int a_c = ((lane >> 4) & 1) * 8;
    int b_r = (lane & 7) + ((lane >> 4) & 1) * 8;
    int b_c = ((lane >> 3) & 1) * 8;
    int v_r = ((lane >> 3) & 1) * 8 + (lane & 7);
    int v_c = ((lane >> 4) & 1) * 8;

    float O[8][4];
    float mrow[2] = {-1e30f, -1e30f};
    float lrow[2] = {0.f, 0.f};
    #pragma unroll
    for (int nt = 0; nt < 8; nt++)
        #pragma unroll
        for (int r = 0; r < 4; r++) O[nt][r] = 0.f;

    int ntiles = 2*qb + 2;
    for (int kt = 0; kt < ntiles; kt++) {
        int cur = kt & 1;
        if (kt + 1 < ntiles) {
            int st = cur ^ 1;
            #pragma unroll
            for (int i = 0; i < 4; i++) {
                int u = i*256 + tid;
                int a = u >> 9, rem = u & 511;
                int row = rem >> 3, col = (rem & 7) * 8;
                uint32_t sa = smem_u32 + (uint32_t)(KVOFF + ((2*st + a)*64 + row)*ASTR + col)*2;
                cpa16(sa, srcs[a] + (size_t)((kt+1)*64 + row)*64 + col);
            }
            asm volatile("cp.async.commit_group;");
        }
        const __half* Kt = sb + KVOFF + (2*cur)*64*ASTR;
        const __half* Vt = Kt + 64*ASTR;

        // ---- S = Q K^T ----
        float s[8][4];
        #pragma unroll
        for (int nt = 0; nt < 8; nt++)
            #pragma unroll
            for (int r = 0; r < 4; r++) s[nt][r] = 0.f;
        #pragma unroll
        for (int kk = 0; kk < 4; kk++) {
            uint32_t QA[4];
            ldsm_x4(QA, Qs + (m0 + a_r)*ASTR + kk*16 + a_c);
            #pragma unroll
            for (int bn = 0; bn < 4; bn++) {
                uint32_t KB[4];
                ldsm_x4(KB, Kt + (bn*16 + b_r)*ASTR + kk*16 + b_c);
                mma_f16(s[2*bn],   QA, KB[0], KB[1]);
                mma_f16(s[2*bn+1], QA, KB[2], KB[3]);
            }
        }
        // ---- causal mask on diagonal band (last two k-tiles) ----
        if (kt >= 2*qb) {
            int r0l = m0 + (lane >> 2);
            int c0l = (kt - 2*qb)*64 + 2*(lane & 3);
            #pragma unroll
            for (int nt = 0; nt < 8; nt++) {
                int c = nt*8 + c0l;
                if (c     > r0l)     s[nt][0] = -1e30f;
                if (c + 1 > r0l)     s[nt][1] = -1e30f;
                if (c     > r0l + 8) s[nt][2] = -1e30f;
                if (c + 1 > r0l + 8) s[nt][3] = -1e30f;
            }
        }
        // ---- online softmax ----
        float rm0 = -1e30f, rm1 = -1e30f;
        #pragma unroll
        for (int nt = 0; nt < 8; nt++) {
            rm0 = fmaxf(rm0, fmaxf(s[nt][0], s[nt][1]));
            rm1 = fmaxf(rm1, fmaxf(s[nt][2], s[nt][3]));
        }
        rm0 = fmaxf(rm0, __shfl_xor_sync(0xffffffffu, rm0, 1));
        rm0 = fmaxf(rm0, __shfl_xor_sync(0xffffffffu, rm0, 2));
        rm1 = fmaxf(rm1, __shfl_xor_sync(0xffffffffu, rm1, 1));
        rm1 = fmaxf(rm1, __shfl_xor_sync(0xffffffffu, rm1, 2));
        float mn0 = fmaxf(mrow[0], rm0), mn1 = fmaxf(mrow[1], rm1);
        float cc0 = __expf(mrow[0] - mn0), cc1 = __expf(mrow[1] - mn1);
        mrow[0] = mn0; mrow[1] = mn1;
        float rs0 = 0.f, rs1 = 0.f;
        #pragma unroll
        for (int nt = 0; nt < 8; nt++) {
            s[nt][0] = __expf(s[nt][0] - mn0); rs0 += s[nt][0];
            s[nt][1] = __expf(s[nt][1] - mn0); rs0 += s[nt][1];
            s[nt][2] = __expf(s[nt][2] - mn1); rs1 += s[nt][2];
            s[nt][3] = __expf(s[nt][3] - mn1); rs1 += s[nt][3];
        }
        rs0 += __shfl_xor_sync(0xffffffffu, rs0, 1);
        rs0 += __shfl_xor_sync(0xffffffffu, rs0, 2);
        rs1 += __shfl_xor_sync(0xffffffffu, rs1, 1);
        rs1 += __shfl_xor_sync(0xffffffffu, rs1, 2);
        lrow[0] = lrow[0]*cc0 + rs0;
        lrow[1] = lrow[1]*cc1 + rs1;
        #pragma unroll
        for (int nt = 0; nt < 8; nt++) {
            O[nt][0] *= cc0; O[nt][1] *= cc0;
            O[nt][2] *= cc1; O[nt][3] *= cc1;
        }
        // ---- O += P V (P single fp16) ----
        #pragma unroll
        for (int kk = 0; kk < 4; kk++) {
            uint32_t Ph[4];
            Ph[0] = pack_h2(s[2*kk][0],   s[2*kk][1]);
            Ph[1] = pack_h2(s[2*kk][2],   s[2*kk][3]);
            Ph[2] = pack_h2(s[2*kk+1][0], s[2*kk+1][1]);
            Ph[3] = pack_h2(s[2*kk+1][2], s[2*kk+1][3]);
            #pragma unroll
            for (int bn = 0; bn < 4; bn++) {
                uint32_t VB[4];
                ldsm_x4_t(VB, Vt + (kk*16 + v_r)*ASTR + bn*16 + v_c);
                mma_f16(O[2*bn],   Ph, VB[0], VB[1]);
                mma_f16(O[2*bn+1], Ph, VB[2], VB[3]);
            }
        }
        asm volatile("cp.async.wait_group 0;");
        __syncthreads();
    }
    // epilogue: write att fp16
    float inv0 = 1.f/lrow[0], inv1 = 1.f/lrow[1];
    int row0 = qb*128 + m0 + (lane >> 2);
    int row1 = row0 + 8;
    #pragma unroll
    for (int nt = 0; nt < 8; nt++) {
        int col = hh*64 + nt*8 + 2*(lane & 3);
        size_t o0 = ((size_t)b*SS + row0)*DD + col;
        size_t o1 = ((size_t)b*SS + row1)*DD + col;
        *(uint32_t*)&g_att[o0] = pack_h2(O[nt][0]*inv0, O[nt][1]*inv0);
        *(uint32_t*)&g_att[o1] = pack_h2(O[nt][2]*inv1, O[nt][3]*inv1);
    }
}
#define FLASH_SMEM ((128 + 4*64)*ASTR*2)   // 55296 bytes

// ---------------- router ----------------
__global__ void router_kernel(const float* __restrict__ rw) {
    int t = blockIdx.x*4 + (threadIdx.x >> 5);
    int lane = threadIdx.x & 31;
    const float* xr = g_x + (size_t)t*DD;
    float s = 0.f;
    for (int d = lane; d < DD; d += 32) s += xr[d]*rw[d];
    #pragma unroll
    for (int o = 16; o > 0; o >>= 1) s += __shfl_xor_sync(0xffffffffu, s, o);
    if (lane == 0) g_probs[t] = 1.f/(1.f + __expf(-s));
}

// ---------------- per-batch top-k via 4-pass radix select + compaction ----------------
__global__ void __launch_bounds__(1024) topk_kernel() {
    __shared__ int hist[256];
    __shared__ int sh_bin, sh_acc;
    __shared__ int pos_gt, pos_eq;
    int bb = blockIdx.x, tid = threadIdx.x;
    uint32_t key0 = __float_as_uint(g_probs[(size_t)bb*SS + tid]);
    uint32_t key1 = __float_as_uint(g_probs[(size_t)bb*SS + tid + 1024]);
    uint32_t prefix = 0;
    int need = KSEL;
    #pragma unroll
    for (int shift = 24; shift >= 0; shift -= 8) {
        uint32_t maskhi = (shift < 24) ? (0xFFFFFFFFu << (shift + 8)) : 0u;
        if (tid < 256) hist[tid] = 0;
        __syncthreads();
        if ((key0 & maskhi) == prefix) atomicAdd(&hist[(key0 >> shift) & 255], 1);
        if ((key1 & maskhi) == prefix) atomicAdd(&hist[(key1 >> shift) & 255], 1);
        __syncthreads();
        if (tid == 0) {
            int acc = 0, b = 255;
            for (; b > 0; b--) {
                int h = hist[b];
                if (acc + h >= need) break;
                acc += h;
            }
            sh_bin = b; sh_acc = acc;
        }
        __syncthreads();
        prefix |= ((uint32_t)sh_bin) << shift;
        need -= sh_acc;
        __syncthreads();
    }
    if (tid == 0) { pos_gt = 0; pos_eq = KSEL - need; }
    __syncthreads();
    float v0 = __uint_as_float(key0), v1 = __uint_as_float(key1);
    if (key0 > prefix) {
        int p = atomicAdd(&pos_gt, 1);
        g_tidx[(size_t)bb*KSEL + p] = tid;      g_tp[(size_t)bb*KSEL + p] = v0;
    } else if (key0 == prefix) {
        int p = atomicAdd(&pos_eq, 1);
        if (p < KSEL) { g_tidx[(size_t)bb*KSEL + p] = tid;      g_tp[(size_t)bb*KSEL + p] = v0; }
    }
    if (key1 > prefix) {
        int p = atomicAdd(&pos_gt, 1);
        g_tidx[(size_t)bb*KSEL + p] = tid + 1024; g_tp[(size_t)bb*KSEL + p] = v1;
    } else if (key1 == prefix) {
        int p = atomicAdd(&pos_eq, 1);
        if (p < KSEL) { g_tidx[(size_t)bb*KSEL + p] = tid + 1024; g_tp[(size_t)bb*KSEL + p] = v1; }
    }
}

// ---------------- gather + rmsnorm (fp16 out) ----------------
__global__ void gather_rmsnorm_kernel(const float* __restrict__ w) {
    int i = blockIdx.x;
    int b = i / KSEL;
    int tok = g_tidx[i];
    const float* xr = g_x + ((size_t)b*SS + tok)*DD;
    float ss = 0.f;
    for (int d = threadIdx.x; d < DD; d += 128) { float v = xr[d]; ss += v*v; }
    #pragma unroll
    for (int o = 16; o > 0; o >>= 1) ss += __shfl_xor_sync(0xffffffffu, ss, o);
    __shared__ float red[4];
    if ((threadIdx.x & 31) == 0) red[threadIdx.x >> 5] = ss;
    __syncthreads();
    float tot = red[0]+red[1]+red[2]+red[3];
    float sc = rsqrtf(tot*(1.f/DD) + EPSF);
    for (int d = threadIdx.x; d < DD; d += 128)
        g_hs[(size_t)i*DD + d] = __float2half_rn(w[d]*xr[d]*sc);
}

// ---------------- host orchestration ----------------
extern "C" void kernel_launch(void* const* d_in, const int* in_sizes, int n_in,
                              void* d_out, int out_size) {
    const int*   ids       = (const int*)d_in[0];
    const int*   iter      = (const int*)d_in[1];
    const float* emb       = (const float*)d_in[2];
    const float* iter_emb  = (const float*)d_in[3];
    const float* attn_norm = (const float*)d_in[4];
    const float* Wqkv      = (const float*)d_in[5];
    const float* wo        = (const float*)d_in[6];
    const float* router    = (const float*)d_in[7];
    const float* mlp_norm  = (const float*)d_in[8];
    const float* gate_w    = (const float*)d_in[9];
    const float* up_w      = (const float*)d_in[10];
    const float* down_w    = (const float*)d_in[11];
    const float* fnorm     = (const float*)d_in[12];

    float *px, *pqkv;
    __half *ph, *patt, *phs, *pga;
    __half *pwqkv, *pwo, *pwgu, *pwd;
    cudaGetSymbolAddress((void**)&px,    g_x);
    cudaGetSymbolAddress((void**)&pqkv,  g_qkv);
    cudaGetSymbolAddress((void**)&ph,    g_h);
    cudaGetSymbolAddress((void**)&patt,  g_att);
    cudaGetSymbolAddress((void**)&phs,   g_hs);
    cudaGetSymbolAddress((void**)&pga,   g_ga);
    cudaGetSymbolAddress((void**)&pwqkv, g_wqkv);
    cudaGetSymbolAddress((void**)&pwo,   g_wo);
    cudaGetSymbolAddress((void**)&pwgu,  g_wgu);
    cudaGetSymbolAddress((void**)&pwd,   g_wd);

    cudaFuncSetAttribute(flash8_kernel, cudaFuncAttributeMaxDynamicSharedMemorySize, FLASH_SMEM);
    cudaFuncSetAttribute(gemm_hf<0>, cudaFuncAttributeMaxDynamicSharedMemorySize, GSMEM);
    cudaFuncSetAttribute(gemm_hf<1>, cudaFuncAttributeMaxDynamicSharedMemorySize, GSMEM);
    cudaFuncSetAttribute(gemm_hf<2>, cudaFuncAttributeMaxDynamicSharedMemorySize, GSMEM);
    cudaFuncSetAttribute(gemm_hf<3>, cudaFuncAttributeMaxDynamicSharedMemorySize, GSMEM);

    rope_table_kernel<<<(SS*32 + 255)/256, 256>>>();
    embed_kernel<<<(M_TOK*DD + 255)/256, 256>>>(ids, iter, emb, iter_emb);
    roundh_kernel<<<(NLL*3*DD*DD + 255)/256, 256>>>(Wqkv, pwqkv, NLL*3*DD*DD);
    roundh_kernel<<<(NLL*DD*DD + 255)/256, 256>>>(wo, pwo, NLL*DD*DD);
    round_gu_kernel<<<(NLL*FFF*DD + 255)/256, 256>>>(gate_w, pwgu, 0);
    round_gu_kernel<<<(NLL*FFF*DD + 255)/256, 256>>>(up_w,   pwgu, 1);
    roundh_kernel<<<(NLL*DD*FFF + 255)/256, 256>>>(down_w, pwd, NLL*DD*FFF);

    for (int l = 0; l < NLL; l++) {
        rmsnorm_h_kernel<<<M_TOK, 128>>>(px, attn_norm + (size_t)l*DD, ph);
        gemm_hf<0><<<dim3((3*DD+127)/128, M_TOK/128), 256, GSMEM>>>(ph,
            pwqkv + (size_t)l*3*DD*DD, pqkv, M_TOK, 3*DD, DD);
        rope_kernel<<<(M_TOK*NHH*32 + 255)/256, 256>>>();
        flash8_kernel<<<dim3(SS/128, NHH, BB), 256, FLASH_SMEM>>>();
        gemm_hf<1><<<dim3((DD+127)/128, M_TOK/128), 256, GSMEM>>>(patt,
            pwo + (size_t)l*DD*DD, px, M_TOK, DD, DD);
        router_kernel<<<M_TOK/4, 128>>>(router + (size_t)l*DD);
        topk_kernel<<<BB, 1024>>>();
        gather_rmsnorm_kernel<<<M_SEL, 128>>>(mlp_norm + (size_t)l*DD);
        gemm_hf<3><<<dim3((2*FFF+127)/128, (M_SEL+127)/128), 256, GSMEM>>>(phs,
            pwgu + (size_t)l*2*FFF*DD, px /*unused*/, M_SEL, 2*FFF, DD);
        gemm_hf<2><<<dim3((DD+127)/128, (M_SEL+127)/128), 256, GSMEM>>>(pga,
            pwd + (size_t)l*DD*FFF, px, M_SEL, DD, FFF);
    }
    rmsnorm_f32_kernel<<<M_TOK, 128>>>(px, fnorm, (float*)d_out);
}